// round 2
// baseline (speedup 1.0000x reference)
#include <cuda_runtime.h>

#define EPS    1e-5f
#define ALPHA  0.2f

#define MAX_O  50000
#define MAX_T  200000

// ---------------- scratch (static device globals; no allocation) -------------
__device__ float g_A1[(size_t)MAX_T * 512];    // layer-1a pre/post BN (also reused as A3)
__device__ float g_A2[(size_t)MAX_T * 1152];   // layer-1b pre-BN
__device__ float g_pooled[(size_t)MAX_O * 512];
__device__ float g_A4[(size_t)MAX_O * 128];
__device__ float g_counts[MAX_O];
__device__ int   g_es[MAX_T];                  // normalized edge subject idx (int32)
__device__ int   g_eo[MAX_T];                  // normalized edge object  idx (int32)
__device__ int   g_flag32;                     // 1 -> edges buffer is int32, 0 -> int64
// per-layer column stats, packed: L1 @0 (512), L2 @512 (1152), L3 @1664 (512), L4 @2176 (128)
__device__ float g_sum[2304];
__device__ float g_sq[2304];
__device__ float g_cA[2304];   // scale  a[n] = gamma*inv_std
__device__ float g_cB[2304];   // offset b[n] = beta - mean*a

// ---------------- zero scratch that is accumulated into ----------------------
__global__ void zero_k(float* pooled, float* counts, float* sum, float* sq,
                       int* flag32, long n_pooled, int O)
{
    if (blockIdx.x == 0 && threadIdx.x == 0) *flag32 = 0;
    long total = n_pooled + O + 2 * 2304;
    for (long i = blockIdx.x * (long)blockDim.x + threadIdx.x; i < total;
         i += (long)gridDim.x * blockDim.x) {
        if (i < n_pooled)            pooled[i] = 0.f;
        else if (i < n_pooled + O)   counts[i - n_pooled] = 0.f;
        else {
            long j = i - n_pooled - O;
            if (j < 2304) sum[j] = 0.f; else sq[j - 2304] = 0.f;
        }
    }
}

// ---------------- edge dtype probe + normalize --------------------------------
// View edges as int32. If true dtype is int64 (values in [0,50000)), every odd
// int32 slot is a zero high word. If int32, odd slots are o_idx values (mostly
// nonzero). Probing first 2T int32 slots is in-bounds under both layouts.
__global__ void probe_k(const int* __restrict__ e32, int* flag32, int T)
{
    int t = blockIdx.x * blockDim.x + threadIdx.x;
    if (t >= T) return;
    if (e32[2 * t + 1] != 0) atomicOr(flag32, 1);
}

__global__ void convert_k(const int* __restrict__ e32, const int* __restrict__ flag32,
                          int* __restrict__ es, int* __restrict__ eo,
                          float* __restrict__ counts, int T)
{
    int t = blockIdx.x * blockDim.x + threadIdx.x;
    if (t >= T) return;
    int s, o;
    if (*flag32) { s = e32[2 * t];     o = e32[2 * t + 1]; }
    else         { s = e32[4 * t];     o = e32[4 * t + 2]; }   // int64 low words (LE)
    es[t] = s;
    eo[t] = o;
    atomicAdd(&counts[s], 1.f);
    atomicAdd(&counts[o], 1.f);
}

// ---------------- SGEMM: C[M,N] = A[M,K] @ B[K,N] + bias ---------------------
// GATHER=true: A row t is concat(obj[es[t]], pred[t], obj[eo[t]]) (Din=128 each)
template<bool GATHER>
__global__ void sgemm_k(const float* __restrict__ A,
                        const float* __restrict__ obj,
                        const float* __restrict__ pred,
                        const int* __restrict__ es,
                        const int* __restrict__ eo,
                        const float* __restrict__ B,
                        const float* __restrict__ bias,
                        float* __restrict__ C,
                        int M, int N, int K)
{
    __shared__ __align__(16) float As[16][128];
    __shared__ __align__(16) float Bs[16][128];

    const int tid = threadIdx.x;
    const int m0 = blockIdx.y * 128;
    const int n0 = blockIdx.x * 128;
    const int tx = tid & 15;
    const int ty = tid >> 4;

    float acc[8][8];
#pragma unroll
    for (int i = 0; i < 8; i++)
#pragma unroll
        for (int j = 0; j < 8; j++) acc[i][j] = 0.f;

    const int aRow = tid >> 2;          // 0..63
    const int aCol = (tid & 3) * 4;     // 0,4,8,12
    const int bRow = tid >> 5;          // 0..7
    const int bCol = (tid & 31) * 4;    // 0..124

    for (int k0 = 0; k0 < K; k0 += 16) {
        // ---- load A tile (transposed into smem) ----
#pragma unroll
        for (int it = 0; it < 2; it++) {
            int r  = aRow + it * 64;
            int gm = m0 + r;
            float4 v = make_float4(0.f, 0.f, 0.f, 0.f);
            if (gm < M) {
                if (GATHER) {
                    int kc = k0 + aCol;          // float4 stays inside one 128-wide segment
                    const float* src;
                    long srow;
                    if (kc < 128)      { srow = (long)es[gm]; src = obj;              }
                    else if (kc < 256) { srow = gm;           src = pred; kc -= 128;  }
                    else               { srow = (long)eo[gm]; src = obj;  kc -= 256;  }
                    v = *reinterpret_cast<const float4*>(src + srow * 128 + kc);
                } else {
                    v = *reinterpret_cast<const float4*>(A + (long)gm * K + k0 + aCol);
                }
            }
            As[aCol + 0][r] = v.x;
            As[aCol + 1][r] = v.y;
            As[aCol + 2][r] = v.z;
            As[aCol + 3][r] = v.w;
        }
        // ---- load B tile ----
#pragma unroll
        for (int it = 0; it < 2; it++) {
            int r = bRow + it * 8;
            float4 v = *reinterpret_cast<const float4*>(B + (long)(k0 + r) * N + n0 + bCol);
            *reinterpret_cast<float4*>(&Bs[r][bCol]) = v;
        }
        __syncthreads();

#pragma unroll
        for (int kk = 0; kk < 16; kk++) {
            float4 a0 = *reinterpret_cast<const float4*>(&As[kk][ty * 8]);
            float4 a1 = *reinterpret_cast<const float4*>(&As[kk][ty * 8 + 4]);
            float4 b0 = *reinterpret_cast<const float4*>(&Bs[kk][tx * 8]);
            float4 b1 = *reinterpret_cast<const float4*>(&Bs[kk][tx * 8 + 4]);
            float ar[8] = {a0.x, a0.y, a0.z, a0.w, a1.x, a1.y, a1.z, a1.w};
            float br[8] = {b0.x, b0.y, b0.z, b0.w, b1.x, b1.y, b1.z, b1.w};
#pragma unroll
            for (int i = 0; i < 8; i++)
#pragma unroll
                for (int j = 0; j < 8; j++) acc[i][j] += ar[i] * br[j];
        }
        __syncthreads();
    }

    // ---- epilogue: + bias, store ----
#pragma unroll
    for (int i = 0; i < 8; i++) {
        int gm = m0 + ty * 8 + i;
        if (gm >= M) break;
#pragma unroll
        for (int j = 0; j < 8; j += 4) {
            int gn = n0 + tx * 8 + j;
            float4 bv = *reinterpret_cast<const float4*>(&bias[gn]);
            float4 o;
            o.x = acc[i][j + 0] + bv.x;
            o.y = acc[i][j + 1] + bv.y;
            o.z = acc[i][j + 2] + bv.z;
            o.w = acc[i][j + 3] + bv.w;
            *reinterpret_cast<float4*>(C + (long)gm * N + gn) = o;
        }
    }
}

// ---------------- per-column sum / sum-of-squares -----------------------------
__global__ void colstats_k(const float* __restrict__ X, int M, int N,
                           float* __restrict__ sum, float* __restrict__ sq)
{
    const int col = blockIdx.y * blockDim.x + threadIdx.x;
    if (col >= N) return;
    long r0 = (long)blockIdx.x * 2048;
    long r1 = r0 + 2048; if (r1 > M) r1 = M;
    float s = 0.f, q = 0.f;
    for (long r = r0; r < r1; r++) {
        float v = X[r * N + col];
        s += v;
        q += v * v;
    }
    atomicAdd(&sum[col], s);
    atomicAdd(&sq[col],  q);
}

__global__ void finalize_k(const float* __restrict__ sum, const float* __restrict__ sq,
                           const float* __restrict__ gamma, const float* __restrict__ beta,
                           float invM, int N,
                           float* __restrict__ cA, float* __restrict__ cB)
{
    int n = blockIdx.x * blockDim.x + threadIdx.x;
    if (n >= N) return;
    float mean = sum[n] * invM;
    float var  = sq[n] * invM - mean * mean;
    float inv  = rsqrtf(var + EPS);
    float a    = inv * gamma[n];
    cA[n] = a;
    cB[n] = beta[n] - mean * a;
}

__global__ void bn_apply_k(float* __restrict__ X, const float* __restrict__ cA,
                           const float* __restrict__ cB, long total, int N)
{
    long i = blockIdx.x * (long)blockDim.x + threadIdx.x;
    if (i >= total) return;
    int n = (int)(i % N);
    float v = X[i] * cA[n] + cB[n];
    X[i] = (v >= 0.f) ? v : ALPHA * v;
}

__global__ void bn_out_k(const float* __restrict__ X, const float* __restrict__ cA,
                         const float* __restrict__ cB, float* __restrict__ out,
                         long total, int N)
{
    long i = blockIdx.x * (long)blockDim.x + threadIdx.x;
    if (i >= total) return;
    int n = (int)(i % N);
    float v = X[i] * cA[n] + cB[n];
    out[i] = (v >= 0.f) ? v : ALPHA * v;
}

// ---------------- scatter, divide ---------------------------------------------
// one block per triple-row: normalize+lrelu row of A2 (1152 wide),
// cols [0,512) -> atomicAdd pooled[s], [512,640) -> out_p, [640,1152) -> pooled[o]
__global__ void scatter_k(const float* __restrict__ A2,
                          const float* __restrict__ cA, const float* __restrict__ cB,
                          const int* __restrict__ es, const int* __restrict__ eo,
                          float* __restrict__ pooled, float* __restrict__ out_p, int T)
{
    int t = blockIdx.x;
    if (t >= T) return;
    int s = es[t];
    int o = eo[t];
    const float* row = A2 + (long)t * 1152;
    for (int c = threadIdx.x; c < 1152; c += blockDim.x) {
        float v = row[c] * cA[c] + cB[c];
        v = (v >= 0.f) ? v : ALPHA * v;
        if (c < 512)       atomicAdd(&pooled[(long)s * 512 + c], v);
        else if (c < 640)  out_p[(long)t * 128 + (c - 512)] = v;
        else               atomicAdd(&pooled[(long)o * 512 + (c - 640)], v);
    }
}

__global__ void divide_k(float* __restrict__ pooled, const float* __restrict__ counts,
                         int O)
{
    long i = blockIdx.x * (long)blockDim.x + threadIdx.x;
    long total = (long)O * 512;
    if (i >= total) return;
    float c = counts[i >> 9];            // /512
    c = fminf(fmaxf(c, 1.f), (float)O);
    pooled[i] /= c;
}

// ---------------- launch -------------------------------------------------------
extern "C" void kernel_launch(void* const* d_in, const int* in_sizes, int n_in,
                              void* d_out, int out_size)
{
    const float* obj   = (const float*)d_in[0];
    const float* pred  = (const float*)d_in[1];
    const int*   e32   = (const int*)d_in[2];    // raw view; dtype probed on device
    const float* W1a = (const float*)d_in[3];
    const float* b1a = (const float*)d_in[4];
    const float* g1a = (const float*)d_in[5];
    const float* be1a= (const float*)d_in[6];
    const float* W1b = (const float*)d_in[7];
    const float* b1b = (const float*)d_in[8];
    const float* g1b = (const float*)d_in[9];
    const float* be1b= (const float*)d_in[10];
    const float* W2a = (const float*)d_in[11];
    const float* b2a = (const float*)d_in[12];
    const float* g2a = (const float*)d_in[13];
    const float* be2a= (const float*)d_in[14];
    const float* W2b = (const float*)d_in[15];
    const float* b2b = (const float*)d_in[16];
    const float* g2b = (const float*)d_in[17];
    const float* be2b= (const float*)d_in[18];

    const int O = in_sizes[0] / 128;
    const int T = in_sizes[1] / 128;

    float* out     = (float*)d_out;
    float* out_obj = out;                       // [O,128]
    float* out_p   = out + (size_t)O * 128;     // [T,128]

    float *A1, *A2, *POOL, *A4, *CNT, *SUM, *SQ, *CA, *CB;
    int *ES, *EO, *FLAG;
    cudaGetSymbolAddress((void**)&A1,   g_A1);
    cudaGetSymbolAddress((void**)&A2,   g_A2);
    cudaGetSymbolAddress((void**)&POOL, g_pooled);
    cudaGetSymbolAddress((void**)&A4,   g_A4);
    cudaGetSymbolAddress((void**)&CNT,  g_counts);
    cudaGetSymbolAddress((void**)&SUM,  g_sum);
    cudaGetSymbolAddress((void**)&SQ,   g_sq);
    cudaGetSymbolAddress((void**)&CA,   g_cA);
    cudaGetSymbolAddress((void**)&CB,   g_cB);
    cudaGetSymbolAddress((void**)&ES,   g_es);
    cudaGetSymbolAddress((void**)&EO,   g_eo);
    cudaGetSymbolAddress((void**)&FLAG, g_flag32);

    const int OFF1 = 0, OFF2 = 512, OFF3 = 1664, OFF4 = 2176;

    // 0) zero accumulated buffers + flag
    zero_k<<<2048, 256>>>(POOL, CNT, SUM, SQ, FLAG, (long)O * 512, O);

    // 0b) probe edge dtype, normalize to int32 (also builds counts)
    probe_k<<<(T + 255) / 256, 256>>>(e32, FLAG, T);
    convert_k<<<(T + 255) / 256, 256>>>(e32, FLAG, ES, EO, CNT, T);

    // 1) GEMM1 (gathered): A1 = cur_t @ W1a + b1a    [T,512]
    sgemm_k<true><<<dim3(512 / 128, (T + 127) / 128), 256>>>(
        nullptr, obj, pred, ES, EO, W1a, b1a, A1, T, 512, 384);

    // 2) BN1 stats + apply (in place, lrelu)
    colstats_k<<<dim3((T + 2047) / 2048, 512 / 128), 128>>>(A1, T, 512, SUM + OFF1, SQ + OFF1);
    finalize_k<<<(512 + 255) / 256, 256>>>(SUM + OFF1, SQ + OFF1, g1a, be1a, 1.f / T, 512, CA + OFF1, CB + OFF1);
    bn_apply_k<<<(unsigned)(((long)T * 512 + 255) / 256), 256>>>(A1, CA + OFF1, CB + OFF1, (long)T * 512, 512);

    // 3) GEMM2: A2 = h @ W1b + b1b     [T,1152]
    sgemm_k<false><<<dim3(1152 / 128, (T + 127) / 128), 256>>>(
        A1, nullptr, nullptr, nullptr, nullptr, W1b, b1b, A2, T, 1152, 512);

    // 4) BN2 stats
    colstats_k<<<dim3((T + 2047) / 2048, 1152 / 128), 128>>>(A2, T, 1152, SUM + OFF2, SQ + OFF2);
    finalize_k<<<(1152 + 255) / 256, 256>>>(SUM + OFF2, SQ + OFF2, g1b, be1b, 1.f / T, 1152, CA + OFF2, CB + OFF2);

    // 5) scatter (normalize+lrelu fused) + mean-pool divide
    scatter_k<<<T, 128>>>(A2, CA + OFF2, CB + OFF2, ES, EO, POOL, out_p, T);
    divide_k<<<(unsigned)(((long)O * 512 + 255) / 256), 256>>>(POOL, CNT, O);

    // 6) GEMM3: A3(=A1) = pooled @ W2a + b2a   [O,512]
    sgemm_k<false><<<dim3(512 / 128, (O + 127) / 128), 256>>>(
        POOL, nullptr, nullptr, nullptr, nullptr, W2a, b2a, A1, O, 512, 512);

    // 7) BN3 stats + apply
    colstats_k<<<dim3((O + 2047) / 2048, 512 / 128), 128>>>(A1, O, 512, SUM + OFF3, SQ + OFF3);
    finalize_k<<<(512 + 255) / 256, 256>>>(SUM + OFF3, SQ + OFF3, g2a, be2a, 1.f / O, 512, CA + OFF3, CB + OFF3);
    bn_apply_k<<<(unsigned)(((long)O * 512 + 255) / 256), 256>>>(A1, CA + OFF3, CB + OFF3, (long)O * 512, 512);

    // 8) GEMM4: A4 = h2 @ W2b + b2b   [O,128]
    sgemm_k<false><<<dim3(128 / 128, (O + 127) / 128), 256>>>(
        A1, nullptr, nullptr, nullptr, nullptr, W2b, b2b, A4, O, 128, 512);

    // 9) BN4 stats + apply -> out_obj
    colstats_k<<<dim3((O + 2047) / 2048, 128 / 128), 128>>>(A4, O, 128, SUM + OFF4, SQ + OFF4);
    finalize_k<<<(128 + 255) / 256, 256>>>(SUM + OFF4, SQ + OFF4, g2b, be2b, 1.f / O, 128, CA + OFF4, CB + OFF4);
    bn_out_k<<<(unsigned)(((long)O * 128 + 255) / 256), 256>>>(A4, CA + OFF4, CB + OFF4, out_obj, (long)O * 128, 128);
}

// round 5
// speedup vs baseline: 1.6066x; 1.6066x over previous
#include <cuda_runtime.h>
#include <cuda_bf16.h>
#include <cstdint>

#define EPS    1e-5f
#define ALPHA  0.2f
#define MAX_O  50000
#define MAX_T  200000

// ---------------- scratch (static device globals; no allocation) -------------
__device__ float g_A1[(size_t)MAX_T * 512];    // layer-1a pre-BN (also reused for A3)
__device__ float g_A2[(size_t)MAX_T * 1152];   // layer-1b pre-BN
__device__ float g_pooled[(size_t)MAX_O * 512];
__device__ float g_A4[(size_t)MAX_O * 128];
__device__ float g_counts[MAX_O];
__device__ int   g_es[MAX_T];
__device__ int   g_eo[MAX_T];
__device__ int   g_flag32;
// transposed + split weights, bf16 [N,K] row-major, packed:
// W1a @0 (196608), W1b @196608 (589824), W2a @786432 (262144), W2b @1048576 (65536)
#define WT_TOTAL 1114112
__device__ __nv_bfloat16 g_wt_hi[WT_TOTAL];
__device__ __nv_bfloat16 g_wt_lo[WT_TOTAL];
// per-layer column stats: L1 @0 (512), L2 @512 (1152), L3 @1664 (512), L4 @2176 (128)
__device__ float g_sum[2304];
__device__ float g_sq[2304];
__device__ float g_cA[2304];
__device__ float g_cB[2304];

// ======================= PTX wrappers (family-wide: ldmatrix + mma.sync) ======
__device__ __forceinline__ uint32_t smem_to_u32(const void* p) {
    uint32_t a;
    asm("{ .reg .u64 t; cvta.to.shared.u64 t, %1; cvt.u32.u64 %0, t; }" : "=r"(a) : "l"(p));
    return a;
}
__device__ __forceinline__ void ldsm_x4(uint32_t addr, uint32_t* r) {
    asm volatile("ldmatrix.sync.aligned.m8n8.x4.shared.b16 {%0,%1,%2,%3}, [%4];"
        : "=r"(r[0]), "=r"(r[1]), "=r"(r[2]), "=r"(r[3]) : "r"(addr));
}
__device__ __forceinline__ void mma_bf16(float* c, const uint32_t* a, const uint32_t* b) {
    asm volatile("mma.sync.aligned.m16n8k16.row.col.f32.bf16.bf16.f32 "
        "{%0,%1,%2,%3},{%4,%5,%6,%7},{%8,%9},{%0,%1,%2,%3};"
        : "+f"(c[0]), "+f"(c[1]), "+f"(c[2]), "+f"(c[3])
        : "r"(a[0]), "r"(a[1]), "r"(a[2]), "r"(a[3]), "r"(b[0]), "r"(b[1]));
}

// ======================= small utility kernels ================================
__global__ void zero_k(float* pooled, float* counts, float* sum, float* sq,
                       int* flag32, long n_pooled, int O)
{
    if (blockIdx.x == 0 && threadIdx.x == 0) *flag32 = 0;
    long total = n_pooled + O + 2 * 2304;
    for (long i = blockIdx.x * (long)blockDim.x + threadIdx.x; i < total;
         i += (long)gridDim.x * blockDim.x) {
        if (i < n_pooled)            pooled[i] = 0.f;
        else if (i < n_pooled + O)   counts[i - n_pooled] = 0.f;
        else {
            long j = i - n_pooled - O;
            if (j < 2304) sum[j] = 0.f; else sq[j - 2304] = 0.f;
        }
    }
}

__global__ void probe_k(const int* __restrict__ e32, int* flag32, int T)
{
    int t = blockIdx.x * blockDim.x + threadIdx.x;
    if (t >= T) return;
    if (e32[2 * t + 1] != 0) atomicOr(flag32, 1);
}

__global__ void convert_k(const int* __restrict__ e32, const int* __restrict__ flag32,
                          int* __restrict__ es, int* __restrict__ eo,
                          float* __restrict__ counts, int T)
{
    int t = blockIdx.x * blockDim.x + threadIdx.x;
    if (t >= T) return;
    int s, o;
    if (*flag32) { s = e32[2 * t]; o = e32[2 * t + 1]; }
    else         { s = e32[4 * t]; o = e32[4 * t + 2]; }
    es[t] = s;
    eo[t] = o;
    atomicAdd(&counts[s], 1.f);
    atomicAdd(&counts[o], 1.f);
}

// transpose + split weights: W[K,N] fp32 -> hi/lo bf16 [N,K]
__global__ void wsplit_k(const float* __restrict__ W,
                         __nv_bfloat16* __restrict__ hi, __nv_bfloat16* __restrict__ lo,
                         int K, int N)
{
    int i = blockIdx.x * blockDim.x + threadIdx.x;
    if (i >= K * N) return;
    int k = i / N, n = i % N;
    float v = W[i];
    __nv_bfloat16 h = __float2bfloat16(v);
    hi[(long)n * K + k] = h;
    lo[(long)n * K + k] = __float2bfloat16(v - __bfloat162float(h));
}

// ======================= mma.sync GEMM =========================================
// C[M,N] = f(A)[M,K] @ Wt^T + bias, Wt is [N,K] bf16 hi/lo, fp32 accumulate.
// bf16x3 split: hi*hi + hi*lo + lo*hi.
// CTA tile 128x128, 8 warps (2x4), warp tile 64x32, K-chunk 32.
// smem rows padded to 80B (conflict-free ldmatrix).
// B fragments loaded with NON-trans ldmatrix: [N,K] row-major storage already
// matches mma.sync's B layout (consecutive k at fixed n per lane).
#define ROWB 80
template<bool GATHER, bool APPLY_BN, bool DIV_ROW>
__global__ void __launch_bounds__(256, 1)
mma_gemm_k(const float* __restrict__ A,
           const float* __restrict__ obj, const float* __restrict__ pred,
           const int* __restrict__ es, const int* __restrict__ eo,
           const __nv_bfloat16* __restrict__ Bth, const __nv_bfloat16* __restrict__ Btl,
           const float* __restrict__ bias,
           const float* __restrict__ cA, const float* __restrict__ cB,
           const float* __restrict__ counts, float ocap,
           float* __restrict__ C, int M, int N, int K)
{
    __shared__ __align__(128) char smem[4 * 128 * ROWB];   // Ah, Al, Bh, Bl
    char* pAh = smem;
    char* pAl = smem + 128 * ROWB;
    char* pBh = smem + 2 * 128 * ROWB;
    char* pBl = smem + 3 * 128 * ROWB;
    const uint32_t sAh = smem_to_u32(pAh);
    const uint32_t sAl = sAh + 128 * ROWB;
    const uint32_t sBh = sAh + 2 * 128 * ROWB;
    const uint32_t sBl = sAh + 3 * 128 * ROWB;

    const int tid  = threadIdx.x;
    const int lane = tid & 31;
    const int wid  = tid >> 5;
    const int wm   = wid >> 2;       // 0..1  (64-row slabs)
    const int wn   = wid & 3;        // 0..3  (32-col slabs)
    const int m0   = blockIdx.y * 128, n0 = blockIdx.x * 128;

    float acc[4][4][4];
#pragma unroll
    for (int i = 0; i < 4; i++)
#pragma unroll
        for (int j = 0; j < 4; j++)
#pragma unroll
            for (int q = 0; q < 4; q++) acc[i][j][q] = 0.f;

    const int q8   = lane >> 3;      // ldmatrix sub-matrix id
    const int r8   = lane & 7;

    for (int k0 = 0; k0 < K; k0 += 32) {
        // ---- A: 128 rows x 32 k fp32 -> bf16 hi/lo ----
#pragma unroll
        for (int i = 0; i < 4; i++) {
            int idx = tid + (i << 8);
            int row = idx >> 3;
            int c4  = (idx & 7) << 2;
            int gm  = m0 + row;
            int gmc = gm < M ? gm : M - 1;
            float4 v;
            if (GATHER) {
                const float* src; long sr;
                if (k0 < 128)      { sr = (long)es[gmc]; src = obj;  }
                else if (k0 < 256) { sr = gmc;           src = pred; }
                else               { sr = (long)eo[gmc]; src = obj;  }
                v = *reinterpret_cast<const float4*>(src + sr * 128 + (k0 & 127) + c4);
            } else {
                v = *reinterpret_cast<const float4*>(A + (long)gmc * K + k0 + c4);
            }
            if (APPLY_BN) {
                float4 a = *reinterpret_cast<const float4*>(cA + k0 + c4);
                float4 b = *reinterpret_cast<const float4*>(cB + k0 + c4);
                v.x = fmaf(v.x, a.x, b.x); v.x = v.x >= 0.f ? v.x : ALPHA * v.x;
                v.y = fmaf(v.y, a.y, b.y); v.y = v.y >= 0.f ? v.y : ALPHA * v.y;
                v.z = fmaf(v.z, a.z, b.z); v.z = v.z >= 0.f ? v.z : ALPHA * v.z;
                v.w = fmaf(v.w, a.w, b.w); v.w = v.w >= 0.f ? v.w : ALPHA * v.w;
            }
            if (DIV_ROW) {
                float c = counts[gmc];
                c = fminf(fmaxf(c, 1.f), ocap);
                float r = 1.f / c;
                v.x *= r; v.y *= r; v.z *= r; v.w *= r;
            }
            __nv_bfloat16 hx = __float2bfloat16(v.x);
            __nv_bfloat16 hy = __float2bfloat16(v.y);
            __nv_bfloat16 hz = __float2bfloat16(v.z);
            __nv_bfloat16 hw = __float2bfloat16(v.w);
            __nv_bfloat162 h01 = __halves2bfloat162(hx, hy);
            __nv_bfloat162 h23 = __halves2bfloat162(hz, hw);
            __nv_bfloat162 l01 = __halves2bfloat162(
                __float2bfloat16(v.x - __bfloat162float(hx)),
                __float2bfloat16(v.y - __bfloat162float(hy)));
            __nv_bfloat162 l23 = __halves2bfloat162(
                __float2bfloat16(v.z - __bfloat162float(hz)),
                __float2bfloat16(v.w - __bfloat162float(hw)));
            uint2 hp = make_uint2(*reinterpret_cast<uint32_t*>(&h01),
                                  *reinterpret_cast<uint32_t*>(&h23));
            uint2 lp = make_uint2(*reinterpret_cast<uint32_t*>(&l01),
                                  *reinterpret_cast<uint32_t*>(&l23));
            int so = row * ROWB + (c4 << 1);
            *reinterpret_cast<uint2*>(pAh + so) = hp;
            *reinterpret_cast<uint2*>(pAl + so) = lp;
        }
        // ---- B: 128 n-rows x 32 k bf16 hi/lo (pre-split) ----
#pragma unroll
        for (int i = 0; i < 2; i++) {
            int idx = tid + (i << 8);
            int row = idx >> 2;
            int c8  = (idx & 3) << 3;
            long g  = (long)(n0 + row) * K + k0 + c8;
            uint4 h = *reinterpret_cast<const uint4*>(Bth + g);
            uint4 l = *reinterpret_cast<const uint4*>(Btl + g);
            int so  = row * ROWB + (c8 << 1);
            *reinterpret_cast<uint4*>(pBh + so) = h;
            *reinterpret_cast<uint4*>(pBl + so) = l;
        }
        __syncthreads();

#pragma unroll
        for (int s = 0; s < 2; s++) {
            uint32_t ah[4][4], al[4][4], bh[4][2], bl[4][2];
            // B fragments: NON-trans x4; matrices map to (b0,b1) of two n-tiles
#pragma unroll
            for (int j = 0; j < 2; j++) {
                int nrow = wn * 32 + j * 16 + (q8 >> 1) * 8 + r8;
                int kb   = s * 32 + (q8 & 1) * 16;
                uint32_t addr = (uint32_t)(nrow * ROWB + kb);
                uint32_t r[4];
                ldsm_x4(sBh + addr, r);
                bh[2 * j][0] = r[0]; bh[2 * j][1] = r[1];
                bh[2 * j + 1][0] = r[2]; bh[2 * j + 1][1] = r[3];
                ldsm_x4(sBl + addr, r);
                bl[2 * j][0] = r[0]; bl[2 * j][1] = r[1];
                bl[2 * j + 1][0] = r[2]; bl[2 * j + 1][1] = r[3];
            }
            // A fragments
#pragma unroll
            for (int mt = 0; mt < 4; mt++) {
                int mrow = wm * 64 + mt * 16 + (q8 & 1) * 8 + r8;
                int kb   = s * 32 + (q8 >> 1) * 16;
                uint32_t addr = (uint32_t)(mrow * ROWB + kb);
                ldsm_x4(sAh + addr, ah[mt]);
                ldsm_x4(sAl + addr, al[mt]);
            }
            // hi*hi + hi*lo + lo*hi
#pragma unroll
            for (int mt = 0; mt < 4; mt++)
#pragma unroll
                for (int nt = 0; nt < 4; nt++) {
                    mma_bf16(acc[mt][nt], ah[mt], bh[nt]);
                    mma_bf16(acc[mt][nt], ah[mt], bl[nt]);
                    mma_bf16(acc[mt][nt], al[mt], bh[nt]);
                }
        }
        __syncthreads();
    }

    // ---- epilogue: acc + bias -> C ----
#pragma unroll
    for (int mt = 0; mt < 4; mt++) {
        int row0 = m0 + wm * 64 + mt * 16 + (lane >> 2);
        int row1 = row0 + 8;
#pragma unroll
        for (int nt = 0; nt < 4; nt++) {
            int col = n0 + wn * 32 + nt * 8 + (lane & 3) * 2;
            float2 bv = *reinterpret_cast<const float2*>(bias + col);
            if (row0 < M) {
                float2 o = make_float2(acc[mt][nt][0] + bv.x, acc[mt][nt][1] + bv.y);
                *reinterpret_cast<float2*>(C + (long)row0 * N + col) = o;
            }
            if (row1 < M) {
                float2 o = make_float2(acc[mt][nt][2] + bv.x, acc[mt][nt][3] + bv.y);
                *reinterpret_cast<float2*>(C + (long)row1 * N + col) = o;
            }
        }
    }
}

// ======================= stats / BN / scatter =================================
__global__ void colstats_k(const float* __restrict__ X, int M, int N,
                           float* __restrict__ sum, float* __restrict__ sq)
{
    const int col = blockIdx.y * blockDim.x + threadIdx.x;
    if (col >= N) return;
    long r0 = (long)blockIdx.x * 2048;
    long r1 = r0 + 2048; if (r1 > M) r1 = M;
    float s = 0.f, q = 0.f;
    for (long r = r0; r < r1; r++) {
        float v = X[r * N + col];
        s += v;
        q += v * v;
    }
    atomicAdd(&sum[col], s);
    atomicAdd(&sq[col],  q);
}

__global__ void finalize_k(const float* __restrict__ sum, const float* __restrict__ sq,
                           const float* __restrict__ gamma, const float* __restrict__ beta,
                           float invM, int N,
                           float* __restrict__ cA, float* __restrict__ cB)
{
    int n = blockIdx.x * blockDim.x + threadIdx.x;
    if (n >= N) return;
    float mean = sum[n] * invM;
    float var  = sq[n] * invM - mean * mean;
    float inv  = rsqrtf(var + EPS);
    float a    = inv * gamma[n];
    cA[n] = a;
    cB[n] = beta[n] - mean * a;
}

__global__ void bn_out_k(const float* __restrict__ X, const float* __restrict__ cA,
                         const float* __restrict__ cB, float* __restrict__ out,
                         long total, int N)
{
    long i = blockIdx.x * (long)blockDim.x + threadIdx.x;
    if (i >= total) return;
    int n = (int)(i % N);
    float v = X[i] * cA[n] + cB[n];
    out[i] = (v >= 0.f) ? v : ALPHA * v;
}

__global__ void scatter_k(const float* __restrict__ A2,
                          const float* __restrict__ cA, const float* __restrict__ cB,
                          const int* __restrict__ es, const int* __restrict__ eo,
                          float* __restrict__ pooled, float* __restrict__ out_p, int T)
{
    int t = blockIdx.x;
    if (t >= T) return;
    int s = es[t];
    int o = eo[t];
    const float* row = A2 + (long)t * 1152;
    for (int c = threadIdx.x; c < 1152; c += blockDim.x) {
        float v = row[c] * cA[c] + cB[c];
        v = (v >= 0.f) ? v : ALPHA * v;
        if (c < 512)       atomicAdd(&pooled[(long)s * 512 + c], v);
        else if (c < 640)  out_p[(long)t * 128 + (c - 512)] = v;
        else               atomicAdd(&pooled[(long)o * 512 + (c - 640)], v);
    }
}

// ======================= launch ================================================
extern "C" void kernel_launch(void* const* d_in, const int* in_sizes, int n_in,
                              void* d_out, int out_size)
{
    const float* obj   = (const float*)d_in[0];
    const float* pred  = (const float*)d_in[1];
    const int*   e32   = (const int*)d_in[2];
    const float* W1a = (const float*)d_in[3];
    const float* b1a = (const float*)d_in[4];
    const float* g1a = (const float*)d_in[5];
    const float* be1a= (const float*)d_in[6];
    const float* W1b = (const float*)d_in[7];
    const float* b1b = (const float*)d_in[8];
    const float* g1b = (const float*)d_in[9];
    const float* be1b= (const float*)d_in[10];
    const float* W2a = (const float*)d_in[11];
    const float* b2a = (const float*)d_in[12];
    const float* g2a = (const float*)d_in[13];
    const float* be2a= (const float*)d_in[14];
    const float* W2b = (const float*)d_in[15];
    const float* b2b = (const float*)d_in[16];
    const float* g2b = (const float*)d_in[17];
    const float* be2b= (const float*)d_in[18];

    const int O = in_sizes[0] / 128;
    const int T = in_sizes[1] / 128;

    float* out     = (float*)d_out;
    float* out_obj = out;
    float* out_p   = out + (size_t)O * 128;

    float *A1, *A2, *POOL, *A4, *CNT, *SUM, *SQ, *CA, *CB;
    int *ES, *EO, *FLAG;
    __nv_bfloat16 *WTH, *WTL;
    cudaGetSymbolAddress((void**)&A1,   g_A1);
    cudaGetSymbolAddress((void**)&A2,   g_A2);
    cudaGetSymbolAddress((void**)&POOL, g_pooled);
    cudaGetSymbolAddress((void**)&A4,   g_A4);
    cudaGetSymbolAddress((void**)&CNT,  g_counts);
    cudaGetSymbolAddress((void**)&SUM,  g_sum);
    cudaGetSymbolAddress((void**)&SQ,   g_sq);
    cudaGetSymbolAddress((void**)&CA,   g_cA);
    cudaGetSymbolAddress((void**)&CB,   g_cB);
    cudaGetSymbolAddress((void**)&ES,   g_es);
    cudaGetSymbolAddress((void**)&EO,   g_eo);
    cudaGetSymbolAddress((void**)&FLAG, g_flag32);
    cudaGetSymbolAddress((void**)&WTH,  g_wt_hi);
    cudaGetSymbolAddress((void**)&WTL,  g_wt_lo);

    const int OFF1 = 0, OFF2 = 512, OFF3 = 1664, OFF4 = 2176;
    const int W1A_OFF = 0, W1B_OFF = 196608, W2A_OFF = 786432, W2B_OFF = 1048576;

    // 0) zero accumulators, probe edge dtype, normalize edges (+counts)
    zero_k<<<2048, 256>>>(POOL, CNT, SUM, SQ, FLAG, (long)O * 512, O);
    probe_k<<<(T + 255) / 256, 256>>>(e32, FLAG, T);
    convert_k<<<(T + 255) / 256, 256>>>(e32, FLAG, ES, EO, CNT, T);

    // 0b) transpose + split all weights to bf16 hi/lo [N,K]
    wsplit_k<<<(384 * 512  + 255) / 256, 256>>>(W1a, WTH + W1A_OFF, WTL + W1A_OFF, 384, 512);
    wsplit_k<<<(512 * 1152 + 255) / 256, 256>>>(W1b, WTH + W1B_OFF, WTL + W1B_OFF, 512, 1152);
    wsplit_k<<<(512 * 512  + 255) / 256, 256>>>(W2a, WTH + W2A_OFF, WTL + W2A_OFF, 512, 512);
    wsplit_k<<<(512 * 128  + 255) / 256, 256>>>(W2b, WTH + W2B_OFF, WTL + W2B_OFF, 512, 128);

    // 1) GEMM1 (gathered): A1 = cur_t @ W1a + b1a   [T,512]
    mma_gemm_k<true, false, false><<<dim3(512 / 128, (T + 127) / 128), 256>>>(
        nullptr, obj, pred, ES, EO, WTH + W1A_OFF, WTL + W1A_OFF, b1a,
        nullptr, nullptr, nullptr, 0.f, A1, T, 512, 384);

    // 2) BN1 stats (pre-BN); apply fused into GEMM2's A-load
    colstats_k<<<dim3((T + 2047) / 2048, 4), 128>>>(A1, T, 512, SUM + OFF1, SQ + OFF1);
    finalize_k<<<2, 256>>>(SUM + OFF1, SQ + OFF1, g1a, be1a, 1.f / T, 512, CA + OFF1, CB + OFF1);

    // 3) GEMM2: A2 = lrelu(bn(A1)) @ W1b + b1b   [T,1152]
    mma_gemm_k<false, true, false><<<dim3(1152 / 128, (T + 127) / 128), 256>>>(
        A1, nullptr, nullptr, nullptr, nullptr, WTH + W1B_OFF, WTL + W1B_OFF, b1b,
        CA + OFF1, CB + OFF1, nullptr, 0.f, A2, T, 1152, 512);

    // 4) BN2 stats
    colstats_k<<<dim3((T + 2047) / 2048, 9), 128>>>(A2, T, 1152, SUM + OFF2, SQ + OFF2);
    finalize_k<<<5, 256>>>(SUM + OFF2, SQ + OFF2, g1b, be1b, 1.f / T, 1152, CA + OFF2, CB + OFF2);

    // 5) scatter (BN2+lrelu fused) -> POOL (raw sums), out_p
    scatter_k<<<T, 128>>>(A2, CA + OFF2, CB + OFF2, ES, EO, POOL, out_p, T);

    // 6) GEMM3: A3(=A1) = (POOL/count) @ W2a + b2a   [O,512]  (divide fused)
    mma_gemm_k<false, false, true><<<dim3(512 / 128, (O + 127) / 128), 256>>>(
        POOL, nullptr, nullptr, nullptr, nullptr, WTH + W2A_OFF, WTL + W2A_OFF, b2a,
        nullptr, nullptr, CNT, (float)O, A1, O, 512, 512);

    // 7) BN3 stats; apply fused into GEMM4's A-load
    colstats_k<<<dim3((O + 2047) / 2048, 4), 128>>>(A1, O, 512, SUM + OFF3, SQ + OFF3);
    finalize_k<<<2, 256>>>(SUM + OFF3, SQ + OFF3, g2a, be2a, 1.f / O, 512, CA + OFF3, CB + OFF3);

    // 8) GEMM4: A4 = lrelu(bn(A3)) @ W2b + b2b   [O,128]
    mma_gemm_k<false, true, false><<<dim3(1, (O + 127) / 128), 256>>>(
        A1, nullptr, nullptr, nullptr, nullptr, WTH + W2B_OFF, WTL + W2B_OFF, b2b,
        CA + OFF3, CB + OFF3, nullptr, 0.f, A4, O, 128, 512);

    // 9) BN4 stats + apply -> out_obj
    colstats_k<<<dim3((O + 2047) / 2048, 1), 128>>>(A4, O, 128, SUM + OFF4, SQ + OFF4);
    finalize_k<<<1, 256>>>(SUM + OFF4, SQ + OFF4, g2b, be2b, 1.f / O, 128, CA + OFF4, CB + OFF4);
    bn_out_k<<<(unsigned)(((long)O * 128 + 255) / 256), 256>>>(A4, CA + OFF4, CB + OFF4,
                                                               out_obj, (long)O * 128, 128);
}

// round 6
// speedup vs baseline: 2.4422x; 1.5202x over previous
#include <cuda_runtime.h>
#include <cuda_bf16.h>
#include <cstdint>

#define EPS    1e-5f
#define ALPHA  0.2f
#define MAX_O  50000
#define MAX_T  200000

// ---------------- scratch (static device globals; no allocation) -------------
__device__ float g_A1[(size_t)MAX_T * 512];    // pre-BN layer outputs (reused for A3)
__device__ float g_A2[(size_t)MAX_T * 1152];
__device__ float g_pooled[(size_t)MAX_O * 512];
__device__ float g_A4[(size_t)MAX_O * 128];
__device__ float g_counts[MAX_O];
__device__ int   g_es[MAX_T];
__device__ int   g_eo[MAX_T];
__device__ int   g_flag32;
// pre-split bf16 A operands
__device__ __nv_bfloat16 g_objh[(size_t)MAX_O * 128];
__device__ __nv_bfloat16 g_objl[(size_t)MAX_O * 128];
__device__ __nv_bfloat16 g_predh[(size_t)MAX_T * 128];
__device__ __nv_bfloat16 g_predl[(size_t)MAX_T * 128];
__device__ __nv_bfloat16 g_xh[(size_t)MAX_T * 512];   // shared split scratch
__device__ __nv_bfloat16 g_xl[(size_t)MAX_T * 512];
// transposed + split weights, bf16 [N,K] row-major, packed:
#define WT_TOTAL 1114112
__device__ __nv_bfloat16 g_wt_hi[WT_TOTAL];
__device__ __nv_bfloat16 g_wt_lo[WT_TOTAL];
// per-layer column stats: L1 @0 (512), L2 @512 (1152), L3 @1664 (512), L4 @2176 (128)
__device__ float g_sum[2304];
__device__ float g_sq[2304];
__device__ float g_cA[2304];
__device__ float g_cB[2304];

// ======================= PTX wrappers =========================================
__device__ __forceinline__ uint32_t smem_to_u32(const void* p) {
    uint32_t a;
    asm("{ .reg .u64 t; cvta.to.shared.u64 t, %1; cvt.u32.u64 %0, t; }" : "=r"(a) : "l"(p));
    return a;
}
__device__ __forceinline__ void ldsm_x4(uint32_t addr, uint32_t* r) {
    asm volatile("ldmatrix.sync.aligned.m8n8.x4.shared.b16 {%0,%1,%2,%3}, [%4];"
        : "=r"(r[0]), "=r"(r[1]), "=r"(r[2]), "=r"(r[3]) : "r"(addr));
}
__device__ __forceinline__ void mma_bf16(float* c, const uint32_t* a, const uint32_t* b) {
    asm volatile("mma.sync.aligned.m16n8k16.row.col.f32.bf16.bf16.f32 "
        "{%0,%1,%2,%3},{%4,%5,%6,%7},{%8,%9},{%0,%1,%2,%3};"
        : "+f"(c[0]), "+f"(c[1]), "+f"(c[2]), "+f"(c[3])
        : "r"(a[0]), "r"(a[1]), "r"(a[2]), "r"(a[3]), "r"(b[0]), "r"(b[1]));
}
__device__ __forceinline__ void cp16(uint32_t dst, const void* src) {
    asm volatile("cp.async.cg.shared.global [%0], [%1], 16;" :: "r"(dst), "l"(src));
}
#define CP_COMMIT() asm volatile("cp.async.commit_group;" ::: "memory")
#define CP_WAIT(n)  asm volatile("cp.async.wait_group %0;" :: "n"(n) : "memory")

// helper: split fp32 -> (hi, lo) bf16
__device__ __forceinline__ void split2(float x, float y, uint32_t& h, uint32_t& l) {
    __nv_bfloat16 hx = __float2bfloat16(x);
    __nv_bfloat16 hy = __float2bfloat16(y);
    __nv_bfloat162 hp = __halves2bfloat162(hx, hy);
    __nv_bfloat162 lp = __halves2bfloat162(
        __float2bfloat16(x - __bfloat162float(hx)),
        __float2bfloat16(y - __bfloat162float(hy)));
    h = *reinterpret_cast<uint32_t*>(&hp);
    l = *reinterpret_cast<uint32_t*>(&lp);
}

// ======================= small utility kernels ================================
__global__ void zero_k(float* pooled, float* counts, float* sum, float* sq,
                       int* flag32, long n_pooled, int O)
{
    if (blockIdx.x == 0 && threadIdx.x == 0) *flag32 = 0;
    long total = n_pooled + O + 2 * 2304;
    for (long i = blockIdx.x * (long)blockDim.x + threadIdx.x; i < total;
         i += (long)gridDim.x * blockDim.x) {
        if (i < n_pooled)            pooled[i] = 0.f;
        else if (i < n_pooled + O)   counts[i - n_pooled] = 0.f;
        else {
            long j = i - n_pooled - O;
            if (j < 2304) sum[j] = 0.f; else sq[j - 2304] = 0.f;
        }
    }
}

__global__ void probe_k(const int* __restrict__ e32, int* flag32, int T)
{
    int t = blockIdx.x * blockDim.x + threadIdx.x;
    if (t >= T) return;
    if (e32[2 * t + 1] != 0) atomicOr(flag32, 1);
}

__global__ void convert_k(const int* __restrict__ e32, const int* __restrict__ flag32,
                          int* __restrict__ es, int* __restrict__ eo,
                          float* __restrict__ counts, int T)
{
    int t = blockIdx.x * blockDim.x + threadIdx.x;
    if (t >= T) return;
    int s, o;
    if (*flag32) { s = e32[2 * t]; o = e32[2 * t + 1]; }
    else         { s = e32[4 * t]; o = e32[4 * t + 2]; }
    es[t] = s;
    eo[t] = o;
    atomicAdd(&counts[s], 1.f);
    atomicAdd(&counts[o], 1.f);
}

// transpose + split weights: W[K,N] fp32 -> hi/lo bf16 [N,K]
__global__ void wsplit_k(const float* __restrict__ W,
                         __nv_bfloat16* __restrict__ hi, __nv_bfloat16* __restrict__ lo,
                         int K, int N)
{
    int i = blockIdx.x * blockDim.x + threadIdx.x;
    if (i >= K * N) return;
    int k = i / N, n = i % N;
    float v = W[i];
    __nv_bfloat16 h = __float2bfloat16(v);
    hi[(long)n * K + k] = h;
    lo[(long)n * K + k] = __float2bfloat16(v - __bfloat162float(h));
}

// plain fp32 -> hi/lo split (vectorized x4)
__global__ void asplit_k(const float* __restrict__ X,
                         __nv_bfloat16* __restrict__ h, __nv_bfloat16* __restrict__ l,
                         long n4)
{
    long i = blockIdx.x * (long)blockDim.x + threadIdx.x;
    if (i >= n4) return;
    float4 v = *reinterpret_cast<const float4*>(X + i * 4);
    uint32_t h01, l01, h23, l23;
    split2(v.x, v.y, h01, l01);
    split2(v.z, v.w, h23, l23);
    *reinterpret_cast<uint2*>(h + i * 4) = make_uint2(h01, h23);
    *reinterpret_cast<uint2*>(l + i * 4) = make_uint2(l01, l23);
}

// bn-apply + lrelu + split (N = 512, power of two)
__global__ void bnsplit_k(const float* __restrict__ X,
                          const float* __restrict__ cA, const float* __restrict__ cB,
                          __nv_bfloat16* __restrict__ h, __nv_bfloat16* __restrict__ l,
                          long n4, int N)
{
    long i = blockIdx.x * (long)blockDim.x + threadIdx.x;
    if (i >= n4) return;
    long e0 = i * 4;
    int c = (int)(e0 & (N - 1));
    float4 v = *reinterpret_cast<const float4*>(X + e0);
    float4 a = *reinterpret_cast<const float4*>(cA + c);
    float4 b = *reinterpret_cast<const float4*>(cB + c);
    v.x = fmaf(v.x, a.x, b.x); v.x = v.x >= 0.f ? v.x : ALPHA * v.x;
    v.y = fmaf(v.y, a.y, b.y); v.y = v.y >= 0.f ? v.y : ALPHA * v.y;
    v.z = fmaf(v.z, a.z, b.z); v.z = v.z >= 0.f ? v.z : ALPHA * v.z;
    v.w = fmaf(v.w, a.w, b.w); v.w = v.w >= 0.f ? v.w : ALPHA * v.w;
    uint32_t h01, l01, h23, l23;
    split2(v.x, v.y, h01, l01);
    split2(v.z, v.w, h23, l23);
    *reinterpret_cast<uint2*>(h + e0) = make_uint2(h01, h23);
    *reinterpret_cast<uint2*>(l + e0) = make_uint2(l01, l23);
}

// pooled / clamp(count) + split
__global__ void divsplit_k(const float* __restrict__ P, const float* __restrict__ cnt,
                           __nv_bfloat16* __restrict__ h, __nv_bfloat16* __restrict__ l,
                           long n4, float ocap)
{
    long i = blockIdx.x * (long)blockDim.x + threadIdx.x;
    if (i >= n4) return;
    long e0 = i * 4;
    float c = cnt[e0 >> 9];
    c = fminf(fmaxf(c, 1.f), ocap);
    float r = 1.f / c;
    float4 v = *reinterpret_cast<const float4*>(P + e0);
    v.x *= r; v.y *= r; v.z *= r; v.w *= r;
    uint32_t h01, l01, h23, l23;
    split2(v.x, v.y, h01, l01);
    split2(v.z, v.w, h23, l23);
    *reinterpret_cast<uint2*>(h + e0) = make_uint2(h01, h23);
    *reinterpret_cast<uint2*>(l + e0) = make_uint2(l01, l23);
}

// ======================= pipelined mma.sync GEMM ===============================
// C[M,N] = A[M,K] @ Wt^T + bias; A and Wt given pre-split bf16 hi/lo.
// bf16x3: hi*hi + hi*lo + lo*hi, fp32 accumulate.
// CTA 128x128, 8 warps (2x4), warp tile 64x32, K-chunk 64, 2-stage cp.async.
// Fused per-column sum / sum-of-squares of (acc+bias) into epilogue.
// GATHER: A row t = concat(obj[es[t]], pred[t], obj[eo[t]]) from split buffers.
#define ROWB  144                      // 128B data + 16B pad, conflict-free ldsm
#define STAGE (4 * 128 * ROWB)         // Ah, Al, Bh, Bl
#define GEMM_SMEM (2 * STAGE)          // 147456 B

template<bool GATHER>
__global__ void __launch_bounds__(256, 1)
mma_gemm_k(const __nv_bfloat16* __restrict__ Ah, const __nv_bfloat16* __restrict__ Al,
           const __nv_bfloat16* __restrict__ objh, const __nv_bfloat16* __restrict__ objl,
           const __nv_bfloat16* __restrict__ predh, const __nv_bfloat16* __restrict__ predl,
           const int* __restrict__ es, const int* __restrict__ eo,
           const __nv_bfloat16* __restrict__ Bth, const __nv_bfloat16* __restrict__ Btl,
           const float* __restrict__ bias,
           float* __restrict__ C, float* __restrict__ gsum, float* __restrict__ gsq,
           int M, int N, int K)
{
    extern __shared__ __align__(16) char smem[];
    const uint32_t sbase = smem_to_u32(smem);

    const int tid  = threadIdx.x;
    const int lane = tid & 31;
    const int wid  = tid >> 5;
    const int wm   = wid >> 2;
    const int wn   = wid & 3;
    const int m0   = blockIdx.y * 128, n0 = blockIdx.x * 128;
    const int q8   = lane >> 3;
    const int r8   = lane & 7;

    float acc[4][4][4];
#pragma unroll
    for (int i = 0; i < 4; i++)
#pragma unroll
        for (int j = 0; j < 4; j++)
#pragma unroll
            for (int q = 0; q < 4; q++) acc[i][j][q] = 0.f;

    const int nk = K >> 6;

    // ---- async load of one K-chunk into a stage ----
    auto load_chunk = [&](int k0, int stage) {
        const uint32_t aAh = sbase + stage * STAGE;
        const uint32_t aAl = aAh + 128 * ROWB;
        const uint32_t aBh = aAl + 128 * ROWB;
        const uint32_t aBl = aBh + 128 * ROWB;
        // A: 2 arrays x 128 rows x 8 chunks of 16B
#pragma unroll
        for (int i = 0; i < 8; i++) {
            int idx = tid + (i << 8);
            int arr = idx >> 10;
            int r   = (idx >> 3) & 127;
            int c   = idx & 7;
            int gm  = m0 + r;
            int gmc = gm < M ? gm : M - 1;
            const __nv_bfloat16* src;
            if (GATHER) {
                long sr; const __nv_bfloat16 *sh, *sl;
                if (k0 < 128)      { sr = (long)es[gmc]; sh = objh;  sl = objl;  }
                else if (k0 < 256) { sr = gmc;           sh = predh; sl = predl; }
                else               { sr = (long)eo[gmc]; sh = objh;  sl = objl;  }
                src = (arr ? sl : sh) + sr * 128 + (k0 & 127) + c * 8;
            } else {
                src = (arr ? Al : Ah) + (long)gmc * K + k0 + c * 8;
            }
            cp16((arr ? aAl : aAh) + r * ROWB + c * 16, src);
        }
        // B: 2 arrays x 128 rows x 8 chunks of 16B
#pragma unroll
        for (int i = 0; i < 8; i++) {
            int idx = tid + (i << 8);
            int arr = idx >> 10;
            int r   = (idx >> 3) & 127;
            int c   = idx & 7;
            const __nv_bfloat16* src = (arr ? Btl : Bth) + (long)(n0 + r) * K + k0 + c * 8;
            cp16((arr ? aBl : aBh) + r * ROWB + c * 16, src);
        }
        CP_COMMIT();
    };

    // ---- compute one K-chunk from a stage ----
    auto compute = [&](int stage) {
        const uint32_t aAh = sbase + stage * STAGE;
        const uint32_t aAl = aAh + 128 * ROWB;
        const uint32_t aBh = aAl + 128 * ROWB;
        const uint32_t aBl = aBh + 128 * ROWB;
#pragma unroll
        for (int s = 0; s < 4; s++) {
            uint32_t ah[4][4], al[4][4], bh[4][2], bl[4][2];
#pragma unroll
            for (int j = 0; j < 2; j++) {
                int nrow = wn * 32 + j * 16 + (q8 >> 1) * 8 + r8;
                int kb   = s * 32 + (q8 & 1) * 16;
                uint32_t addr = (uint32_t)(nrow * ROWB + kb);
                uint32_t r[4];
                ldsm_x4(aBh + addr, r);
                bh[2 * j][0] = r[0]; bh[2 * j][1] = r[1];
                bh[2 * j + 1][0] = r[2]; bh[2 * j + 1][1] = r[3];
                ldsm_x4(aBl + addr, r);
                bl[2 * j][0] = r[0]; bl[2 * j][1] = r[1];
                bl[2 * j + 1][0] = r[2]; bl[2 * j + 1][1] = r[3];
            }
#pragma unroll
            for (int mt = 0; mt < 4; mt++) {
                int mrow = wm * 64 + mt * 16 + (q8 & 1) * 8 + r8;
                int kb   = s * 32 + (q8 >> 1) * 16;
                uint32_t addr = (uint32_t)(mrow * ROWB + kb);
                ldsm_x4(aAh + addr, ah[mt]);
                ldsm_x4(aAl + addr, al[mt]);
            }
#pragma unroll
            for (int mt = 0; mt < 4; mt++)
#pragma unroll
                for (int nt = 0; nt < 4; nt++) {
                    mma_bf16(acc[mt][nt], ah[mt], bh[nt]);
                    mma_bf16(acc[mt][nt], ah[mt], bl[nt]);
                    mma_bf16(acc[mt][nt], al[mt], bh[nt]);
                }
        }
    };

    // ---- 2-stage pipeline ----
    load_chunk(0, 0);
    load_chunk(64, 1);
    for (int it = 0; it < nk; it++) {
        if (it == nk - 1) { CP_WAIT(0); } else { CP_WAIT(1); }
        __syncthreads();
        compute(it & 1);
        __syncthreads();
        if (it + 2 < nk) load_chunk((it + 2) << 6, it & 1);
    }

    // ---- epilogue: +bias, store, fused column stats ----
#pragma unroll
    for (int nt = 0; nt < 4; nt++) {
        int col = n0 + wn * 32 + nt * 8 + (lane & 3) * 2;
        float2 bv = *reinterpret_cast<const float2*>(bias + col);
        float s0 = 0.f, s1 = 0.f, q0 = 0.f, q1 = 0.f;
#pragma unroll
        for (int mt = 0; mt < 4; mt++) {
            int row0 = m0 + wm * 64 + mt * 16 + (lane >> 2);
            int row1 = row0 + 8;
            float v0 = acc[mt][nt][0] + bv.x;
            float v1 = acc[mt][nt][1] + bv.y;
            float v2 = acc[mt][nt][2] + bv.x;
            float v3 = acc[mt][nt][3] + bv.y;
            if (row0 < M) {
                *reinterpret_cast<float2*>(C + (long)row0 * N + col) = make_float2(v0, v1);
                s0 += v0; q0 += v0 * v0; s1 += v1; q1 += v1 * v1;
            }
            if (row1 < M) {
                *reinterpret_cast<float2*>(C + (long)row1 * N + col) = make_float2(v2, v3);
                s0 += v2; q0 += v2 * v2; s1 += v3; q1 += v3 * v3;
            }
        }
#pragma unroll
        for (int off = 4; off < 32; off <<= 1) {
            s0 += __shfl_down_sync(0xffffffffu, s0, off);
            s1 += __shfl_down_sync(0xffffffffu, s1, off);
            q0 += __shfl_down_sync(0xffffffffu, q0, off);
            q1 += __shfl_down_sync(0xffffffffu, q1, off);
        }
        if (lane < 4) {
            atomicAdd(&gsum[col],     s0);
            atomicAdd(&gsum[col + 1], s1);
            atomicAdd(&gsq[col],      q0);
            atomicAdd(&gsq[col + 1],  q1);
        }
    }
}

// ======================= stats finalize / BN out / scatter ====================
__global__ void finalize_k(const float* __restrict__ sum, const float* __restrict__ sq,
                           const float* __restrict__ gamma, const float* __restrict__ beta,
                           float invM, int N,
                           float* __restrict__ cA, float* __restrict__ cB)
{
    int n = blockIdx.x * blockDim.x + threadIdx.x;
    if (n >= N) return;
    float mean = sum[n] * invM;
    float var  = sq[n] * invM - mean * mean;
    float inv  = rsqrtf(var + EPS);
    float a    = inv * gamma[n];
    cA[n] = a;
    cB[n] = beta[n] - mean * a;
}

__global__ void bn_out_k(const float* __restrict__ X, const float* __restrict__ cA,
                         const float* __restrict__ cB, float* __restrict__ out,
                         long total, int N)
{
    long i = blockIdx.x * (long)blockDim.x + threadIdx.x;
    if (i >= total) return;
    int n = (int)(i % N);
    float v = X[i] * cA[n] + cB[n];
    out[i] = (v >= 0.f) ? v : ALPHA * v;
}

__global__ void scatter_k(const float* __restrict__ A2,
                          const float* __restrict__ cA, const float* __restrict__ cB,
                          const int* __restrict__ es, const int* __restrict__ eo,
                          float* __restrict__ pooled, float* __restrict__ out_p, int T)
{
    int t = blockIdx.x;
    if (t >= T) return;
    int s = es[t];
    int o = eo[t];
    const float* row = A2 + (long)t * 1152;
    for (int c = threadIdx.x; c < 1152; c += blockDim.x) {
        float v = row[c] * cA[c] + cB[c];
        v = (v >= 0.f) ? v : ALPHA * v;
        if (c < 512)       atomicAdd(&pooled[(long)s * 512 + c], v);
        else if (c < 640)  out_p[(long)t * 128 + (c - 512)] = v;
        else               atomicAdd(&pooled[(long)o * 512 + (c - 640)], v);
    }
}

// ======================= launch ================================================
extern "C" void kernel_launch(void* const* d_in, const int* in_sizes, int n_in,
                              void* d_out, int out_size)
{
    const float* obj   = (const float*)d_in[0];
    const float* pred  = (const float*)d_in[1];
    const int*   e32   = (const int*)d_in[2];
    const float* W1a = (const float*)d_in[3];
    const float* b1a = (const float*)d_in[4];
    const float* g1a = (const float*)d_in[5];
    const float* be1a= (const float*)d_in[6];
    const float* W1b = (const float*)d_in[7];
    const float* b1b = (const float*)d_in[8];
    const float* g1b = (const float*)d_in[9];
    const float* be1b= (const float*)d_in[10];
    const float* W2a = (const float*)d_in[11];
    const float* b2a = (const float*)d_in[12];
    const float* g2a = (const float*)d_in[13];
    const float* be2a= (const float*)d_in[14];
    const float* W2b = (const float*)d_in[15];
    const float* b2b = (const float*)d_in[16];
    const float* g2b = (const float*)d_in[17];
    const float* be2b= (const float*)d_in[18];

    const int O = in_sizes[0] / 128;
    const int T = in_sizes[1] / 128;

    float* out     = (float*)d_out;
    float* out_obj = out;
    float* out_p   = out + (size_t)O * 128;

    float *A1, *A2, *POOL, *A4, *CNT, *SUM, *SQ, *CA, *CB;
    int *ES, *EO, *FLAG;
    __nv_bfloat16 *WTH, *WTL, *OBJH, *OBJL, *PRH, *PRL, *XH, *XL;
    cudaGetSymbolAddress((void**)&A1,   g_A1);
    cudaGetSymbolAddress((void**)&A2,   g_A2);
    cudaGetSymbolAddress((void**)&POOL, g_pooled);
    cudaGetSymbolAddress((void**)&A4,   g_A4);
    cudaGetSymbolAddress((void**)&CNT,  g_counts);
    cudaGetSymbolAddress((void**)&SUM,  g_sum);
    cudaGetSymbolAddress((void**)&SQ,   g_sq);
    cudaGetSymbolAddress((void**)&CA,   g_cA);
    cudaGetSymbolAddress((void**)&CB,   g_cB);
    cudaGetSymbolAddress((void**)&ES,   g_es);
    cudaGetSymbolAddress((void**)&EO,   g_eo);
    cudaGetSymbolAddress((void**)&FLAG, g_flag32);
    cudaGetSymbolAddress((void**)&WTH,  g_wt_hi);
    cudaGetSymbolAddress((void**)&WTL,  g_wt_lo);
    cudaGetSymbolAddress((void**)&OBJH, g_objh);
    cudaGetSymbolAddress((void**)&OBJL, g_objl);
    cudaGetSymbolAddress((void**)&PRH,  g_predh);
    cudaGetSymbolAddress((void**)&PRL,  g_predl);
    cudaGetSymbolAddress((void**)&XH,   g_xh);
    cudaGetSymbolAddress((void**)&XL,   g_xl);

    cudaFuncSetAttribute(mma_gemm_k<true>,
                         cudaFuncAttributeMaxDynamicSharedMemorySize, GEMM_SMEM);
    cudaFuncSetAttribute(mma_gemm_k<false>,
                         cudaFuncAttributeMaxDynamicSharedMemorySize, GEMM_SMEM);

    const int OFF1 = 0, OFF2 = 512, OFF3 = 1664, OFF4 = 2176;
    const int W1A_OFF = 0, W1B_OFF = 196608, W2A_OFF = 786432, W2B_OFF = 1048576;

    // 0) zero accumulators; probe + normalize edges (+counts)
    zero_k<<<2048, 256>>>(POOL, CNT, SUM, SQ, FLAG, (long)O * 512, O);
    probe_k<<<(T + 255) / 256, 256>>>(e32, FLAG, T);
    convert_k<<<(T + 255) / 256, 256>>>(e32, FLAG, ES, EO, CNT, T);

    // 0b) split weights [N,K] and inputs obj/pred
    wsplit_k<<<(384 * 512  + 255) / 256, 256>>>(W1a, WTH + W1A_OFF, WTL + W1A_OFF, 384, 512);
    wsplit_k<<<(512 * 1152 + 255) / 256, 256>>>(W1b, WTH + W1B_OFF, WTL + W1B_OFF, 512, 1152);
    wsplit_k<<<(512 * 512  + 255) / 256, 256>>>(W2a, WTH + W2A_OFF, WTL + W2A_OFF, 512, 512);
    wsplit_k<<<(512 * 128  + 255) / 256, 256>>>(W2b, WTH + W2B_OFF, WTL + W2B_OFF, 512, 128);
    asplit_k<<<(unsigned)(((long)O * 32 + 255) / 256), 256>>>(obj,  OBJH, OBJL, (long)O * 32);
    asplit_k<<<(unsigned)(((long)T * 32 + 255) / 256), 256>>>(pred, PRH,  PRL,  (long)T * 32);

    // 1) GEMM1 (gathered): A1 = cur_t @ W1a + b1a  [T,512]  + L1 stats
    mma_gemm_k<true><<<dim3(4, (T + 127) / 128), 256, GEMM_SMEM>>>(
        nullptr, nullptr, OBJH, OBJL, PRH, PRL, ES, EO,
        WTH + W1A_OFF, WTL + W1A_OFF, b1a, A1, SUM + OFF1, SQ + OFF1, T, 512, 384);
    finalize_k<<<2, 256>>>(SUM + OFF1, SQ + OFF1, g1a, be1a, 1.f / T, 512, CA + OFF1, CB + OFF1);

    // 2) BN1-apply + lrelu + split -> XH/XL
    bnsplit_k<<<(unsigned)(((long)T * 128 + 255) / 256), 256>>>(
        A1, CA + OFF1, CB + OFF1, XH, XL, (long)T * 128, 512);

    // 3) GEMM2: A2 = X @ W1b + b1b  [T,1152]  + L2 stats
    mma_gemm_k<false><<<dim3(9, (T + 127) / 128), 256, GEMM_SMEM>>>(
        XH, XL, nullptr, nullptr, nullptr, nullptr, nullptr, nullptr,
        WTH + W1B_OFF, WTL + W1B_OFF, b1b, A2, SUM + OFF2, SQ + OFF2, T, 1152, 512);
    finalize_k<<<5, 256>>>(SUM + OFF2, SQ + OFF2, g1b, be1b, 1.f / T, 1152, CA + OFF2, CB + OFF2);

    // 4) scatter (BN2+lrelu fused) -> POOL raw sums, out_p
    scatter_k<<<T, 128>>>(A2, CA + OFF2, CB + OFF2, ES, EO, POOL, out_p, T);

    // 5) divide + split pooled -> XH/XL
    divsplit_k<<<(unsigned)(((long)O * 128 + 255) / 256), 256>>>(
        POOL, CNT, XH, XL, (long)O * 128, (float)O);

    // 6) GEMM3: A3(=A1) = X @ W2a + b2a  [O,512]  + L3 stats
    mma_gemm_k<false><<<dim3(4, (O + 127) / 128), 256, GEMM_SMEM>>>(
        XH, XL, nullptr, nullptr, nullptr, nullptr, nullptr, nullptr,
        WTH + W2A_OFF, WTL + W2A_OFF, b2a, A1, SUM + OFF3, SQ + OFF3, O, 512, 512);
    finalize_k<<<2, 256>>>(SUM + OFF3, SQ + OFF3, g2a, be2a, 1.f / O, 512, CA + OFF3, CB + OFF3);

    // 7) BN3-apply + lrelu + split -> XH/XL
    bnsplit_k<<<(unsigned)(((long)O * 128 + 255) / 256), 256>>>(
        A1, CA + OFF3, CB + OFF3, XH, XL, (long)O * 128, 512);

    // 8) GEMM4: A4 = X @ W2b + b2b  [O,128]  + L4 stats
    mma_gemm_k<false><<<dim3(1, (O + 127) / 128), 256, GEMM_SMEM>>>(
        XH, XL, nullptr, nullptr, nullptr, nullptr, nullptr, nullptr,
        WTH + W2B_OFF, WTL + W2B_OFF, b2b, A4, SUM + OFF4, SQ + OFF4, O, 128, 512);
    finalize_k<<<1, 256>>>(SUM + OFF4, SQ + OFF4, g2b, be2b, 1.f / O, 128, CA + OFF4, CB + OFF4);

    // 9) BN4 apply -> out_obj
    bn_out_k<<<(unsigned)(((long)O * 128 + 255) / 256), 256>>>(
        A4, CA + OFF4, CB + OFF4, out_obj, (long)O * 128, 128);
}

// round 7
// speedup vs baseline: 2.4607x; 1.0076x over previous
#include <cuda_runtime.h>
#include <cuda_bf16.h>
#include <cstdint>

#define EPS    1e-5f
#define ALPHA  0.2f
#define MAX_O  50000
#define MAX_T  200000

// ---------------- scratch (static device globals; no allocation) -------------
__device__ float g_A1[(size_t)MAX_T * 512];
__device__ float g_A2[(size_t)MAX_T * 1152];
__device__ float g_pooled[(size_t)MAX_O * 512];
__device__ float g_A4[(size_t)MAX_O * 128];
__device__ float g_counts[MAX_O];
__device__ int   g_es[MAX_T];
__device__ int   g_eo[MAX_T];
__device__ int   g_flag32;
__device__ __nv_bfloat16 g_objh[(size_t)MAX_O * 128];
__device__ __nv_bfloat16 g_objl[(size_t)MAX_O * 128];
__device__ __nv_bfloat16 g_predh[(size_t)MAX_T * 128];
__device__ __nv_bfloat16 g_predl[(size_t)MAX_T * 128];
__device__ __nv_bfloat16 g_xh[(size_t)MAX_T * 512];
__device__ __nv_bfloat16 g_xl[(size_t)MAX_T * 512];
#define WT_TOTAL 1114112
__device__ __nv_bfloat16 g_wt_hi[WT_TOTAL];
__device__ __nv_bfloat16 g_wt_lo[WT_TOTAL];
__device__ float g_sum[2304];
__device__ float g_sq[2304];
__device__ float g_cA[2304];
__device__ float g_cB[2304];

// ======================= PTX wrappers =========================================
__device__ __forceinline__ uint32_t smem_to_u32(const void* p) {
    uint32_t a;
    asm("{ .reg .u64 t; cvta.to.shared.u64 t, %1; cvt.u32.u64 %0, t; }" : "=r"(a) : "l"(p));
    return a;
}
__device__ __forceinline__ void ldsm_x4(uint32_t addr, uint32_t* r) {
    asm volatile("ldmatrix.sync.aligned.m8n8.x4.shared.b16 {%0,%1,%2,%3}, [%4];"
        : "=r"(r[0]), "=r"(r[1]), "=r"(r[2]), "=r"(r[3]) : "r"(addr));
}
__device__ __forceinline__ void mma_bf16(float* c, const uint32_t* a, const uint32_t* b) {
    asm volatile("mma.sync.aligned.m16n8k16.row.col.f32.bf16.bf16.f32 "
        "{%0,%1,%2,%3},{%4,%5,%6,%7},{%8,%9},{%0,%1,%2,%3};"
        : "+f"(c[0]), "+f"(c[1]), "+f"(c[2]), "+f"(c[3])
        : "r"(a[0]), "r"(a[1]), "r"(a[2]), "r"(a[3]), "r"(b[0]), "r"(b[1]));
}
__device__ __forceinline__ void cp16(uint32_t dst, const void* src) {
    asm volatile("cp.async.cg.shared.global [%0], [%1], 16;" :: "r"(dst), "l"(src));
}
#define CP_COMMIT() asm volatile("cp.async.commit_group;" ::: "memory")
#define CP_WAIT(n)  asm volatile("cp.async.wait_group %0;" :: "n"(n) : "memory")

__device__ __forceinline__ void split2(float x, float y, uint32_t& h, uint32_t& l) {
    __nv_bfloat16 hx = __float2bfloat16(x);
    __nv_bfloat16 hy = __float2bfloat16(y);
    __nv_bfloat162 hp = __halves2bfloat162(hx, hy);
    __nv_bfloat162 lp = __halves2bfloat162(
        __float2bfloat16(x - __bfloat162float(hx)),
        __float2bfloat16(y - __bfloat162float(hy)));
    h = *reinterpret_cast<uint32_t*>(&hp);
    l = *reinterpret_cast<uint32_t*>(&lp);
}

// ======================= small utility kernels ================================
__global__ void zero_k(float* pooled, float* counts, float* sum, float* sq,
                       int* flag32, long n_pooled, int O)
{
    if (blockIdx.x == 0 && threadIdx.x == 0) *flag32 = 0;
    long total = n_pooled + O + 2 * 2304;
    for (long i = blockIdx.x * (long)blockDim.x + threadIdx.x; i < total;
         i += (long)gridDim.x * blockDim.x) {
        if (i < n_pooled)            pooled[i] = 0.f;
        else if (i < n_pooled + O)   counts[i - n_pooled] = 0.f;
        else {
            long j = i - n_pooled - O;
            if (j < 2304) sum[j] = 0.f; else sq[j - 2304] = 0.f;
        }
    }
}

__global__ void probe_k(const int* __restrict__ e32, int* flag32, int T)
{
    int t = blockIdx.x * blockDim.x + threadIdx.x;
    if (t >= T) return;
    if (e32[2 * t + 1] != 0) atomicOr(flag32, 1);
}

__global__ void convert_k(const int* __restrict__ e32, const int* __restrict__ flag32,
                          int* __restrict__ es, int* __restrict__ eo,
                          float* __restrict__ counts, int T)
{
    int t = blockIdx.x * blockDim.x + threadIdx.x;
    if (t >= T) return;
    int s, o;
    if (*flag32) { s = e32[2 * t]; o = e32[2 * t + 1]; }
    else         { s = e32[4 * t]; o = e32[4 * t + 2]; }
    es[t] = s;
    eo[t] = o;
    atomicAdd(&counts[s], 1.f);
    atomicAdd(&counts[o], 1.f);
}

__global__ void wsplit_k(const float* __restrict__ W,
                         __nv_bfloat16* __restrict__ hi, __nv_bfloat16* __restrict__ lo,
                         int K, int N)
{
    int i = blockIdx.x * blockDim.x + threadIdx.x;
    if (i >= K * N) return;
    int k = i / N, n = i % N;
    float v = W[i];
    __nv_bfloat16 h = __float2bfloat16(v);
    hi[(long)n * K + k] = h;
    lo[(long)n * K + k] = __float2bfloat16(v - __bfloat162float(h));
}

__global__ void asplit_k(const float* __restrict__ X,
                         __nv_bfloat16* __restrict__ h, __nv_bfloat16* __restrict__ l,
                         long n4)
{
    long i = blockIdx.x * (long)blockDim.x + threadIdx.x;
    if (i >= n4) return;
    float4 v = *reinterpret_cast<const float4*>(X + i * 4);
    uint32_t h01, l01, h23, l23;
    split2(v.x, v.y, h01, l01);
    split2(v.z, v.w, h23, l23);
    *reinterpret_cast<uint2*>(h + i * 4) = make_uint2(h01, h23);
    *reinterpret_cast<uint2*>(l + i * 4) = make_uint2(l01, l23);
}

__global__ void bnsplit_k(const float* __restrict__ X,
                          const float* __restrict__ cA, const float* __restrict__ cB,
                          __nv_bfloat16* __restrict__ h, __nv_bfloat16* __restrict__ l,
                          long n4, int N)
{
    long i = blockIdx.x * (long)blockDim.x + threadIdx.x;
    if (i >= n4) return;
    long e0 = i * 4;
    int c = (int)(e0 & (N - 1));
    float4 v = *reinterpret_cast<const float4*>(X + e0);
    float4 a = *reinterpret_cast<const float4*>(cA + c);
    float4 b = *reinterpret_cast<const float4*>(cB + c);
    v.x = fmaf(v.x, a.x, b.x); v.x = v.x >= 0.f ? v.x : ALPHA * v.x;
    v.y = fmaf(v.y, a.y, b.y); v.y = v.y >= 0.f ? v.y : ALPHA * v.y;
    v.z = fmaf(v.z, a.z, b.z); v.z = v.z >= 0.f ? v.z : ALPHA * v.z;
    v.w = fmaf(v.w, a.w, b.w); v.w = v.w >= 0.f ? v.w : ALPHA * v.w;
    uint32_t h01, l01, h23, l23;
    split2(v.x, v.y, h01, l01);
    split2(v.z, v.w, h23, l23);
    *reinterpret_cast<uint2*>(h + e0) = make_uint2(h01, h23);
    *reinterpret_cast<uint2*>(l + e0) = make_uint2(l01, l23);
}

__global__ void divsplit_k(const float* __restrict__ P, const float* __restrict__ cnt,
                           __nv_bfloat16* __restrict__ h, __nv_bfloat16* __restrict__ l,
                           long n4, float ocap)
{
    long i = blockIdx.x * (long)blockDim.x + threadIdx.x;
    if (i >= n4) return;
    long e0 = i * 4;
    float c = cnt[e0 >> 9];
    c = fminf(fmaxf(c, 1.f), ocap);
    float r = 1.f / c;
    float4 v = *reinterpret_cast<const float4*>(P + e0);
    v.x *= r; v.y *= r; v.z *= r; v.w *= r;
    uint32_t h01, l01, h23, l23;
    split2(v.x, v.y, h01, l01);
    split2(v.z, v.w, h23, l23);
    *reinterpret_cast<uint2*>(h + e0) = make_uint2(h01, h23);
    *reinterpret_cast<uint2*>(l + e0) = make_uint2(l01, l23);
}

// ======================= pipelined mma.sync GEMM ===============================
// CTA 128x128, 8 warps (2x4), warp tile 64x32.
// K-chunk 32, 4-stage cp.async, ONE __syncthreads per chunk.
// bf16x3: hi*hi + hi*lo + lo*hi, fp32 accumulate. Fused column stats.
#define ROWB   80                       // 64B data + 16B pad, ldsm conflict-free
#define STAGE  (4 * 128 * ROWB)         // 40960 B: Ah, Al, Bh, Bl
#define NSTG   4
#define GEMM_SMEM (NSTG * STAGE)        // 163840 B

template<bool GATHER>
__global__ void __launch_bounds__(256, 1)
mma_gemm_k(const __nv_bfloat16* __restrict__ Ah, const __nv_bfloat16* __restrict__ Al,
           const __nv_bfloat16* __restrict__ objh, const __nv_bfloat16* __restrict__ objl,
           const __nv_bfloat16* __restrict__ predh, const __nv_bfloat16* __restrict__ predl,
           const int* __restrict__ es, const int* __restrict__ eo,
           const __nv_bfloat16* __restrict__ Bth, const __nv_bfloat16* __restrict__ Btl,
           const float* __restrict__ bias,
           float* __restrict__ C, float* __restrict__ gsum, float* __restrict__ gsq,
           int M, int N, int K)
{
    extern __shared__ __align__(16) char smem[];
    const uint32_t sbase = smem_to_u32(smem);

    const int tid  = threadIdx.x;
    const int lane = tid & 31;
    const int wid  = tid >> 5;
    const int wm   = wid >> 2;
    const int wn   = wid & 3;
    const int m0   = blockIdx.y * 128, n0 = blockIdx.x * 128;
    const int q8   = lane >> 3;
    const int r8   = lane & 7;

    float acc[4][4][4];
#pragma unroll
    for (int i = 0; i < 4; i++)
#pragma unroll
        for (int j = 0; j < 4; j++)
#pragma unroll
            for (int q = 0; q < 4; q++) acc[i][j][q] = 0.f;

    const int nk = K >> 5;    // K chunks of 32

    // ---- async load of one K32-chunk into a stage ----
    auto load_chunk = [&](int k0, int stage) {
        const uint32_t aAh = sbase + stage * STAGE;
        const uint32_t aAl = aAh + 128 * ROWB;
        const uint32_t aBh = aAl + 128 * ROWB;
        const uint32_t aBl = aBh + 128 * ROWB;
        // A: 2 arrays x 128 rows x 4 chunks of 16B  (1024 cp16 / 256 thr = 4)
#pragma unroll
        for (int i = 0; i < 4; i++) {
            int idx = tid + (i << 8);
            int arr = idx >> 9;
            int r   = (idx >> 2) & 127;
            int c   = idx & 3;
            int gm  = m0 + r;
            int gmc = gm < M ? gm : M - 1;
            const __nv_bfloat16* src;
            if (GATHER) {
                long sr; const __nv_bfloat16 *sh, *sl;
                if (k0 < 128)      { sr = (long)es[gmc]; sh = objh;  sl = objl;  }
                else if (k0 < 256) { sr = gmc;           sh = predh; sl = predl; }
                else               { sr = (long)eo[gmc]; sh = objh;  sl = objl;  }
                src = (arr ? sl : sh) + sr * 128 + (k0 & 127) + c * 8;
            } else {
                src = (arr ? Al : Ah) + (long)gmc * K + k0 + c * 8;
            }
            cp16((arr ? aAl : aAh) + r * ROWB + c * 16, src);
        }
        // B: 2 arrays x 128 rows x 4 chunks of 16B
#pragma unroll
        for (int i = 0; i < 4; i++) {
            int idx = tid + (i << 8);
            int arr = idx >> 9;
            int r   = (idx >> 2) & 127;
            int c   = idx & 3;
            const __nv_bfloat16* src = (arr ? Btl : Bth) + (long)(n0 + r) * K + k0 + c * 8;
            cp16((arr ? aBl : aBh) + r * ROWB + c * 16, src);
        }
        CP_COMMIT();
    };

    // ---- compute one K32-chunk (2 k16 steps); B fragments hoisted ----
    auto compute = [&](int stage) {
        const uint32_t aAh = sbase + stage * STAGE;
        const uint32_t aAl = aAh + 128 * ROWB;
        const uint32_t aBh = aAl + 128 * ROWB;
        const uint32_t aBl = aBh + 128 * ROWB;
        uint32_t bh[2][4][2], bl[2][4][2];
#pragma unroll
        for (int s = 0; s < 2; s++)
#pragma unroll
            for (int j = 0; j < 2; j++) {
                int nrow = wn * 32 + j * 16 + (q8 >> 1) * 8 + r8;
                int kb   = s * 32 + (q8 & 1) * 16;
                uint32_t addr = (uint32_t)(nrow * ROWB + kb);
                uint32_t r[4];
                ldsm_x4(aBh + addr, r);
                bh[s][2 * j][0] = r[0]; bh[s][2 * j][1] = r[1];
                bh[s][2 * j + 1][0] = r[2]; bh[s][2 * j + 1][1] = r[3];
                ldsm_x4(aBl + addr, r);
                bl[s][2 * j][0] = r[0]; bl[s][2 * j][1] = r[1];
                bl[s][2 * j + 1][0] = r[2]; bl[s][2 * j + 1][1] = r[3];
            }
#pragma unroll
        for (int s = 0; s < 2; s++) {
            uint32_t ah[4][4], al[4][4];
#pragma unroll
            for (int mt = 0; mt < 4; mt++) {
                int mrow = wm * 64 + mt * 16 + (q8 & 1) * 8 + r8;
                int kb   = s * 32 + (q8 >> 1) * 16;
                uint32_t addr = (uint32_t)(mrow * ROWB + kb);
                ldsm_x4(aAh + addr, ah[mt]);
                ldsm_x4(aAl + addr, al[mt]);
            }
#pragma unroll
            for (int mt = 0; mt < 4; mt++)
#pragma unroll
                for (int nt = 0; nt < 4; nt++) {
                    mma_bf16(acc[mt][nt], ah[mt], bh[s][nt]);
                    mma_bf16(acc[mt][nt], ah[mt], bl[s][nt]);
                    mma_bf16(acc[mt][nt], al[mt], bh[s][nt]);
                }
        }
    };

    // ---- 4-stage pipeline, one sync per chunk ----
    load_chunk(0, 0);
    load_chunk(32, 1);
    load_chunk(64, 2);
    for (int it = 0; it < nk; it++) {
        CP_WAIT(2);
        __syncthreads();
        compute(it & (NSTG - 1));
        if (it + 3 < nk) load_chunk((it + 3) << 5, (it + 3) & (NSTG - 1));
    }

    // ---- epilogue: +bias, store, fused column stats ----
#pragma unroll
    for (int nt = 0; nt < 4; nt++) {
        int col = n0 + wn * 32 + nt * 8 + (lane & 3) * 2;
        float2 bv = *reinterpret_cast<const float2*>(bias + col);
        float s0 = 0.f, s1 = 0.f, q0 = 0.f, q1 = 0.f;
#pragma unroll
        for (int mt = 0; mt < 4; mt++) {
            int row0 = m0 + wm * 64 + mt * 16 + (lane >> 2);
            int row1 = row0 + 8;
            float v0 = acc[mt][nt][0] + bv.x;
            float v1 = acc[mt][nt][1] + bv.y;
            float v2 = acc[mt][nt][2] + bv.x;
            float v3 = acc[mt][nt][3] + bv.y;
            if (row0 < M) {
                *reinterpret_cast<float2*>(C + (long)row0 * N + col) = make_float2(v0, v1);
                s0 += v0; q0 += v0 * v0; s1 += v1; q1 += v1 * v1;
            }
            if (row1 < M) {
                *reinterpret_cast<float2*>(C + (long)row1 * N + col) = make_float2(v2, v3);
                s0 += v2; q0 += v2 * v2; s1 += v3; q1 += v3 * v3;
            }
        }
#pragma unroll
        for (int off = 4; off < 32; off <<= 1) {
            s0 += __shfl_down_sync(0xffffffffu, s0, off);
            s1 += __shfl_down_sync(0xffffffffu, s1, off);
            q0 += __shfl_down_sync(0xffffffffu, q0, off);
            q1 += __shfl_down_sync(0xffffffffu, q1, off);
        }
        if (lane < 4) {
            atomicAdd(&gsum[col],     s0);
            atomicAdd(&gsum[col + 1], s1);
            atomicAdd(&gsq[col],      q0);
            atomicAdd(&gsq[col + 1],  q1);
        }
    }
}

// ======================= stats finalize / BN out / scatter ====================
__global__ void finalize_k(const float* __restrict__ sum, const float* __restrict__ sq,
                           const float* __restrict__ gamma, const float* __restrict__ beta,
                           float invM, int N,
                           float* __restrict__ cA, float* __restrict__ cB)
{
    int n = blockIdx.x * blockDim.x + threadIdx.x;
    if (n >= N) return;
    float mean = sum[n] * invM;
    float var  = sq[n] * invM - mean * mean;
    float inv  = rsqrtf(var + EPS);
    float a    = inv * gamma[n];
    cA[n] = a;
    cB[n] = beta[n] - mean * a;
}

__global__ void bn_out_k(const float* __restrict__ X, const float* __restrict__ cA,
                         const float* __restrict__ cB, float* __restrict__ out,
                         long total, int N)
{
    long i = blockIdx.x * (long)blockDim.x + threadIdx.x;
    if (i >= total) return;
    int n = (int)(i % N);
    float v = X[i] * cA[n] + cB[n];
    out[i] = (v >= 0.f) ? v : ALPHA * v;
}

__global__ void scatter_k(const float* __restrict__ A2,
                          const float* __restrict__ cA, const float* __restrict__ cB,
                          const int* __restrict__ es, const int* __restrict__ eo,
                          float* __restrict__ pooled, float* __restrict__ out_p, int T)
{
    int t = blockIdx.x;
    if (t >= T) return;
    int s = es[t];
    int o = eo[t];
    const float* row = A2 + (long)t * 1152;
    for (int c = threadIdx.x; c < 1152; c += blockDim.x) {
        float v = row[c] * cA[c] + cB[c];
        v = (v >= 0.f) ? v : ALPHA * v;
        if (c < 512)       atomicAdd(&pooled[(long)s * 512 + c], v);
        else if (c < 640)  out_p[(long)t * 128 + (c - 512)] = v;
        else               atomicAdd(&pooled[(long)o * 512 + (c - 640)], v);
    }
}

// ======================= launch ================================================
extern "C" void kernel_launch(void* const* d_in, const int* in_sizes, int n_in,
                              void* d_out, int out_size)
{
    const float* obj   = (const float*)d_in[0];
    const float* pred  = (const float*)d_in[1];
    const int*   e32   = (const int*)d_in[2];
    const float* W1a = (const float*)d_in[3];
    const float* b1a = (const float*)d_in[4];
    const float* g1a = (const float*)d_in[5];
    const float* be1a= (const float*)d_in[6];
    const float* W1b = (const float*)d_in[7];
    const float* b1b = (const float*)d_in[8];
    const float* g1b = (const float*)d_in[9];
    const float* be1b= (const float*)d_in[10];
    const float* W2a = (const float*)d_in[11];
    const float* b2a = (const float*)d_in[12];
    const float* g2a = (const float*)d_in[13];
    const float* be2a= (const float*)d_in[14];
    const float* W2b = (const float*)d_in[15];
    const float* b2b = (const float*)d_in[16];
    const float* g2b = (const float*)d_in[17];
    const float* be2b= (const float*)d_in[18];

    const int O = in_sizes[0] / 128;
    const int T = in_sizes[1] / 128;

    float* out     = (float*)d_out;
    float* out_obj = out;
    float* out_p   = out + (size_t)O * 128;

    float *A1, *A2, *POOL, *A4, *CNT, *SUM, *SQ, *CA, *CB;
    int *ES, *EO, *FLAG;
    __nv_bfloat16 *WTH, *WTL, *OBJH, *OBJL, *PRH, *PRL, *XH, *XL;
    cudaGetSymbolAddress((void**)&A1,   g_A1);
    cudaGetSymbolAddress((void**)&A2,   g_A2);
    cudaGetSymbolAddress((void**)&POOL, g_pooled);
    cudaGetSymbolAddress((void**)&A4,   g_A4);
    cudaGetSymbolAddress((void**)&CNT,  g_counts);
    cudaGetSymbolAddress((void**)&SUM,  g_sum);
    cudaGetSymbolAddress((void**)&SQ,   g_sq);
    cudaGetSymbolAddress((void**)&CA,   g_cA);
    cudaGetSymbolAddress((void**)&CB,   g_cB);
    cudaGetSymbolAddress((void**)&ES,   g_es);
    cudaGetSymbolAddress((void**)&EO,   g_eo);
    cudaGetSymbolAddress((void**)&FLAG, g_flag32);
    cudaGetSymbolAddress((void**)&WTH,  g_wt_hi);
    cudaGetSymbolAddress((void**)&WTL,  g_wt_lo);
    cudaGetSymbolAddress((void**)&OBJH, g_objh);
    cudaGetSymbolAddress((void**)&OBJL, g_objl);
    cudaGetSymbolAddress((void**)&PRH,  g_predh);
    cudaGetSymbolAddress((void**)&PRL,  g_predl);
    cudaGetSymbolAddress((void**)&XH,   g_xh);
    cudaGetSymbolAddress((void**)&XL,   g_xl);

    cudaFuncSetAttribute(mma_gemm_k<true>,
                         cudaFuncAttributeMaxDynamicSharedMemorySize, GEMM_SMEM);
    cudaFuncSetAttribute(mma_gemm_k<false>,
                         cudaFuncAttributeMaxDynamicSharedMemorySize, GEMM_SMEM);

    const int OFF1 = 0, OFF2 = 512, OFF3 = 1664, OFF4 = 2176;
    const int W1A_OFF = 0, W1B_OFF = 196608, W2A_OFF = 786432, W2B_OFF = 1048576;

    // 0) zero accumulators; probe + normalize edges (+counts)
    zero_k<<<2048, 256>>>(POOL, CNT, SUM, SQ, FLAG, (long)O * 512, O);
    probe_k<<<(T + 255) / 256, 256>>>(e32, FLAG, T);
    convert_k<<<(T + 255) / 256, 256>>>(e32, FLAG, ES, EO, CNT, T);

    // 0b) split weights [N,K] and inputs obj/pred
    wsplit_k<<<(384 * 512  + 255) / 256, 256>>>(W1a, WTH + W1A_OFF, WTL + W1A_OFF, 384, 512);
    wsplit_k<<<(512 * 1152 + 255) / 256, 256>>>(W1b, WTH + W1B_OFF, WTL + W1B_OFF, 512, 1152);
    wsplit_k<<<(512 * 512  + 255) / 256, 256>>>(W2a, WTH + W2A_OFF, WTL + W2A_OFF, 512, 512);
    wsplit_k<<<(512 * 128  + 255) / 256, 256>>>(W2b, WTH + W2B_OFF, WTL + W2B_OFF, 512, 128);
    asplit_k<<<(unsigned)(((long)O * 32 + 255) / 256), 256>>>(obj,  OBJH, OBJL, (long)O * 32);
    asplit_k<<<(unsigned)(((long)T * 32 + 255) / 256), 256>>>(pred, PRH,  PRL,  (long)T * 32);

    // 1) GEMM1 (gathered): A1 = cur_t @ W1a + b1a  [T,512]  + L1 stats
    mma_gemm_k<true><<<dim3(4, (T + 127) / 128), 256, GEMM_SMEM>>>(
        nullptr, nullptr, OBJH, OBJL, PRH, PRL, ES, EO,
        WTH + W1A_OFF, WTL + W1A_OFF, b1a, A1, SUM + OFF1, SQ + OFF1, T, 512, 384);
    finalize_k<<<2, 256>>>(SUM + OFF1, SQ + OFF1, g1a, be1a, 1.f / T, 512, CA + OFF1, CB + OFF1);

    // 2) BN1-apply + lrelu + split -> XH/XL
    bnsplit_k<<<(unsigned)(((long)T * 128 + 255) / 256), 256>>>(
        A1, CA + OFF1, CB + OFF1, XH, XL, (long)T * 128, 512);

    // 3) GEMM2: A2 = X @ W1b + b1b  [T,1152]  + L2 stats
    mma_gemm_k<false><<<dim3(9, (T + 127) / 128), 256, GEMM_SMEM>>>(
        XH, XL, nullptr, nullptr, nullptr, nullptr, nullptr, nullptr,
        WTH + W1B_OFF, WTL + W1B_OFF, b1b, A2, SUM + OFF2, SQ + OFF2, T, 1152, 512);
    finalize_k<<<5, 256>>>(SUM + OFF2, SQ + OFF2, g1b, be1b, 1.f / T, 1152, CA + OFF2, CB + OFF2);

    // 4) scatter (BN2+lrelu fused) -> POOL raw sums, out_p
    scatter_k<<<T, 128>>>(A2, CA + OFF2, CB + OFF2, ES, EO, POOL, out_p, T);

    // 5) divide + split pooled -> XH/XL
    divsplit_k<<<(unsigned)(((long)O * 128 + 255) / 256), 256>>>(
        POOL, CNT, XH, XL, (long)O * 128, (float)O);

    // 6) GEMM3: A3(=A1) = X @ W2a + b2a  [O,512]  + L3 stats
    mma_gemm_k<false><<<dim3(4, (O + 127) / 128), 256, GEMM_SMEM>>>(
        XH, XL, nullptr, nullptr, nullptr, nullptr, nullptr, nullptr,
        WTH + W2A_OFF, WTL + W2A_OFF, b2a, A1, SUM + OFF3, SQ + OFF3, O, 512, 512);
    finalize_k<<<2, 256>>>(SUM + OFF3, SQ + OFF3, g2a, be2a, 1.f / O, 512, CA + OFF3, CB + OFF3);

    // 7) BN3-apply + lrelu + split -> XH/XL
    bnsplit_k<<<(unsigned)(((long)O * 128 + 255) / 256), 256>>>(
        A1, CA + OFF3, CB + OFF3, XH, XL, (long)O * 128, 512);

    // 8) GEMM4: A4 = X @ W2b + b2b  [O,128]  + L4 stats
    mma_gemm_k<false><<<dim3(1, (O + 127) / 128), 256, GEMM_SMEM>>>(
        XH, XL, nullptr, nullptr, nullptr, nullptr, nullptr, nullptr,
        WTH + W2B_OFF, WTL + W2B_OFF, b2b, A4, SUM + OFF4, SQ + OFF4, O, 128, 512);
    finalize_k<<<1, 256>>>(SUM + OFF4, SQ + OFF4, g2b, be2b, 1.f / O, 128, CA + OFF4, CB + OFF4);

    // 9) BN4 apply -> out_obj
    bn_out_k<<<(unsigned)(((long)O * 128 + 255) / 256), 256>>>(
        A4, CA + OFF4, CB + OFF4, out_obj, (long)O * 128, 128);
}

// round 8
// speedup vs baseline: 2.5413x; 1.0328x over previous
#include <cuda_runtime.h>
#include <cuda_bf16.h>
#include <cstdint>

#define EPS    1e-5f
#define ALPHA  0.2f
#define MAX_O  50000
#define MAX_T  200000

// ---------------- scratch (static device globals; no allocation) -------------
__device__ float g_A1[(size_t)MAX_T * 512];
__device__ float g_A2[(size_t)MAX_T * 1152];
__device__ float g_pooled[(size_t)MAX_O * 512];
__device__ float g_A4[(size_t)MAX_O * 128];
__device__ float g_counts[MAX_O];
__device__ int   g_es[MAX_T];
__device__ int   g_eo[MAX_T];
__device__ int   g_flag32;
__device__ __nv_bfloat16 g_objh[(size_t)MAX_O * 128];
__device__ __nv_bfloat16 g_objl[(size_t)MAX_O * 128];
__device__ __nv_bfloat16 g_predh[(size_t)MAX_T * 128];
__device__ __nv_bfloat16 g_predl[(size_t)MAX_T * 128];
__device__ __nv_bfloat16 g_xh[(size_t)MAX_T * 512];
__device__ __nv_bfloat16 g_xl[(size_t)MAX_T * 512];
#define WT_TOTAL 1114112
__device__ __nv_bfloat16 g_wt_hi[WT_TOTAL];
__device__ __nv_bfloat16 g_wt_lo[WT_TOTAL];
__device__ float g_sum[2304];
__device__ float g_sq[2304];
__device__ float g_cA[2304];
__device__ float g_cB[2304];

// ======================= PTX wrappers =========================================
__device__ __forceinline__ uint32_t smem_to_u32(const void* p) {
    uint32_t a;
    asm("{ .reg .u64 t; cvta.to.shared.u64 t, %1; cvt.u32.u64 %0, t; }" : "=r"(a) : "l"(p));
    return a;
}
__device__ __forceinline__ void ldsm_x4(uint32_t addr, uint32_t* r) {
    asm volatile("ldmatrix.sync.aligned.m8n8.x4.shared.b16 {%0,%1,%2,%3}, [%4];"
        : "=r"(r[0]), "=r"(r[1]), "=r"(r[2]), "=r"(r[3]) : "r"(addr));
}
__device__ __forceinline__ void mma_bf16(float* c, const uint32_t* a, const uint32_t* b) {
    asm volatile("mma.sync.aligned.m16n8k16.row.col.f32.bf16.bf16.f32 "
        "{%0,%1,%2,%3},{%4,%5,%6,%7},{%8,%9},{%0,%1,%2,%3};"
        : "+f"(c[0]), "+f"(c[1]), "+f"(c[2]), "+f"(c[3])
        : "r"(a[0]), "r"(a[1]), "r"(a[2]), "r"(a[3]), "r"(b[0]), "r"(b[1]));
}
__device__ __forceinline__ void cp16(uint32_t dst, const void* src) {
    asm volatile("cp.async.cg.shared.global [%0], [%1], 16;" :: "r"(dst), "l"(src));
}
#define CP_COMMIT() asm volatile("cp.async.commit_group;" ::: "memory")
#define CP_WAIT(n)  asm volatile("cp.async.wait_group %0;" :: "n"(n) : "memory")

__device__ __forceinline__ void red4(float* addr, float4 v) {
    asm volatile("red.global.add.v4.f32 [%0], {%1,%2,%3,%4};"
        :: "l"(addr), "f"(v.x), "f"(v.y), "f"(v.z), "f"(v.w) : "memory");
}

__device__ __forceinline__ void split2(float x, float y, uint32_t& h, uint32_t& l) {
    __nv_bfloat16 hx = __float2bfloat16(x);
    __nv_bfloat16 hy = __float2bfloat16(y);
    __nv_bfloat162 hp = __halves2bfloat162(hx, hy);
    __nv_bfloat162 lp = __halves2bfloat162(
        __float2bfloat16(x - __bfloat162float(hx)),
        __float2bfloat16(y - __bfloat162float(hy)));
    h = *reinterpret_cast<uint32_t*>(&hp);
    l = *reinterpret_cast<uint32_t*>(&lp);
}

// ======================= small utility kernels ================================
__global__ void zero_k(float* pooled, float* counts, float* sum, float* sq,
                       int* flag32, long n_pooled, int O)
{
    if (blockIdx.x == 0 && threadIdx.x == 0) *flag32 = 0;
    long total = n_pooled + O + 2 * 2304;
    for (long i = blockIdx.x * (long)blockDim.x + threadIdx.x; i < total;
         i += (long)gridDim.x * blockDim.x) {
        if (i < n_pooled)            pooled[i] = 0.f;
        else if (i < n_pooled + O)   counts[i - n_pooled] = 0.f;
        else {
            long j = i - n_pooled - O;
            if (j < 2304) sum[j] = 0.f; else sq[j - 2304] = 0.f;
        }
    }
}

__global__ void probe_k(const int* __restrict__ e32, int* flag32, int T)
{
    int t = blockIdx.x * blockDim.x + threadIdx.x;
    if (t >= T) return;
    if (e32[2 * t + 1] != 0) atomicOr(flag32, 1);
}

__global__ void convert_k(const int* __restrict__ e32, const int* __restrict__ flag32,
                          int* __restrict__ es, int* __restrict__ eo,
                          float* __restrict__ counts, int T)
{
    int t = blockIdx.x * blockDim.x + threadIdx.x;
    if (t >= T) return;
    int s, o;
    if (*flag32) { s = e32[2 * t]; o = e32[2 * t + 1]; }
    else         { s = e32[4 * t]; o = e32[4 * t + 2]; }
    es[t] = s;
    eo[t] = o;
    atomicAdd(&counts[s], 1.f);
    atomicAdd(&counts[o], 1.f);
}

__global__ void wsplit_k(const float* __restrict__ W,
                         __nv_bfloat16* __restrict__ hi, __nv_bfloat16* __restrict__ lo,
                         int K, int N)
{
    int i = blockIdx.x * blockDim.x + threadIdx.x;
    if (i >= K * N) return;
    int k = i / N, n = i % N;
    float v = W[i];
    __nv_bfloat16 h = __float2bfloat16(v);
    hi[(long)n * K + k] = h;
    lo[(long)n * K + k] = __float2bfloat16(v - __bfloat162float(h));
}

__global__ void asplit_k(const float* __restrict__ X,
                         __nv_bfloat16* __restrict__ h, __nv_bfloat16* __restrict__ l,
                         long n4)
{
    long i = blockIdx.x * (long)blockDim.x + threadIdx.x;
    if (i >= n4) return;
    float4 v = *reinterpret_cast<const float4*>(X + i * 4);
    uint32_t h01, l01, h23, l23;
    split2(v.x, v.y, h01, l01);
    split2(v.z, v.w, h23, l23);
    *reinterpret_cast<uint2*>(h + i * 4) = make_uint2(h01, h23);
    *reinterpret_cast<uint2*>(l + i * 4) = make_uint2(l01, l23);
}

__global__ void bnsplit_k(const float* __restrict__ X,
                          const float* __restrict__ cA, const float* __restrict__ cB,
                          __nv_bfloat16* __restrict__ h, __nv_bfloat16* __restrict__ l,
                          long n4, int N)
{
    long i = blockIdx.x * (long)blockDim.x + threadIdx.x;
    if (i >= n4) return;
    long e0 = i * 4;
    int c = (int)(e0 & (N - 1));
    float4 v = *reinterpret_cast<const float4*>(X + e0);
    float4 a = *reinterpret_cast<const float4*>(cA + c);
    float4 b = *reinterpret_cast<const float4*>(cB + c);
    v.x = fmaf(v.x, a.x, b.x); v.x = v.x >= 0.f ? v.x : ALPHA * v.x;
    v.y = fmaf(v.y, a.y, b.y); v.y = v.y >= 0.f ? v.y : ALPHA * v.y;
    v.z = fmaf(v.z, a.z, b.z); v.z = v.z >= 0.f ? v.z : ALPHA * v.z;
    v.w = fmaf(v.w, a.w, b.w); v.w = v.w >= 0.f ? v.w : ALPHA * v.w;
    uint32_t h01, l01, h23, l23;
    split2(v.x, v.y, h01, l01);
    split2(v.z, v.w, h23, l23);
    *reinterpret_cast<uint2*>(h + e0) = make_uint2(h01, h23);
    *reinterpret_cast<uint2*>(l + e0) = make_uint2(l01, l23);
}

__global__ void divsplit_k(const float* __restrict__ P, const float* __restrict__ cnt,
                           __nv_bfloat16* __restrict__ h, __nv_bfloat16* __restrict__ l,
                           long n4, float ocap)
{
    long i = blockIdx.x * (long)blockDim.x + threadIdx.x;
    if (i >= n4) return;
    long e0 = i * 4;
    float c = cnt[e0 >> 9];
    c = fminf(fmaxf(c, 1.f), ocap);
    float r = 1.f / c;
    float4 v = *reinterpret_cast<const float4*>(P + e0);
    v.x *= r; v.y *= r; v.z *= r; v.w *= r;
    uint32_t h01, l01, h23, l23;
    split2(v.x, v.y, h01, l01);
    split2(v.z, v.w, h23, l23);
    *reinterpret_cast<uint2*>(h + e0) = make_uint2(h01, h23);
    *reinterpret_cast<uint2*>(l + e0) = make_uint2(l01, l23);
}

// ======================= pipelined mma.sync GEMM ===============================
// CTA 128x128, 16 warps (4x4), warp tile 32x32, 4 warps/SMSP.
// K-chunk 32, 4-stage cp.async, one __syncthreads per chunk.
// bf16x3: hi*hi + hi*lo + lo*hi, fp32 accumulate. Fused column stats.
#define ROWB   80
#define STAGE  (4 * 128 * ROWB)
#define NSTG   4
#define GEMM_SMEM (NSTG * STAGE)        // 163840 B

template<bool GATHER>
__global__ void __launch_bounds__(512, 1)
mma_gemm_k(const __nv_bfloat16* __restrict__ Ah, const __nv_bfloat16* __restrict__ Al,
           const __nv_bfloat16* __restrict__ objh, const __nv_bfloat16* __restrict__ objl,
           const __nv_bfloat16* __restrict__ predh, const __nv_bfloat16* __restrict__ predl,
           const int* __restrict__ es, const int* __restrict__ eo,
           const __nv_bfloat16* __restrict__ Bth, const __nv_bfloat16* __restrict__ Btl,
           const float* __restrict__ bias,
           float* __restrict__ C, float* __restrict__ gsum, float* __restrict__ gsq,
           int M, int N, int K)
{
    extern __shared__ __align__(16) char smem[];
    const uint32_t sbase = smem_to_u32(smem);

    const int tid  = threadIdx.x;
    const int lane = tid & 31;
    const int wid  = tid >> 5;
    const int wm   = wid >> 2;       // 0..3 (32-row slabs)
    const int wn   = wid & 3;        // 0..3 (32-col slabs)
    const int m0   = blockIdx.y * 128, n0 = blockIdx.x * 128;
    const int q8   = lane >> 3;
    const int r8   = lane & 7;

    float acc[2][4][4];
#pragma unroll
    for (int i = 0; i < 2; i++)
#pragma unroll
        for (int j = 0; j < 4; j++)
#pragma unroll
            for (int q = 0; q < 4; q++) acc[i][j][q] = 0.f;

    const int nk = K >> 5;

    // ---- async load of one K32-chunk into a stage (512 threads) ----
    auto load_chunk = [&](int k0, int stage) {
        const uint32_t aAh = sbase + stage * STAGE;
        const uint32_t aAl = aAh + 128 * ROWB;
        const uint32_t aBh = aAl + 128 * ROWB;
        const uint32_t aBl = aBh + 128 * ROWB;
        // A: 2 arrays x 128 rows x 4 chunks of 16B = 1024 cp16 / 512 thr = 2
#pragma unroll
        for (int i = 0; i < 2; i++) {
            int idx = tid + (i << 9);
            int arr = idx >> 9;
            int r   = (idx >> 2) & 127;
            int c   = idx & 3;
            int gm  = m0 + r;
            int gmc = gm < M ? gm : M - 1;
            const __nv_bfloat16* src;
            if (GATHER) {
                long sr; const __nv_bfloat16 *sh, *sl;
                if (k0 < 128)      { sr = (long)es[gmc]; sh = objh;  sl = objl;  }
                else if (k0 < 256) { sr = gmc;           sh = predh; sl = predl; }
                else               { sr = (long)eo[gmc]; sh = objh;  sl = objl;  }
                src = (arr ? sl : sh) + sr * 128 + (k0 & 127) + c * 8;
            } else {
                src = (arr ? Al : Ah) + (long)gmc * K + k0 + c * 8;
            }
            cp16((arr ? aAl : aAh) + r * ROWB + c * 16, src);
        }
        // B: 2 arrays x 128 rows x 4 chunks of 16B
#pragma unroll
        for (int i = 0; i < 2; i++) {
            int idx = tid + (i << 9);
            int arr = idx >> 9;
            int r   = (idx >> 2) & 127;
            int c   = idx & 3;
            const __nv_bfloat16* src = (arr ? Btl : Bth) + (long)(n0 + r) * K + k0 + c * 8;
            cp16((arr ? aBl : aBh) + r * ROWB + c * 16, src);
        }
        CP_COMMIT();
    };

    // ---- compute one K32-chunk (2 k16 steps); B fragments hoisted ----
    auto compute = [&](int stage) {
        const uint32_t aAh = sbase + stage * STAGE;
        const uint32_t aAl = aAh + 128 * ROWB;
        const uint32_t aBh = aAl + 128 * ROWB;
        const uint32_t aBl = aBh + 128 * ROWB;
        uint32_t bh[2][4][2], bl[2][4][2];
#pragma unroll
        for (int s = 0; s < 2; s++)
#pragma unroll
            for (int j = 0; j < 2; j++) {
                int nrow = wn * 32 + j * 16 + (q8 >> 1) * 8 + r8;
                int kb   = s * 32 + (q8 & 1) * 16;
                uint32_t addr = (uint32_t)(nrow * ROWB + kb);
                uint32_t r[4];
                ldsm_x4(aBh + addr, r);
                bh[s][2 * j][0] = r[0]; bh[s][2 * j][1] = r[1];
                bh[s][2 * j + 1][0] = r[2]; bh[s][2 * j + 1][1] = r[3];
                ldsm_x4(aBl + addr, r);
                bl[s][2 * j][0] = r[0]; bl[s][2 * j][1] = r[1];
                bl[s][2 * j + 1][0] = r[2]; bl[s][2 * j + 1][1] = r[3];
            }
#pragma unroll
        for (int s = 0; s < 2; s++) {
            uint32_t ah[2][4], al[2][4];
#pragma unroll
            for (int mt = 0; mt < 2; mt++) {
                int mrow = wm * 32 + mt * 16 + (q8 & 1) * 8 + r8;
                int kb   = s * 32 + (q8 >> 1) * 16;
                uint32_t addr = (uint32_t)(mrow * ROWB + kb);
                ldsm_x4(aAh + addr, ah[mt]);
                ldsm_x4(aAl + addr, al[mt]);
            }
#pragma unroll
            for (int mt = 0; mt < 2; mt++)
#pragma unroll
                for (int nt = 0; nt < 4; nt++) {
                    mma_bf16(acc[mt][nt], ah[mt], bh[s][nt]);
                    mma_bf16(acc[mt][nt], ah[mt], bl[s][nt]);
                    mma_bf16(acc[mt][nt], al[mt], bh[s][nt]);
                }
        }
    };

    // ---- 4-stage pipeline, one sync per chunk ----
    load_chunk(0, 0);
    load_chunk(32, 1);
    load_chunk(64, 2);
    for (int it = 0; it < nk; it++) {
        CP_WAIT(2);
        __syncthreads();
        compute(it & (NSTG - 1));
        if (it + 3 < nk) load_chunk((it + 3) << 5, (it + 3) & (NSTG - 1));
    }

    // ---- epilogue: +bias, store, fused column stats ----
#pragma unroll
    for (int nt = 0; nt < 4; nt++) {
        int col = n0 + wn * 32 + nt * 8 + (lane & 3) * 2;
        float2 bv = *reinterpret_cast<const float2*>(bias + col);
        float s0 = 0.f, s1 = 0.f, q0 = 0.f, q1 = 0.f;
#pragma unroll
        for (int mt = 0; mt < 2; mt++) {
            int row0 = m0 + wm * 32 + mt * 16 + (lane >> 2);
            int row1 = row0 + 8;
            float v0 = acc[mt][nt][0] + bv.x;
            float v1 = acc[mt][nt][1] + bv.y;
            float v2 = acc[mt][nt][2] + bv.x;
            float v3 = acc[mt][nt][3] + bv.y;
            if (row0 < M) {
                *reinterpret_cast<float2*>(C + (long)row0 * N + col) = make_float2(v0, v1);
                s0 += v0; q0 += v0 * v0; s1 += v1; q1 += v1 * v1;
            }
            if (row1 < M) {
                *reinterpret_cast<float2*>(C + (long)row1 * N + col) = make_float2(v2, v3);
                s0 += v2; q0 += v2 * v2; s1 += v3; q1 += v3 * v3;
            }
        }
#pragma unroll
        for (int off = 4; off < 32; off <<= 1) {
            s0 += __shfl_down_sync(0xffffffffu, s0, off);
            s1 += __shfl_down_sync(0xffffffffu, s1, off);
            q0 += __shfl_down_sync(0xffffffffu, q0, off);
            q1 += __shfl_down_sync(0xffffffffu, q1, off);
        }
        if (lane < 4) {
            atomicAdd(&gsum[col],     s0);
            atomicAdd(&gsum[col + 1], s1);
            atomicAdd(&gsq[col],      q0);
            atomicAdd(&gsq[col + 1],  q1);
        }
    }
}

// ======================= stats finalize / BN out / scatter ====================
__global__ void finalize_k(const float* __restrict__ sum, const float* __restrict__ sq,
                           const float* __restrict__ gamma, const float* __restrict__ beta,
                           float invM, int N,
                           float* __restrict__ cA, float* __restrict__ cB)
{
    int n = blockIdx.x * blockDim.x + threadIdx.x;
    if (n >= N) return;
    float mean = sum[n] * invM;
    float var  = sq[n] * invM - mean * mean;
    float inv  = rsqrtf(var + EPS);
    float a    = inv * gamma[n];
    cA[n] = a;
    cB[n] = beta[n] - mean * a;
}

__global__ void bn_out_k(const float* __restrict__ X, const float* __restrict__ cA,
                         const float* __restrict__ cB, float* __restrict__ out,
                         long total, int N)
{
    long i = blockIdx.x * (long)blockDim.x + threadIdx.x;
    if (i >= total) return;
    int n = (int)(i % N);
    float v = X[i] * cA[n] + cB[n];
    out[i] = (v >= 0.f) ? v : ALPHA * v;
}

__device__ __forceinline__ float4 bn4(float4 v, float4 a, float4 b) {
    v.x = fmaf(v.x, a.x, b.x); v.x = v.x >= 0.f ? v.x : ALPHA * v.x;
    v.y = fmaf(v.y, a.y, b.y); v.y = v.y >= 0.f ? v.y : ALPHA * v.y;
    v.z = fmaf(v.z, a.z, b.z); v.z = v.z >= 0.f ? v.z : ALPHA * v.z;
    v.w = fmaf(v.w, a.w, b.w); v.w = v.w >= 0.f ? v.w : ALPHA * v.w;
    return v;
}

// one block (128 thr) per triple row; vectorized red.add.v4.f32 into pooled
__global__ void scatter_k(const float* __restrict__ A2,
                          const float* __restrict__ cA, const float* __restrict__ cB,
                          const int* __restrict__ es, const int* __restrict__ eo,
                          float* __restrict__ pooled, float* __restrict__ out_p, int T)
{
    int t = blockIdx.x;
    if (t >= T) return;
    int s = es[t];
    int o = eo[t];
    int tid = threadIdx.x;                       // 0..127
    const float4* row = reinterpret_cast<const float4*>(A2 + (long)t * 1152);
    const float4* a4  = reinterpret_cast<const float4*>(cA);
    const float4* b4  = reinterpret_cast<const float4*>(cB);

    // cols [0,512): pooled[s]
    {
        float4 v = bn4(row[tid], a4[tid], b4[tid]);
        red4(&pooled[(long)s * 512 + tid * 4], v);
    }
    // cols [512,640): out_p row t
    if (tid < 32) {
        int c4 = 128 + tid;
        float4 v = bn4(row[c4], a4[c4], b4[c4]);
        *reinterpret_cast<float4*>(out_p + (long)t * 128 + tid * 4) = v;
    }
    // cols [640,1152): pooled[o]
    {
        int c4 = 160 + tid;
        float4 v = bn4(row[c4], a4[c4], b4[c4]);
        red4(&pooled[(long)o * 512 + tid * 4], v);
    }
}

// ======================= launch ================================================
extern "C" void kernel_launch(void* const* d_in, const int* in_sizes, int n_in,
                              void* d_out, int out_size)
{
    const float* obj   = (const float*)d_in[0];
    const float* pred  = (const float*)d_in[1];
    const int*   e32   = (const int*)d_in[2];
    const float* W1a = (const float*)d_in[3];
    const float* b1a = (const float*)d_in[4];
    const float* g1a = (const float*)d_in[5];
    const float* be1a= (const float*)d_in[6];
    const float* W1b = (const float*)d_in[7];
    const float* b1b = (const float*)d_in[8];
    const float* g1b = (const float*)d_in[9];
    const float* be1b= (const float*)d_in[10];
    const float* W2a = (const float*)d_in[11];
    const float* b2a = (const float*)d_in[12];
    const float* g2a = (const float*)d_in[13];
    const float* be2a= (const float*)d_in[14];
    const float* W2b = (const float*)d_in[15];
    const float* b2b = (const float*)d_in[16];
    const float* g2b = (const float*)d_in[17];
    const float* be2b= (const float*)d_in[18];

    const int O = in_sizes[0] / 128;
    const int T = in_sizes[1] / 128;

    float* out     = (float*)d_out;
    float* out_obj = out;
    float* out_p   = out + (size_t)O * 128;

    float *A1, *A2, *POOL, *A4, *CNT, *SUM, *SQ, *CA, *CB;
    int *ES, *EO, *FLAG;
    __nv_bfloat16 *WTH, *WTL, *OBJH, *OBJL, *PRH, *PRL, *XH, *XL;
    cudaGetSymbolAddress((void**)&A1,   g_A1);
    cudaGetSymbolAddress((void**)&A2,   g_A2);
    cudaGetSymbolAddress((void**)&POOL, g_pooled);
    cudaGetSymbolAddress((void**)&A4,   g_A4);
    cudaGetSymbolAddress((void**)&CNT,  g_counts);
    cudaGetSymbolAddress((void**)&SUM,  g_sum);
    cudaGetSymbolAddress((void**)&SQ,   g_sq);
    cudaGetSymbolAddress((void**)&CA,   g_cA);
    cudaGetSymbolAddress((void**)&CB,   g_cB);
    cudaGetSymbolAddress((void**)&ES,   g_es);
    cudaGetSymbolAddress((void**)&EO,   g_eo);
    cudaGetSymbolAddress((void**)&FLAG, g_flag32);
    cudaGetSymbolAddress((void**)&WTH,  g_wt_hi);
    cudaGetSymbolAddress((void**)&WTL,  g_wt_lo);
    cudaGetSymbolAddress((void**)&OBJH, g_objh);
    cudaGetSymbolAddress((void**)&OBJL, g_objl);
    cudaGetSymbolAddress((void**)&PRH,  g_predh);
    cudaGetSymbolAddress((void**)&PRL,  g_predl);
    cudaGetSymbolAddress((void**)&XH,   g_xh);
    cudaGetSymbolAddress((void**)&XL,   g_xl);

    cudaFuncSetAttribute(mma_gemm_k<true>,
                         cudaFuncAttributeMaxDynamicSharedMemorySize, GEMM_SMEM);
    cudaFuncSetAttribute(mma_gemm_k<false>,
                         cudaFuncAttributeMaxDynamicSharedMemorySize, GEMM_SMEM);

    const int OFF1 = 0, OFF2 = 512, OFF3 = 1664, OFF4 = 2176;
    const int W1A_OFF = 0, W1B_OFF = 196608, W2A_OFF = 786432, W2B_OFF = 1048576;

    // 0) zero accumulators; probe + normalize edges (+counts)
    zero_k<<<2048, 256>>>(POOL, CNT, SUM, SQ, FLAG, (long)O * 512, O);
    probe_k<<<(T + 255) / 256, 256>>>(e32, FLAG, T);
    convert_k<<<(T + 255) / 256, 256>>>(e32, FLAG, ES, EO, CNT, T);

    // 0b) split weights [N,K] and inputs obj/pred
    wsplit_k<<<(384 * 512  + 255) / 256, 256>>>(W1a, WTH + W1A_OFF, WTL + W1A_OFF, 384, 512);
    wsplit_k<<<(512 * 1152 + 255) / 256, 256>>>(W1b, WTH + W1B_OFF, WTL + W1B_OFF, 512, 1152);
    wsplit_k<<<(512 * 512  + 255) / 256, 256>>>(W2a, WTH + W2A_OFF, WTL + W2A_OFF, 512, 512);
    wsplit_k<<<(512 * 128  + 255) / 256, 256>>>(W2b, WTH + W2B_OFF, WTL + W2B_OFF, 512, 128);
    asplit_k<<<(unsigned)(((long)O * 32 + 255) / 256), 256>>>(obj,  OBJH, OBJL, (long)O * 32);
    asplit_k<<<(unsigned)(((long)T * 32 + 255) / 256), 256>>>(pred, PRH,  PRL,  (long)T * 32);

    // 1) GEMM1 (gathered): A1 = cur_t @ W1a + b1a  [T,512]  + L1 stats
    mma_gemm_k<true><<<dim3(4, (T + 127) / 128), 512, GEMM_SMEM>>>(
        nullptr, nullptr, OBJH, OBJL, PRH, PRL, ES, EO,
        WTH + W1A_OFF, WTL + W1A_OFF, b1a, A1, SUM + OFF1, SQ + OFF1, T, 512, 384);
    finalize_k<<<2, 256>>>(SUM + OFF1, SQ + OFF1, g1a, be1a, 1.f / T, 512, CA + OFF1, CB + OFF1);

    // 2) BN1-apply + lrelu + split -> XH/XL
    bnsplit_k<<<(unsigned)(((long)T * 128 + 255) / 256), 256>>>(
        A1, CA + OFF1, CB + OFF1, XH, XL, (long)T * 128, 512);

    // 3) GEMM2: A2 = X @ W1b + b1b  [T,1152]  + L2 stats
    mma_gemm_k<false><<<dim3(9, (T + 127) / 128), 512, GEMM_SMEM>>>(
        XH, XL, nullptr, nullptr, nullptr, nullptr, nullptr, nullptr,
        WTH + W1B_OFF, WTL + W1B_OFF, b1b, A2, SUM + OFF2, SQ + OFF2, T, 1152, 512);
    finalize_k<<<5, 256>>>(SUM + OFF2, SQ + OFF2, g1b, be1b, 1.f / T, 1152, CA + OFF2, CB + OFF2);

    // 4) scatter (BN2+lrelu fused, v4 reductions) -> POOL raw sums, out_p
    scatter_k<<<T, 128>>>(A2, CA + OFF2, CB + OFF2, ES, EO, POOL, out_p, T);

    // 5) divide + split pooled -> XH/XL
    divsplit_k<<<(unsigned)(((long)O * 128 + 255) / 256), 256>>>(
        POOL, CNT, XH, XL, (long)O * 128, (float)O);

    // 6) GEMM3: A3(=A1) = X @ W2a + b2a  [O,512]  + L3 stats
    mma_gemm_k<false><<<dim3(4, (O + 127) / 128), 512, GEMM_SMEM>>>(
        XH, XL, nullptr, nullptr, nullptr, nullptr, nullptr, nullptr,
        WTH + W2A_OFF, WTL + W2A_OFF, b2a, A1, SUM + OFF3, SQ + OFF3, O, 512, 512);
    finalize_k<<<2, 256>>>(SUM + OFF3, SQ + OFF3, g2a, be2a, 1.f / O, 512, CA + OFF3, CB + OFF3);

    // 7) BN3-apply + lrelu + split -> XH/XL
    bnsplit_k<<<(unsigned)(((long)O * 128 + 255) / 256), 256>>>(
        A1, CA + OFF3, CB + OFF3, XH, XL, (long)O * 128, 512);

    // 8) GEMM4: A4 = X @ W2b + b2b  [O,128]  + L4 stats
    mma_gemm_k<false><<<dim3(1, (O + 127) / 128), 512, GEMM_SMEM>>>(
        XH, XL, nullptr, nullptr, nullptr, nullptr, nullptr, nullptr,
        WTH + W2B_OFF, WTL + W2B_OFF, b2b, A4, SUM + OFF4, SQ + OFF4, O, 128, 512);
    finalize_k<<<1, 256>>>(SUM + OFF4, SQ + OFF4, g2b, be2b, 1.f / O, 128, CA + OFF4, CB + OFF4);

    // 9) BN4 apply -> out_obj
    bn_out_k<<<(unsigned)(((long)O * 128 + 255) / 256), 256>>>(
        A4, CA + OFF4, CB + OFF4, out_obj, (long)O * 128, 128);
}

// round 9
// speedup vs baseline: 2.5619x; 1.0081x over previous
#include <cuda_runtime.h>
#include <cuda_bf16.h>
#include <cstdint>

#define EPS    1e-5f
#define ALPHA  0.2f
#define MAX_O  50000
#define MAX_T  200000

// ---------------- scratch (static device globals; no allocation) -------------
__device__ float g_A1[(size_t)MAX_T * 512];
__device__ float g_A2[(size_t)MAX_T * 1152];
__device__ float g_pooled[(size_t)MAX_O * 512];
__device__ float g_A4[(size_t)MAX_O * 128];
__device__ float g_counts[MAX_O];
__device__ int   g_es[MAX_T];
__device__ int   g_eo[MAX_T];
__device__ int   g_flag32;
__device__ __nv_bfloat16 g_objh[(size_t)MAX_O * 128];
__device__ __nv_bfloat16 g_objl[(size_t)MAX_O * 128];
__device__ __nv_bfloat16 g_predh[(size_t)MAX_T * 128];
__device__ __nv_bfloat16 g_predl[(size_t)MAX_T * 128];
__device__ __nv_bfloat16 g_xh[(size_t)MAX_T * 512];
__device__ __nv_bfloat16 g_xl[(size_t)MAX_T * 512];
#define WT_TOTAL 1114112
__device__ __nv_bfloat16 g_wt_hi[WT_TOTAL];
__device__ __nv_bfloat16 g_wt_lo[WT_TOTAL];
__device__ float g_sum[2304];
__device__ float g_sq[2304];
__device__ float g_cA[2304];
__device__ float g_cB[2304];

// ======================= PTX wrappers =========================================
__device__ __forceinline__ uint32_t smem_to_u32(const void* p) {
    uint32_t a;
    asm("{ .reg .u64 t; cvta.to.shared.u64 t, %1; cvt.u32.u64 %0, t; }" : "=r"(a) : "l"(p));
    return a;
}
__device__ __forceinline__ void ldsm_x4(uint32_t addr, uint32_t* r) {
    asm volatile("ldmatrix.sync.aligned.m8n8.x4.shared.b16 {%0,%1,%2,%3}, [%4];"
        : "=r"(r[0]), "=r"(r[1]), "=r"(r[2]), "=r"(r[3]) : "r"(addr));
}
__device__ __forceinline__ void mma_bf16(float* c, const uint32_t* a, const uint32_t* b) {
    asm volatile("mma.sync.aligned.m16n8k16.row.col.f32.bf16.bf16.f32 "
        "{%0,%1,%2,%3},{%4,%5,%6,%7},{%8,%9},{%0,%1,%2,%3};"
        : "+f"(c[0]), "+f"(c[1]), "+f"(c[2]), "+f"(c[3])
        : "r"(a[0]), "r"(a[1]), "r"(a[2]), "r"(a[3]), "r"(b[0]), "r"(b[1]));
}
__device__ __forceinline__ void cp16(uint32_t dst, const void* src) {
    asm volatile("cp.async.cg.shared.global [%0], [%1], 16;" :: "r"(dst), "l"(src));
}
#define CP_COMMIT() asm volatile("cp.async.commit_group;" ::: "memory")
#define CP_WAIT(n)  asm volatile("cp.async.wait_group %0;" :: "n"(n) : "memory")

__device__ __forceinline__ void red4(float* addr, float4 v) {
    asm volatile("red.global.add.v4.f32 [%0], {%1,%2,%3,%4};"
        :: "l"(addr), "f"(v.x), "f"(v.y), "f"(v.z), "f"(v.w) : "memory");
}

__device__ __forceinline__ void split2(float x, float y, uint32_t& h, uint32_t& l) {
    __nv_bfloat16 hx = __float2bfloat16(x);
    __nv_bfloat16 hy = __float2bfloat16(y);
    __nv_bfloat162 hp = __halves2bfloat162(hx, hy);
    __nv_bfloat162 lp = __halves2bfloat162(
        __float2bfloat16(x - __bfloat162float(hx)),
        __float2bfloat16(y - __bfloat162float(hy)));
    h = *reinterpret_cast<uint32_t*>(&hp);
    l = *reinterpret_cast<uint32_t*>(&lp);
}

// ======================= small utility kernels ================================
__global__ void zero_k(float* pooled, float* counts, float* sum, float* sq,
                       int* flag32, long n_pooled, int O)
{
    if (blockIdx.x == 0 && threadIdx.x == 0) *flag32 = 0;
    long total = n_pooled + O + 2 * 2304;
    for (long i = blockIdx.x * (long)blockDim.x + threadIdx.x; i < total;
         i += (long)gridDim.x * blockDim.x) {
        if (i < n_pooled)            pooled[i] = 0.f;
        else if (i < n_pooled + O)   counts[i - n_pooled] = 0.f;
        else {
            long j = i - n_pooled - O;
            if (j < 2304) sum[j] = 0.f; else sq[j - 2304] = 0.f;
        }
    }
}

__global__ void probe_k(const int* __restrict__ e32, int* flag32, int T)
{
    int t = blockIdx.x * blockDim.x + threadIdx.x;
    if (t >= T) return;
    if (e32[2 * t + 1] != 0) atomicOr(flag32, 1);
}

__global__ void convert_k(const int* __restrict__ e32, const int* __restrict__ flag32,
                          int* __restrict__ es, int* __restrict__ eo,
                          float* __restrict__ counts, int T)
{
    int t = blockIdx.x * blockDim.x + threadIdx.x;
    if (t >= T) return;
    int s, o;
    if (*flag32) { s = e32[2 * t]; o = e32[2 * t + 1]; }
    else         { s = e32[4 * t]; o = e32[4 * t + 2]; }
    es[t] = s;
    eo[t] = o;
    atomicAdd(&counts[s], 1.f);
    atomicAdd(&counts[o], 1.f);
}

__global__ void wsplit_k(const float* __restrict__ W,
                         __nv_bfloat16* __restrict__ hi, __nv_bfloat16* __restrict__ lo,
                         int K, int N)
{
    int i = blockIdx.x * blockDim.x + threadIdx.x;
    if (i >= K * N) return;
    int k = i / N, n = i % N;
    float v = W[i];
    __nv_bfloat16 h = __float2bfloat16(v);
    hi[(long)n * K + k] = h;
    lo[(long)n * K + k] = __float2bfloat16(v - __bfloat162float(h));
}

__global__ void asplit_k(const float* __restrict__ X,
                         __nv_bfloat16* __restrict__ h, __nv_bfloat16* __restrict__ l,
                         long n4)
{
    long i = blockIdx.x * (long)blockDim.x + threadIdx.x;
    if (i >= n4) return;
    float4 v = *reinterpret_cast<const float4*>(X + i * 4);
    uint32_t h01, l01, h23, l23;
    split2(v.x, v.y, h01, l01);
    split2(v.z, v.w, h23, l23);
    *reinterpret_cast<uint2*>(h + i * 4) = make_uint2(h01, h23);
    *reinterpret_cast<uint2*>(l + i * 4) = make_uint2(l01, l23);
}

__global__ void bnsplit_k(const float* __restrict__ X,
                          const float* __restrict__ cA, const float* __restrict__ cB,
                          __nv_bfloat16* __restrict__ h, __nv_bfloat16* __restrict__ l,
                          long n4, int N)
{
    long i = blockIdx.x * (long)blockDim.x + threadIdx.x;
    if (i >= n4) return;
    long e0 = i * 4;
    int c = (int)(e0 & (N - 1));
    float4 v = *reinterpret_cast<const float4*>(X + e0);
    float4 a = *reinterpret_cast<const float4*>(cA + c);
    float4 b = *reinterpret_cast<const float4*>(cB + c);
    v.x = fmaf(v.x, a.x, b.x); v.x = v.x >= 0.f ? v.x : ALPHA * v.x;
    v.y = fmaf(v.y, a.y, b.y); v.y = v.y >= 0.f ? v.y : ALPHA * v.y;
    v.z = fmaf(v.z, a.z, b.z); v.z = v.z >= 0.f ? v.z : ALPHA * v.z;
    v.w = fmaf(v.w, a.w, b.w); v.w = v.w >= 0.f ? v.w : ALPHA * v.w;
    uint32_t h01, l01, h23, l23;
    split2(v.x, v.y, h01, l01);
    split2(v.z, v.w, h23, l23);
    *reinterpret_cast<uint2*>(h + e0) = make_uint2(h01, h23);
    *reinterpret_cast<uint2*>(l + e0) = make_uint2(l01, l23);
}

__global__ void divsplit_k(const float* __restrict__ P, const float* __restrict__ cnt,
                           __nv_bfloat16* __restrict__ h, __nv_bfloat16* __restrict__ l,
                           long n4, float ocap)
{
    long i = blockIdx.x * (long)blockDim.x + threadIdx.x;
    if (i >= n4) return;
    long e0 = i * 4;
    float c = cnt[e0 >> 9];
    c = fminf(fmaxf(c, 1.f), ocap);
    float r = 1.f / c;
    float4 v = *reinterpret_cast<const float4*>(P + e0);
    v.x *= r; v.y *= r; v.z *= r; v.w *= r;
    uint32_t h01, l01, h23, l23;
    split2(v.x, v.y, h01, l01);
    split2(v.z, v.w, h23, l23);
    *reinterpret_cast<uint2*>(h + e0) = make_uint2(h01, h23);
    *reinterpret_cast<uint2*>(l + e0) = make_uint2(l01, l23);
}

// ======================= pipelined mma.sync GEMM ===============================
// CTA 128x128, 16 warps (4x4), warp tile 32x32.
// K-chunk 64, 3-stage cp.async (ROWB=144: conflict-free cp.async stores + ldsm).
// bf16x3 as 3 independent passes per k16-step (8 accs of ILP between same-acc reuse).
#define ROWB   144
#define STAGE  (4 * 128 * ROWB)          // 73728 B: Ah, Al, Bh, Bl
#define NSTG   3
#define GEMM_SMEM (NSTG * STAGE)         // 221184 B

template<bool GATHER>
__global__ void __launch_bounds__(512, 1)
mma_gemm_k(const __nv_bfloat16* __restrict__ Ah, const __nv_bfloat16* __restrict__ Al,
           const __nv_bfloat16* __restrict__ objh, const __nv_bfloat16* __restrict__ objl,
           const __nv_bfloat16* __restrict__ predh, const __nv_bfloat16* __restrict__ predl,
           const int* __restrict__ es, const int* __restrict__ eo,
           const __nv_bfloat16* __restrict__ Bth, const __nv_bfloat16* __restrict__ Btl,
           const float* __restrict__ bias,
           float* __restrict__ C, float* __restrict__ gsum, float* __restrict__ gsq,
           int M, int N, int K)
{
    extern __shared__ __align__(16) char smem[];
    const uint32_t sbase = smem_to_u32(smem);

    const int tid  = threadIdx.x;
    const int lane = tid & 31;
    const int wid  = tid >> 5;
    const int wm   = wid >> 2;
    const int wn   = wid & 3;
    const int m0   = blockIdx.y * 128, n0 = blockIdx.x * 128;
    const int q8   = lane >> 3;
    const int r8   = lane & 7;

    float acc[2][4][4];
#pragma unroll
    for (int i = 0; i < 2; i++)
#pragma unroll
        for (int j = 0; j < 4; j++)
#pragma unroll
            for (int q = 0; q < 4; q++) acc[i][j][q] = 0.f;

    const int nk = K >> 6;    // K chunks of 64

    // ---- async load of one K64-chunk into a stage (512 threads) ----
    auto load_chunk = [&](int k0, int stage) {
        const uint32_t aAh = sbase + stage * STAGE;
        const uint32_t aAl = aAh + 128 * ROWB;
        const uint32_t aBh = aAl + 128 * ROWB;
        const uint32_t aBl = aBh + 128 * ROWB;
        // A: 2 arrays x 128 rows x 8 chunks of 16B = 2048 cp16 / 512 thr = 4
#pragma unroll
        for (int i = 0; i < 4; i++) {
            int idx = tid + (i << 9);
            int arr = idx >> 10;
            int r   = (idx >> 3) & 127;
            int c   = idx & 7;
            int gm  = m0 + r;
            int gmc = gm < M ? gm : M - 1;
            const __nv_bfloat16* src;
            if (GATHER) {
                long sr; const __nv_bfloat16 *sh, *sl;
                if (k0 < 128)      { sr = (long)es[gmc]; sh = objh;  sl = objl;  }
                else if (k0 < 256) { sr = gmc;           sh = predh; sl = predl; }
                else               { sr = (long)eo[gmc]; sh = objh;  sl = objl;  }
                src = (arr ? sl : sh) + sr * 128 + (k0 & 127) + c * 8;
            } else {
                src = (arr ? Al : Ah) + (long)gmc * K + k0 + c * 8;
            }
            cp16((arr ? aAl : aAh) + r * ROWB + c * 16, src);
        }
        // B: 2 arrays x 128 rows x 8 chunks of 16B
#pragma unroll
        for (int i = 0; i < 4; i++) {
            int idx = tid + (i << 9);
            int arr = idx >> 10;
            int r   = (idx >> 3) & 127;
            int c   = idx & 7;
            const __nv_bfloat16* src = (arr ? Btl : Bth) + (long)(n0 + r) * K + k0 + c * 8;
            cp16((arr ? aBl : aBh) + r * ROWB + c * 16, src);
        }
        CP_COMMIT();
    };

    // ---- compute one K64-chunk (4 k16 steps), 3 independent MMA passes ----
    auto compute = [&](int stage) {
        const uint32_t aAh = sbase + stage * STAGE;
        const uint32_t aAl = aAh + 128 * ROWB;
        const uint32_t aBh = aAl + 128 * ROWB;
        const uint32_t aBl = aBh + 128 * ROWB;
#pragma unroll
        for (int s = 0; s < 4; s++) {
            uint32_t bh[4][2], bl[4][2], ah[2][4], al[2][4];
#pragma unroll
            for (int j = 0; j < 2; j++) {
                int nrow = wn * 32 + j * 16 + (q8 >> 1) * 8 + r8;
                int kb   = s * 32 + (q8 & 1) * 16;
                uint32_t addr = (uint32_t)(nrow * ROWB + kb);
                uint32_t r[4];
                ldsm_x4(aBh + addr, r);
                bh[2 * j][0] = r[0]; bh[2 * j][1] = r[1];
                bh[2 * j + 1][0] = r[2]; bh[2 * j + 1][1] = r[3];
                ldsm_x4(aBl + addr, r);
                bl[2 * j][0] = r[0]; bl[2 * j][1] = r[1];
                bl[2 * j + 1][0] = r[2]; bl[2 * j + 1][1] = r[3];
            }
#pragma unroll
            for (int mt = 0; mt < 2; mt++) {
                int mrow = wm * 32 + mt * 16 + (q8 & 1) * 8 + r8;
                int kb   = s * 32 + (q8 >> 1) * 16;
                uint32_t addr = (uint32_t)(mrow * ROWB + kb);
                ldsm_x4(aAh + addr, ah[mt]);
                ldsm_x4(aAl + addr, al[mt]);
            }
            // pass 1: hi*hi (8 independent accs)
#pragma unroll
            for (int mt = 0; mt < 2; mt++)
#pragma unroll
                for (int nt = 0; nt < 4; nt++)
                    mma_bf16(acc[mt][nt], ah[mt], bh[nt]);
            // pass 2: hi*lo
#pragma unroll
            for (int mt = 0; mt < 2; mt++)
#pragma unroll
                for (int nt = 0; nt < 4; nt++)
                    mma_bf16(acc[mt][nt], ah[mt], bl[nt]);
            // pass 3: lo*hi
#pragma unroll
            for (int mt = 0; mt < 2; mt++)
#pragma unroll
                for (int nt = 0; nt < 4; nt++)
                    mma_bf16(acc[mt][nt], al[mt], bh[nt]);
        }
    };

    // ---- 3-stage pipeline, one sync per chunk ----
    load_chunk(0, 0);
    if (nk > 1) load_chunk(64, 1);
    for (int it = 0; it < nk; it++) {
        if (it == nk - 1) { CP_WAIT(0); } else { CP_WAIT(1); }
        __syncthreads();
        compute(it % NSTG);
        if (it + 2 < nk) load_chunk((it + 2) << 6, (it + 2) % NSTG);
    }

    // ---- epilogue: +bias, store, fused column stats ----
#pragma unroll
    for (int nt = 0; nt < 4; nt++) {
        int col = n0 + wn * 32 + nt * 8 + (lane & 3) * 2;
        float2 bv = *reinterpret_cast<const float2*>(bias + col);
        float s0 = 0.f, s1 = 0.f, q0 = 0.f, q1 = 0.f;
#pragma unroll
        for (int mt = 0; mt < 2; mt++) {
            int row0 = m0 + wm * 32 + mt * 16 + (lane >> 2);
            int row1 = row0 + 8;
            float v0 = acc[mt][nt][0] + bv.x;
            float v1 = acc[mt][nt][1] + bv.y;
            float v2 = acc[mt][nt][2] + bv.x;
            float v3 = acc[mt][nt][3] + bv.y;
            if (row0 < M) {
                *reinterpret_cast<float2*>(C + (long)row0 * N + col) = make_float2(v0, v1);
                s0 += v0; q0 += v0 * v0; s1 += v1; q1 += v1 * v1;
            }
            if (row1 < M) {
                *reinterpret_cast<float2*>(C + (long)row1 * N + col) = make_float2(v2, v3);
                s0 += v2; q0 += v2 * v2; s1 += v3; q1 += v3 * v3;
            }
        }
#pragma unroll
        for (int off = 4; off < 32; off <<= 1) {
            s0 += __shfl_down_sync(0xffffffffu, s0, off);
            s1 += __shfl_down_sync(0xffffffffu, s1, off);
            q0 += __shfl_down_sync(0xffffffffu, q0, off);
            q1 += __shfl_down_sync(0xffffffffu, q1, off);
        }
        if (lane < 4) {
            atomicAdd(&gsum[col],     s0);
            atomicAdd(&gsum[col + 1], s1);
            atomicAdd(&gsq[col],      q0);
            atomicAdd(&gsq[col + 1],  q1);
        }
    }
}

// ======================= stats finalize / BN out / scatter ====================
__global__ void finalize_k(const float* __restrict__ sum, const float* __restrict__ sq,
                           const float* __restrict__ gamma, const float* __restrict__ beta,
                           float invM, int N,
                           float* __restrict__ cA, float* __restrict__ cB)
{
    int n = blockIdx.x * blockDim.x + threadIdx.x;
    if (n >= N) return;
    float mean = sum[n] * invM;
    float var  = sq[n] * invM - mean * mean;
    float inv  = rsqrtf(var + EPS);
    float a    = inv * gamma[n];
    cA[n] = a;
    cB[n] = beta[n] - mean * a;
}

__global__ void bn_out_k(const float* __restrict__ X, const float* __restrict__ cA,
                         const float* __restrict__ cB, float* __restrict__ out,
                         long total, int N)
{
    long i = blockIdx.x * (long)blockDim.x + threadIdx.x;
    if (i >= total) return;
    int n = (int)(i % N);
    float v = X[i] * cA[n] + cB[n];
    out[i] = (v >= 0.f) ? v : ALPHA * v;
}

__device__ __forceinline__ float4 bn4(float4 v, float4 a, float4 b) {
    v.x = fmaf(v.x, a.x, b.x); v.x = v.x >= 0.f ? v.x : ALPHA * v.x;
    v.y = fmaf(v.y, a.y, b.y); v.y = v.y >= 0.f ? v.y : ALPHA * v.y;
    v.z = fmaf(v.z, a.z, b.z); v.z = v.z >= 0.f ? v.z : ALPHA * v.z;
    v.w = fmaf(v.w, a.w, b.w); v.w = v.w >= 0.f ? v.w : ALPHA * v.w;
    return v;
}

__global__ void scatter_k(const float* __restrict__ A2,
                          const float* __restrict__ cA, const float* __restrict__ cB,
                          const int* __restrict__ es, const int* __restrict__ eo,
                          float* __restrict__ pooled, float* __restrict__ out_p, int T)
{
    int t = blockIdx.x;
    if (t >= T) return;
    int s = es[t];
    int o = eo[t];
    int tid = threadIdx.x;
    const float4* row = reinterpret_cast<const float4*>(A2 + (long)t * 1152);
    const float4* a4  = reinterpret_cast<const float4*>(cA);
    const float4* b4  = reinterpret_cast<const float4*>(cB);

    {
        float4 v = bn4(row[tid], a4[tid], b4[tid]);
        red4(&pooled[(long)s * 512 + tid * 4], v);
    }
    if (tid < 32) {
        int c4 = 128 + tid;
        float4 v = bn4(row[c4], a4[c4], b4[c4]);
        *reinterpret_cast<float4*>(out_p + (long)t * 128 + tid * 4) = v;
    }
    {
        int c4 = 160 + tid;
        float4 v = bn4(row[c4], a4[c4], b4[c4]);
        red4(&pooled[(long)o * 512 + tid * 4], v);
    }
}

// ======================= launch ================================================
extern "C" void kernel_launch(void* const* d_in, const int* in_sizes, int n_in,
                              void* d_out, int out_size)
{
    const float* obj   = (const float*)d_in[0];
    const float* pred  = (const float*)d_in[1];
    const int*   e32   = (const int*)d_in[2];
    const float* W1a = (const float*)d_in[3];
    const float* b1a = (const float*)d_in[4];
    const float* g1a = (const float*)d_in[5];
    const float* be1a= (const float*)d_in[6];
    const float* W1b = (const float*)d_in[7];
    const float* b1b = (const float*)d_in[8];
    const float* g1b = (const float*)d_in[9];
    const float* be1b= (const float*)d_in[10];
    const float* W2a = (const float*)d_in[11];
    const float* b2a = (const float*)d_in[12];
    const float* g2a = (const float*)d_in[13];
    const float* be2a= (const float*)d_in[14];
    const float* W2b = (const float*)d_in[15];
    const float* b2b = (const float*)d_in[16];
    const float* g2b = (const float*)d_in[17];
    const float* be2b= (const float*)d_in[18];

    const int O = in_sizes[0] / 128;
    const int T = in_sizes[1] / 128;

    float* out     = (float*)d_out;
    float* out_obj = out;
    float* out_p   = out + (size_t)O * 128;

    float *A1, *A2, *POOL, *A4, *CNT, *SUM, *SQ, *CA, *CB;
    int *ES, *EO, *FLAG;
    __nv_bfloat16 *WTH, *WTL, *OBJH, *OBJL, *PRH, *PRL, *XH, *XL;
    cudaGetSymbolAddress((void**)&A1,   g_A1);
    cudaGetSymbolAddress((void**)&A2,   g_A2);
    cudaGetSymbolAddress((void**)&POOL, g_pooled);
    cudaGetSymbolAddress((void**)&A4,   g_A4);
    cudaGetSymbolAddress((void**)&CNT,  g_counts);
    cudaGetSymbolAddress((void**)&SUM,  g_sum);
    cudaGetSymbolAddress((void**)&SQ,   g_sq);
    cudaGetSymbolAddress((void**)&CA,   g_cA);
    cudaGetSymbolAddress((void**)&CB,   g_cB);
    cudaGetSymbolAddress((void**)&ES,   g_es);
    cudaGetSymbolAddress((void**)&EO,   g_eo);
    cudaGetSymbolAddress((void**)&FLAG, g_flag32);
    cudaGetSymbolAddress((void**)&WTH,  g_wt_hi);
    cudaGetSymbolAddress((void**)&WTL,  g_wt_lo);
    cudaGetSymbolAddress((void**)&OBJH, g_objh);
    cudaGetSymbolAddress((void**)&OBJL, g_objl);
    cudaGetSymbolAddress((void**)&PRH,  g_predh);
    cudaGetSymbolAddress((void**)&PRL,  g_predl);
    cudaGetSymbolAddress((void**)&XH,   g_xh);
    cudaGetSymbolAddress((void**)&XL,   g_xl);

    cudaFuncSetAttribute(mma_gemm_k<true>,
                         cudaFuncAttributeMaxDynamicSharedMemorySize, GEMM_SMEM);
    cudaFuncSetAttribute(mma_gemm_k<false>,
                         cudaFuncAttributeMaxDynamicSharedMemorySize, GEMM_SMEM);

    const int OFF1 = 0, OFF2 = 512, OFF3 = 1664, OFF4 = 2176;
    const int W1A_OFF = 0, W1B_OFF = 196608, W2A_OFF = 786432, W2B_OFF = 1048576;

    // 0) zero accumulators; probe + normalize edges (+counts)
    zero_k<<<2048, 256>>>(POOL, CNT, SUM, SQ, FLAG, (long)O * 512, O);
    probe_k<<<(T + 255) / 256, 256>>>(e32, FLAG, T);
    convert_k<<<(T + 255) / 256, 256>>>(e32, FLAG, ES, EO, CNT, T);

    // 0b) split weights [N,K] and inputs obj/pred
    wsplit_k<<<(384 * 512  + 255) / 256, 256>>>(W1a, WTH + W1A_OFF, WTL + W1A_OFF, 384, 512);
    wsplit_k<<<(512 * 1152 + 255) / 256, 256>>>(W1b, WTH + W1B_OFF, WTL + W1B_OFF, 512, 1152);
    wsplit_k<<<(512 * 512  + 255) / 256, 256>>>(W2a, WTH + W2A_OFF, WTL + W2A_OFF, 512, 512);
    wsplit_k<<<(512 * 128  + 255) / 256, 256>>>(W2b, WTH + W2B_OFF, WTL + W2B_OFF, 512, 128);
    asplit_k<<<(unsigned)(((long)O * 32 + 255) / 256), 256>>>(obj,  OBJH, OBJL, (long)O * 32);
    asplit_k<<<(unsigned)(((long)T * 32 + 255) / 256), 256>>>(pred, PRH,  PRL,  (long)T * 32);

    // 1) GEMM1 (gathered): A1 = cur_t @ W1a + b1a  [T,512]  + L1 stats
    mma_gemm_k<true><<<dim3(4, (T + 127) / 128), 512, GEMM_SMEM>>>(
        nullptr, nullptr, OBJH, OBJL, PRH, PRL, ES, EO,
        WTH + W1A_OFF, WTL + W1A_OFF, b1a, A1, SUM + OFF1, SQ + OFF1, T, 512, 384);
    finalize_k<<<2, 256>>>(SUM + OFF1, SQ + OFF1, g1a, be1a, 1.f / T, 512, CA + OFF1, CB + OFF1);

    // 2) BN1-apply + lrelu + split -> XH/XL
    bnsplit_k<<<(unsigned)(((long)T * 128 + 255) / 256), 256>>>(
        A1, CA + OFF1, CB + OFF1, XH, XL, (long)T * 128, 512);

    // 3) GEMM2: A2 = X @ W1b + b1b  [T,1152]  + L2 stats
    mma_gemm_k<false><<<dim3(9, (T + 127) / 128), 512, GEMM_SMEM>>>(
        XH, XL, nullptr, nullptr, nullptr, nullptr, nullptr, nullptr,
        WTH + W1B_OFF, WTL + W1B_OFF, b1b, A2, SUM + OFF2, SQ + OFF2, T, 1152, 512);
    finalize_k<<<5, 256>>>(SUM + OFF2, SQ + OFF2, g1b, be1b, 1.f / T, 1152, CA + OFF2, CB + OFF2);

    // 4) scatter (BN2+lrelu fused, v4 reductions) -> POOL raw sums, out_p
    scatter_k<<<T, 128>>>(A2, CA + OFF2, CB + OFF2, ES, EO, POOL, out_p, T);

    // 5) divide + split pooled -> XH/XL
    divsplit_k<<<(unsigned)(((long)O * 128 + 255) / 256), 256>>>(
        POOL, CNT, XH, XL, (long)O * 128, (float)O);

    // 6) GEMM3: A3(=A1) = X @ W2a + b2a  [O,512]  + L3 stats
    mma_gemm_k<false><<<dim3(4, (O + 127) / 128), 512, GEMM_SMEM>>>(
        XH, XL, nullptr, nullptr, nullptr, nullptr, nullptr, nullptr,
        WTH + W2A_OFF, WTL + W2A_OFF, b2a, A1, SUM + OFF3, SQ + OFF3, O, 512, 512);
    finalize_k<<<2, 256>>>(SUM + OFF3, SQ + OFF3, g2a, be2a, 1.f / O, 512, CA + OFF3, CB + OFF3);

    // 7) BN3-apply + lrelu + split -> XH/XL
    bnsplit_k<<<(unsigned)(((long)O * 128 + 255) / 256), 256>>>(
        A1, CA + OFF3, CB + OFF3, XH, XL, (long)O * 128, 512);

    // 8) GEMM4: A4 = X @ W2b + b2b  [O,128]  + L4 stats
    mma_gemm_k<false><<<dim3(1, (O + 127) / 128), 512, GEMM_SMEM>>>(
        XH, XL, nullptr, nullptr, nullptr, nullptr, nullptr, nullptr,
        WTH + W2B_OFF, WTL + W2B_OFF, b2b, A4, SUM + OFF4, SQ + OFF4, O, 128, 512);
    finalize_k<<<1, 256>>>(SUM + OFF4, SQ + OFF4, g2b, be2b, 1.f / O, 128, CA + OFF4, CB + OFF4);

    // 9) BN4 apply -> out_obj
    bn_out_k<<<(unsigned)(((long)O * 128 + 255) / 256), 256>>>(
        A4, CA + OFF4, CB + OFF4, out_obj, (long)O * 128, 128);
}

// round 10
// speedup vs baseline: 3.3076x; 1.2911x over previous
#include <cuda_runtime.h>
#include <cuda_fp16.h>
#include <cstdint>

#define EPS    1e-5f
#define ALPHA  0.2f
#define MAX_O  50000
#define MAX_T  200000

// ---------------- scratch (static device globals; no allocation) -------------
__device__ float g_A1[(size_t)MAX_T * 512];
__device__ float g_A2[(size_t)MAX_T * 1152];
__device__ float g_pooled[(size_t)MAX_O * 512];
__device__ float g_A4[(size_t)MAX_O * 128];
__device__ float g_counts[MAX_O];
__device__ int   g_es[MAX_T];
__device__ int   g_eo[MAX_T];
__device__ int   g_flag32;
// fp16 hi/lo splits of A operands
__device__ __half g_objh[(size_t)MAX_O * 128];
__device__ __half g_objl[(size_t)MAX_O * 128];
__device__ __half g_predh[(size_t)MAX_T * 128];
__device__ __half g_predl[(size_t)MAX_T * 128];
__device__ __half g_xh[(size_t)MAX_T * 512];
__device__ __half g_xl[(size_t)MAX_T * 512];
// transposed weights, single fp16 [N,K] row-major, packed:
#define WT_TOTAL 1114112
__device__ __half g_wt[WT_TOTAL];
__device__ float g_sum[2304];
__device__ float g_sq[2304];
__device__ float g_cA[2304];
__device__ float g_cB[2304];

// ======================= PTX wrappers =========================================
__device__ __forceinline__ uint32_t smem_to_u32(const void* p) {
    uint32_t a;
    asm("{ .reg .u64 t; cvta.to.shared.u64 t, %1; cvt.u32.u64 %0, t; }" : "=r"(a) : "l"(p));
    return a;
}
__device__ __forceinline__ void ldsm_x4(uint32_t addr, uint32_t* r) {
    asm volatile("ldmatrix.sync.aligned.m8n8.x4.shared.b16 {%0,%1,%2,%3}, [%4];"
        : "=r"(r[0]), "=r"(r[1]), "=r"(r[2]), "=r"(r[3]) : "r"(addr));
}
__device__ __forceinline__ void mma_f16(float* c, const uint32_t* a, const uint32_t* b) {
    asm volatile("mma.sync.aligned.m16n8k16.row.col.f32.f16.f16.f32 "
        "{%0,%1,%2,%3},{%4,%5,%6,%7},{%8,%9},{%0,%1,%2,%3};"
        : "+f"(c[0]), "+f"(c[1]), "+f"(c[2]), "+f"(c[3])
        : "r"(a[0]), "r"(a[1]), "r"(a[2]), "r"(a[3]), "r"(b[0]), "r"(b[1]));
}
__device__ __forceinline__ void cp16(uint32_t dst, const void* src) {
    asm volatile("cp.async.cg.shared.global [%0], [%1], 16;" :: "r"(dst), "l"(src));
}
#define CP_COMMIT() asm volatile("cp.async.commit_group;" ::: "memory")
#define CP_WAIT(n)  asm volatile("cp.async.wait_group %0;" :: "n"(n) : "memory")

__device__ __forceinline__ void red4(float* addr, float4 v) {
    asm volatile("red.global.add.v4.f32 [%0], {%1,%2,%3,%4};"
        :: "l"(addr), "f"(v.x), "f"(v.y), "f"(v.z), "f"(v.w) : "memory");
}

// split fp32 -> (hi, lo) fp16 pairs packed as u32
__device__ __forceinline__ void split2h(float x, float y, uint32_t& h, uint32_t& l) {
    __half hx = __float2half(x);
    __half hy = __float2half(y);
    __half2 hp = __halves2half2(hx, hy);
    __half2 lp = __halves2half2(__float2half(x - __half2float(hx)),
                                __float2half(y - __half2float(hy)));
    h = *reinterpret_cast<uint32_t*>(&hp);
    l = *reinterpret_cast<uint32_t*>(&lp);
}

// ======================= small utility kernels ================================
__global__ void zero_k(float* pooled, float* counts, float* sum, float* sq,
                       int* flag32, long n_pooled, int O)
{
    if (blockIdx.x == 0 && threadIdx.x == 0) *flag32 = 0;
    long total = n_pooled + O + 2 * 2304;
    for (long i = blockIdx.x * (long)blockDim.x + threadIdx.x; i < total;
         i += (long)gridDim.x * blockDim.x) {
        if (i < n_pooled)            pooled[i] = 0.f;
        else if (i < n_pooled + O)   counts[i - n_pooled] = 0.f;
        else {
            long j = i - n_pooled - O;
            if (j < 2304) sum[j] = 0.f; else sq[j - 2304] = 0.f;
        }
    }
}

__global__ void probe_k(const int* __restrict__ e32, int* flag32, int T)
{
    int t = blockIdx.x * blockDim.x + threadIdx.x;
    if (t >= T) return;
    if (e32[2 * t + 1] != 0) atomicOr(flag32, 1);
}

__global__ void convert_k(const int* __restrict__ e32, const int* __restrict__ flag32,
                          int* __restrict__ es, int* __restrict__ eo,
                          float* __restrict__ counts, int T)
{
    int t = blockIdx.x * blockDim.x + threadIdx.x;
    if (t >= T) return;
    int s, o;
    if (*flag32) { s = e32[2 * t]; o = e32[2 * t + 1]; }
    else         { s = e32[4 * t]; o = e32[4 * t + 2]; }
    es[t] = s;
    eo[t] = o;
    atomicAdd(&counts[s], 1.f);
    atomicAdd(&counts[o], 1.f);
}

// transpose weights: W[K,N] fp32 -> single fp16 [N,K]
__global__ void wsplit_k(const float* __restrict__ W,
                         __half* __restrict__ wt, int K, int N)
{
    int i = blockIdx.x * blockDim.x + threadIdx.x;
    if (i >= K * N) return;
    int k = i / N, n = i % N;
    wt[(long)n * K + k] = __float2half(W[i]);
}

__global__ void asplit_k(const float* __restrict__ X,
                         __half* __restrict__ h, __half* __restrict__ l, long n4)
{
    long i = blockIdx.x * (long)blockDim.x + threadIdx.x;
    if (i >= n4) return;
    float4 v = *reinterpret_cast<const float4*>(X + i * 4);
    uint32_t h01, l01, h23, l23;
    split2h(v.x, v.y, h01, l01);
    split2h(v.z, v.w, h23, l23);
    *reinterpret_cast<uint2*>(h + i * 4) = make_uint2(h01, h23);
    *reinterpret_cast<uint2*>(l + i * 4) = make_uint2(l01, l23);
}

__global__ void bnsplit_k(const float* __restrict__ X,
                          const float* __restrict__ cA, const float* __restrict__ cB,
                          __half* __restrict__ h, __half* __restrict__ l,
                          long n4, int N)
{
    long i = blockIdx.x * (long)blockDim.x + threadIdx.x;
    if (i >= n4) return;
    long e0 = i * 4;
    int c = (int)(e0 & (N - 1));
    float4 v = *reinterpret_cast<const float4*>(X + e0);
    float4 a = *reinterpret_cast<const float4*>(cA + c);
    float4 b = *reinterpret_cast<const float4*>(cB + c);
    v.x = fmaf(v.x, a.x, b.x); v.x = v.x >= 0.f ? v.x : ALPHA * v.x;
    v.y = fmaf(v.y, a.y, b.y); v.y = v.y >= 0.f ? v.y : ALPHA * v.y;
    v.z = fmaf(v.z, a.z, b.z); v.z = v.z >= 0.f ? v.z : ALPHA * v.z;
    v.w = fmaf(v.w, a.w, b.w); v.w = v.w >= 0.f ? v.w : ALPHA * v.w;
    uint32_t h01, l01, h23, l23;
    split2h(v.x, v.y, h01, l01);
    split2h(v.z, v.w, h23, l23);
    *reinterpret_cast<uint2*>(h + e0) = make_uint2(h01, h23);
    *reinterpret_cast<uint2*>(l + e0) = make_uint2(l01, l23);
}

__global__ void divsplit_k(const float* __restrict__ P, const float* __restrict__ cnt,
                           __half* __restrict__ h, __half* __restrict__ l,
                           long n4, float ocap)
{
    long i = blockIdx.x * (long)blockDim.x + threadIdx.x;
    if (i >= n4) return;
    long e0 = i * 4;
    float c = cnt[e0 >> 9];
    c = fminf(fmaxf(c, 1.f), ocap);
    float r = 1.f / c;
    float4 v = *reinterpret_cast<const float4*>(P + e0);
    v.x *= r; v.y *= r; v.z *= r; v.w *= r;
    uint32_t h01, l01, h23, l23;
    split2h(v.x, v.y, h01, l01);
    split2h(v.z, v.w, h23, l23);
    *reinterpret_cast<uint2*>(h + e0) = make_uint2(h01, h23);
    *reinterpret_cast<uint2*>(l + e0) = make_uint2(l01, l23);
}

// ======================= pipelined mma.sync GEMM ===============================
// CTA 128x128, 16 warps (4x4), warp tile 32x32.
// fp16x2 scheme: A = ah + al (fp16 hi/lo), B = single fp16.
//   acc += ah@B ; acc += al@B   (2 MMAs per tile instead of 3)
// K-chunk 64, 3-stage cp.async, smem arrays: Ah, Al, B (ROWB=144, conflict-free).
#define ROWB   144
#define STAGE  (3 * 128 * ROWB)          // 55296 B
#define NSTG   3
#define GEMM_SMEM (NSTG * STAGE)         // 165888 B

template<bool GATHER>
__global__ void __launch_bounds__(512, 1)
mma_gemm_k(const __half* __restrict__ Ah, const __half* __restrict__ Al,
           const __half* __restrict__ objh, const __half* __restrict__ objl,
           const __half* __restrict__ predh, const __half* __restrict__ predl,
           const int* __restrict__ es, const int* __restrict__ eo,
           const __half* __restrict__ Bt,
           const float* __restrict__ bias,
           float* __restrict__ C, float* __restrict__ gsum, float* __restrict__ gsq,
           int M, int N, int K)
{
    extern __shared__ __align__(16) char smem[];
    const uint32_t sbase = smem_to_u32(smem);

    const int tid  = threadIdx.x;
    const int lane = tid & 31;
    const int wid  = tid >> 5;
    const int wm   = wid >> 2;
    const int wn   = wid & 3;
    const int m0   = blockIdx.y * 128, n0 = blockIdx.x * 128;
    const int q8   = lane >> 3;
    const int r8   = lane & 7;

    float acc[2][4][4];
#pragma unroll
    for (int i = 0; i < 2; i++)
#pragma unroll
        for (int j = 0; j < 4; j++)
#pragma unroll
            for (int q = 0; q < 4; q++) acc[i][j][q] = 0.f;

    const int nk = K >> 6;    // K chunks of 64

    // ---- async load of one K64-chunk into a stage (512 threads) ----
    auto load_chunk = [&](int k0, int stage) {
        const uint32_t aAh = sbase + stage * STAGE;
        const uint32_t aAl = aAh + 128 * ROWB;
        const uint32_t aB  = aAl + 128 * ROWB;
        // A: 2 arrays x 128 rows x 8 chunks of 16B = 2048 cp16 / 512 thr = 4
#pragma unroll
        for (int i = 0; i < 4; i++) {
            int idx = tid + (i << 9);
            int arr = idx >> 10;
            int r   = (idx >> 3) & 127;
            int c   = idx & 7;
            int gm  = m0 + r;
            int gmc = gm < M ? gm : M - 1;
            const __half* src;
            if (GATHER) {
                long sr; const __half *sh, *sl;
                if (k0 < 128)      { sr = (long)es[gmc]; sh = objh;  sl = objl;  }
                else if (k0 < 256) { sr = gmc;           sh = predh; sl = predl; }
                else               { sr = (long)eo[gmc]; sh = objh;  sl = objl;  }
                src = (arr ? sl : sh) + sr * 128 + (k0 & 127) + c * 8;
            } else {
                src = (arr ? Al : Ah) + (long)gmc * K + k0 + c * 8;
            }
            cp16((arr ? aAl : aAh) + r * ROWB + c * 16, src);
        }
        // B: 1 array x 128 rows x 8 chunks of 16B = 1024 cp16 / 512 thr = 2
#pragma unroll
        for (int i = 0; i < 2; i++) {
            int idx = tid + (i << 9);
            int r   = (idx >> 3) & 127;
            int c   = idx & 7;
            const __half* src = Bt + (long)(n0 + r) * K + k0 + c * 8;
            cp16(aB + r * ROWB + c * 16, src);
        }
        CP_COMMIT();
    };

    // ---- compute one K64-chunk (4 k16 steps), 2 MMA passes per step ----
    auto compute = [&](int stage) {
        const uint32_t aAh = sbase + stage * STAGE;
        const uint32_t aAl = aAh + 128 * ROWB;
        const uint32_t aB  = aAl + 128 * ROWB;
#pragma unroll
        for (int s = 0; s < 4; s++) {
            uint32_t bh[4][2], ah[2][4], al[2][4];
#pragma unroll
            for (int j = 0; j < 2; j++) {
                int nrow = wn * 32 + j * 16 + (q8 >> 1) * 8 + r8;
                int kb   = s * 32 + (q8 & 1) * 16;
                uint32_t addr = (uint32_t)(nrow * ROWB + kb);
                uint32_t r[4];
                ldsm_x4(aB + addr, r);
                bh[2 * j][0] = r[0]; bh[2 * j][1] = r[1];
                bh[2 * j + 1][0] = r[2]; bh[2 * j + 1][1] = r[3];
            }
#pragma unroll
            for (int mt = 0; mt < 2; mt++) {
                int mrow = wm * 32 + mt * 16 + (q8 & 1) * 8 + r8;
                int kb   = s * 32 + (q8 >> 1) * 16;
                uint32_t addr = (uint32_t)(mrow * ROWB + kb);
                ldsm_x4(aAh + addr, ah[mt]);
                ldsm_x4(aAl + addr, al[mt]);
            }
            // pass 1: ah @ B (8 independent accs)
#pragma unroll
            for (int mt = 0; mt < 2; mt++)
#pragma unroll
                for (int nt = 0; nt < 4; nt++)
                    mma_f16(acc[mt][nt], ah[mt], bh[nt]);
            // pass 2: al @ B
#pragma unroll
            for (int mt = 0; mt < 2; mt++)
#pragma unroll
                for (int nt = 0; nt < 4; nt++)
                    mma_f16(acc[mt][nt], al[mt], bh[nt]);
        }
    };

    // ---- 3-stage pipeline, one sync per chunk ----
    load_chunk(0, 0);
    if (nk > 1) load_chunk(64, 1);
    for (int it = 0; it < nk; it++) {
        if (it == nk - 1) { CP_WAIT(0); } else { CP_WAIT(1); }
        __syncthreads();
        compute(it % NSTG);
        if (it + 2 < nk) load_chunk((it + 2) << 6, (it + 2) % NSTG);
    }

    // ---- epilogue: +bias, store, fused column stats ----
#pragma unroll
    for (int nt = 0; nt < 4; nt++) {
        int col = n0 + wn * 32 + nt * 8 + (lane & 3) * 2;
        float2 bv = *reinterpret_cast<const float2*>(bias + col);
        float s0 = 0.f, s1 = 0.f, q0 = 0.f, q1 = 0.f;
#pragma unroll
        for (int mt = 0; mt < 2; mt++) {
            int row0 = m0 + wm * 32 + mt * 16 + (lane >> 2);
            int row1 = row0 + 8;
            float v0 = acc[mt][nt][0] + bv.x;
            float v1 = acc[mt][nt][1] + bv.y;
            float v2 = acc[mt][nt][2] + bv.x;
            float v3 = acc[mt][nt][3] + bv.y;
            if (row0 < M) {
                *reinterpret_cast<float2*>(C + (long)row0 * N + col) = make_float2(v0, v1);
                s0 += v0; q0 += v0 * v0; s1 += v1; q1 += v1 * v1;
            }
            if (row1 < M) {
                *reinterpret_cast<float2*>(C + (long)row1 * N + col) = make_float2(v2, v3);
                s0 += v2; q0 += v2 * v2; s1 += v3; q1 += v3 * v3;
            }
        }
#pragma unroll
        for (int off = 4; off < 32; off <<= 1) {
            s0 += __shfl_down_sync(0xffffffffu, s0, off);
            s1 += __shfl_down_sync(0xffffffffu, s1, off);
            q0 += __shfl_down_sync(0xffffffffu, q0, off);
            q1 += __shfl_down_sync(0xffffffffu, q1, off);
        }
        if (lane < 4) {
            atomicAdd(&gsum[col],     s0);
            atomicAdd(&gsum[col + 1], s1);
            atomicAdd(&gsq[col],      q0);
            atomicAdd(&gsq[col + 1],  q1);
        }
    }
}

// ======================= stats finalize / BN out / scatter ====================
__global__ void finalize_k(const float* __restrict__ sum, const float* __restrict__ sq,
                           const float* __restrict__ gamma, const float* __restrict__ beta,
                           float invM, int N,
                           float* __restrict__ cA, float* __restrict__ cB)
{
    int n = blockIdx.x * blockDim.x + threadIdx.x;
    if (n >= N) return;
    float mean = sum[n] * invM;
    float var  = sq[n] * invM - mean * mean;
    float inv  = rsqrtf(var + EPS);
    float a    = inv * gamma[n];
    cA[n] = a;
    cB[n] = beta[n] - mean * a;
}

__global__ void bn_out_k(const float* __restrict__ X, const float* __restrict__ cA,
                         const float* __restrict__ cB, float* __restrict__ out,
                         long total, int N)
{
    long i = blockIdx.x * (long)blockDim.x + threadIdx.x;
    if (i >= total) return;
    int n = (int)(i % N);
    float v = X[i] * cA[n] + cB[n];
    out[i] = (v >= 0.f) ? v : ALPHA * v;
}

__device__ __forceinline__ float4 bn4(float4 v, float4 a, float4 b) {
    v.x = fmaf(v.x, a.x, b.x); v.x = v.x >= 0.f ? v.x : ALPHA * v.x;
    v.y = fmaf(v.y, a.y, b.y); v.y = v.y >= 0.f ? v.y : ALPHA * v.y;
    v.z = fmaf(v.z, a.z, b.z); v.z = v.z >= 0.f ? v.z : ALPHA * v.z;
    v.w = fmaf(v.w, a.w, b.w); v.w = v.w >= 0.f ? v.w : ALPHA * v.w;
    return v;
}

__global__ void scatter_k(const float* __restrict__ A2,
                          const float* __restrict__ cA, const float* __restrict__ cB,
                          const int* __restrict__ es, const int* __restrict__ eo,
                          float* __restrict__ pooled, float* __restrict__ out_p, int T)
{
    int t = blockIdx.x;
    if (t >= T) return;
    int s = es[t];
    int o = eo[t];
    int tid = threadIdx.x;
    const float4* row = reinterpret_cast<const float4*>(A2 + (long)t * 1152);
    const float4* a4  = reinterpret_cast<const float4*>(cA);
    const float4* b4  = reinterpret_cast<const float4*>(cB);

    {
        float4 v = bn4(row[tid], a4[tid], b4[tid]);
        red4(&pooled[(long)s * 512 + tid * 4], v);
    }
    if (tid < 32) {
        int c4 = 128 + tid;
        float4 v = bn4(row[c4], a4[c4], b4[c4]);
        *reinterpret_cast<float4*>(out_p + (long)t * 128 + tid * 4) = v;
    }
    {
        int c4 = 160 + tid;
        float4 v = bn4(row[c4], a4[c4], b4[c4]);
        red4(&pooled[(long)o * 512 + tid * 4], v);
    }
}

// ======================= launch ================================================
extern "C" void kernel_launch(void* const* d_in, const int* in_sizes, int n_in,
                              void* d_out, int out_size)
{
    const float* obj   = (const float*)d_in[0];
    const float* pred  = (const float*)d_in[1];
    const int*   e32   = (const int*)d_in[2];
    const float* W1a = (const float*)d_in[3];
    const float* b1a = (const float*)d_in[4];
    const float* g1a = (const float*)d_in[5];
    const float* be1a= (const float*)d_in[6];
    const float* W1b = (const float*)d_in[7];
    const float* b1b = (const float*)d_in[8];
    const float* g1b = (const float*)d_in[9];
    const float* be1b= (const float*)d_in[10];
    const float* W2a = (const float*)d_in[11];
    const float* b2a = (const float*)d_in[12];
    const float* g2a = (const float*)d_in[13];
    const float* be2a= (const float*)d_in[14];
    const float* W2b = (const float*)d_in[15];
    const float* b2b = (const float*)d_in[16];
    const float* g2b = (const float*)d_in[17];
    const float* be2b= (const float*)d_in[18];

    const int O = in_sizes[0] / 128;
    const int T = in_sizes[1] / 128;

    float* out     = (float*)d_out;
    float* out_obj = out;
    float* out_p   = out + (size_t)O * 128;

    float *A1, *A2, *POOL, *A4, *CNT, *SUM, *SQ, *CA, *CB;
    int *ES, *EO, *FLAG;
    __half *WT, *OBJH, *OBJL, *PRH, *PRL, *XH, *XL;
    cudaGetSymbolAddress((void**)&A1,   g_A1);
    cudaGetSymbolAddress((void**)&A2,   g_A2);
    cudaGetSymbolAddress((void**)&POOL, g_pooled);
    cudaGetSymbolAddress((void**)&A4,   g_A4);
    cudaGetSymbolAddress((void**)&CNT,  g_counts);
    cudaGetSymbolAddress((void**)&SUM,  g_sum);
    cudaGetSymbolAddress((void**)&SQ,   g_sq);
    cudaGetSymbolAddress((void**)&CA,   g_cA);
    cudaGetSymbolAddress((void**)&CB,   g_cB);
    cudaGetSymbolAddress((void**)&ES,   g_es);
    cudaGetSymbolAddress((void**)&EO,   g_eo);
    cudaGetSymbolAddress((void**)&FLAG, g_flag32);
    cudaGetSymbolAddress((void**)&WT,   g_wt);
    cudaGetSymbolAddress((void**)&OBJH, g_objh);
    cudaGetSymbolAddress((void**)&OBJL, g_objl);
    cudaGetSymbolAddress((void**)&PRH,  g_predh);
    cudaGetSymbolAddress((void**)&PRL,  g_predl);
    cudaGetSymbolAddress((void**)&XH,   g_xh);
    cudaGetSymbolAddress((void**)&XL,   g_xl);

    cudaFuncSetAttribute(mma_gemm_k<true>,
                         cudaFuncAttributeMaxDynamicSharedMemorySize, GEMM_SMEM);
    cudaFuncSetAttribute(mma_gemm_k<false>,
                         cudaFuncAttributeMaxDynamicSharedMemorySize, GEMM_SMEM);

    const int OFF1 = 0, OFF2 = 512, OFF3 = 1664, OFF4 = 2176;
    const int W1A_OFF = 0, W1B_OFF = 196608, W2A_OFF = 786432, W2B_OFF = 1048576;

    // 0) zero accumulators; probe + normalize edges (+counts)
    zero_k<<<2048, 256>>>(POOL, CNT, SUM, SQ, FLAG, (long)O * 512, O);
    probe_k<<<(T + 255) / 256, 256>>>(e32, FLAG, T);
    convert_k<<<(T + 255) / 256, 256>>>(e32, FLAG, ES, EO, CNT, T);

    // 0b) transpose weights to fp16 [N,K]; split inputs obj/pred to fp16 hi/lo
    wsplit_k<<<(384 * 512  + 255) / 256, 256>>>(W1a, WT + W1A_OFF, 384, 512);
    wsplit_k<<<(512 * 1152 + 255) / 256, 256>>>(W1b, WT + W1B_OFF, 512, 1152);
    wsplit_k<<<(512 * 512  + 255) / 256, 256>>>(W2a, WT + W2A_OFF, 512, 512);
    wsplit_k<<<(512 * 128  + 255) / 256, 256>>>(W2b, WT + W2B_OFF, 512, 128);
    asplit_k<<<(unsigned)(((long)O * 32 + 255) / 256), 256>>>(obj,  OBJH, OBJL, (long)O * 32);
    asplit_k<<<(unsigned)(((long)T * 32 + 255) / 256), 256>>>(pred, PRH,  PRL,  (long)T * 32);

    // 1) GEMM1 (gathered): A1 = cur_t @ W1a + b1a  [T,512]  + L1 stats
    mma_gemm_k<true><<<dim3(4, (T + 127) / 128), 512, GEMM_SMEM>>>(
        nullptr, nullptr, OBJH, OBJL, PRH, PRL, ES, EO,
        WT + W1A_OFF, b1a, A1, SUM + OFF1, SQ + OFF1, T, 512, 384);
    finalize_k<<<2, 256>>>(SUM + OFF1, SQ + OFF1, g1a, be1a, 1.f / T, 512, CA + OFF1, CB + OFF1);

    // 2) BN1-apply + lrelu + split -> XH/XL
    bnsplit_k<<<(unsigned)(((long)T * 128 + 255) / 256), 256>>>(
        A1, CA + OFF1, CB + OFF1, XH, XL, (long)T * 128, 512);

    // 3) GEMM2: A2 = X @ W1b + b1b  [T,1152]  + L2 stats
    mma_gemm_k<false><<<dim3(9, (T + 127) / 128), 512, GEMM_SMEM>>>(
        XH, XL, nullptr, nullptr, nullptr, nullptr, nullptr, nullptr,
        WT + W1B_OFF, b1b, A2, SUM + OFF2, SQ + OFF2, T, 1152, 512);
    finalize_k<<<5, 256>>>(SUM + OFF2, SQ + OFF2, g1b, be1b, 1.f / T, 1152, CA + OFF2, CB + OFF2);

    // 4) scatter (BN2+lrelu fused, v4 reductions) -> POOL raw sums, out_p
    scatter_k<<<T, 128>>>(A2, CA + OFF2, CB + OFF2, ES, EO, POOL, out_p, T);

    // 5) divide + split pooled -> XH/XL
    divsplit_k<<<(unsigned)(((long)O * 128 + 255) / 256), 256>>>(
        POOL, CNT, XH, XL, (long)O * 128, (float)O);

    // 6) GEMM3: A3(=A1) = X @ W2a + b2a  [O,512]  + L3 stats
    mma_gemm_k<false><<<dim3(4, (O + 127) / 128), 512, GEMM_SMEM>>>(
        XH, XL, nullptr, nullptr, nullptr, nullptr, nullptr, nullptr,
        WT + W2A_OFF, b2a, A1, SUM + OFF3, SQ + OFF3, O, 512, 512);
    finalize_k<<<2, 256>>>(SUM + OFF3, SQ + OFF3, g2a, be2a, 1.f / O, 512, CA + OFF3, CB + OFF3);

    // 7) BN3-apply + lrelu + split -> XH/XL
    bnsplit_k<<<(unsigned)(((long)O * 128 + 255) / 256), 256>>>(
        A1, CA + OFF3, CB + OFF3, XH, XL, (long)O * 128, 512);

    // 8) GEMM4: A4 = X @ W2b + b2b  [O,128]  + L4 stats
    mma_gemm_k<false><<<dim3(1, (O + 127) / 128), 512, GEMM_SMEM>>>(
        XH, XL, nullptr, nullptr, nullptr, nullptr, nullptr, nullptr,
        WT + W2B_OFF, b2b, A4, SUM + OFF4, SQ + OFF4, O, 128, 512);
    finalize_k<<<1, 256>>>(SUM + OFF4, SQ + OFF4, g2b, be2b, 1.f / O, 128, CA + OFF4, CB + OFF4);

    // 9) BN4 apply -> out_obj
    bn_out_k<<<(unsigned)(((long)O * 128 + 255) / 256), 256>>>(
        A4, CA + OFF4, CB + OFF4, out_obj, (long)O * 128, 128);
}

// round 11
// speedup vs baseline: 4.7314x; 1.4305x over previous
#include <cuda_runtime.h>
#include <cuda_fp16.h>
#include <cstdint>

#define EPS    1e-5f
#define ALPHA  0.2f
#define MAX_O  50000
#define MAX_T  200000

// ---------------- scratch (static device globals; no allocation) -------------
__device__ float  g_A1[(size_t)MAX_T * 512];          // pre-BN fp32 (reused for A3)
__device__ __half g_A2[(size_t)MAX_T * 1152];         // pre-BN fp16 (big buffer)
__device__ float  g_pooled[(size_t)MAX_O * 512];
__device__ float  g_A4[(size_t)MAX_O * 128];
__device__ float  g_counts[MAX_O];
__device__ int    g_es[MAX_T];
__device__ int    g_eo[MAX_T];
__device__ int    g_flag32;
__device__ __half g_objh[(size_t)MAX_O * 128];
__device__ __half g_predh[(size_t)MAX_T * 128];
__device__ __half g_xh[(size_t)MAX_T * 512];
#define WT_TOTAL 1114112
__device__ __half g_wt[WT_TOTAL];
__device__ float g_sum[2304];
__device__ float g_sq[2304];
__device__ float g_cA[2304];
__device__ float g_cB[2304];

// ======================= PTX wrappers =========================================
__device__ __forceinline__ uint32_t smem_to_u32(const void* p) {
    uint32_t a;
    asm("{ .reg .u64 t; cvta.to.shared.u64 t, %1; cvt.u32.u64 %0, t; }" : "=r"(a) : "l"(p));
    return a;
}
__device__ __forceinline__ void ldsm_x4(uint32_t addr, uint32_t* r) {
    asm volatile("ldmatrix.sync.aligned.m8n8.x4.shared.b16 {%0,%1,%2,%3}, [%4];"
        : "=r"(r[0]), "=r"(r[1]), "=r"(r[2]), "=r"(r[3]) : "r"(addr));
}
__device__ __forceinline__ void mma_f16(float* c, const uint32_t* a, const uint32_t* b) {
    asm volatile("mma.sync.aligned.m16n8k16.row.col.f32.f16.f16.f32 "
        "{%0,%1,%2,%3},{%4,%5,%6,%7},{%8,%9},{%0,%1,%2,%3};"
        : "+f"(c[0]), "+f"(c[1]), "+f"(c[2]), "+f"(c[3])
        : "r"(a[0]), "r"(a[1]), "r"(a[2]), "r"(a[3]), "r"(b[0]), "r"(b[1]));
}
__device__ __forceinline__ void cp16(uint32_t dst, const void* src) {
    asm volatile("cp.async.cg.shared.global [%0], [%1], 16;" :: "r"(dst), "l"(src));
}
#define CP_COMMIT() asm volatile("cp.async.commit_group;" ::: "memory")
#define CP_WAIT(n)  asm volatile("cp.async.wait_group %0;" :: "n"(n) : "memory")

__device__ __forceinline__ void red4(float* addr, float4 v) {
    asm volatile("red.global.add.v4.f32 [%0], {%1,%2,%3,%4};"
        :: "l"(addr), "f"(v.x), "f"(v.y), "f"(v.z), "f"(v.w) : "memory");
}

// epilogue store helpers (fp32 or fp16 C)
__device__ __forceinline__ void store2(float* C, long off, float v0, float v1) {
    *reinterpret_cast<float2*>(C + off) = make_float2(v0, v1);
}
__device__ __forceinline__ void store2(__half* C, long off, float v0, float v1) {
    *reinterpret_cast<__half2*>(C + off) = __floats2half2_rn(v0, v1);
}

// ======================= small utility kernels ================================
__global__ void zero_k(float* pooled, float* counts, float* sum, float* sq,
                       int* flag32, long n_pooled, int O)
{
    if (blockIdx.x == 0 && threadIdx.x == 0) *flag32 = 0;
    long total = n_pooled + O + 2 * 2304;
    for (long i = blockIdx.x * (long)blockDim.x + threadIdx.x; i < total;
         i += (long)gridDim.x * blockDim.x) {
        if (i < n_pooled)            pooled[i] = 0.f;
        else if (i < n_pooled + O)   counts[i - n_pooled] = 0.f;
        else {
            long j = i - n_pooled - O;
            if (j < 2304) sum[j] = 0.f; else sq[j - 2304] = 0.f;
        }
    }
}

__global__ void probe_k(const int* __restrict__ e32, int* flag32, int T)
{
    int t = blockIdx.x * blockDim.x + threadIdx.x;
    if (t >= T) return;
    if (e32[2 * t + 1] != 0) atomicOr(flag32, 1);
}

__global__ void convert_k(const int* __restrict__ e32, const int* __restrict__ flag32,
                          int* __restrict__ es, int* __restrict__ eo,
                          float* __restrict__ counts, int T)
{
    int t = blockIdx.x * blockDim.x + threadIdx.x;
    if (t >= T) return;
    int s, o;
    if (*flag32) { s = e32[2 * t]; o = e32[2 * t + 1]; }
    else         { s = e32[4 * t]; o = e32[4 * t + 2]; }
    es[t] = s;
    eo[t] = o;
    atomicAdd(&counts[s], 1.f);
    atomicAdd(&counts[o], 1.f);
}

// ONE kernel: transpose all 4 weights fp32[K,N] -> fp16[N,K] into packed g_wt
__global__ void prep_w_k(const float* __restrict__ W1a, const float* __restrict__ W1b,
                         const float* __restrict__ W2a, const float* __restrict__ W2b,
                         __half* __restrict__ wt)
{
    int i = blockIdx.x * blockDim.x + threadIdx.x;
    if (i >= WT_TOTAL) return;
    const float* W; int K, N, base;
    if (i < 196608)       { W = W1a; K = 384; N = 512;  base = 0;       }
    else if (i < 786432)  { W = W1b; K = 512; N = 1152; base = 196608;  }
    else if (i < 1048576) { W = W2a; K = 512; N = 512;  base = 786432;  }
    else                  { W = W2b; K = 512; N = 128;  base = 1048576; }
    int j = i - base;
    int k = j / N, n = j % N;
    wt[(long)base + (long)n * K + k] = __float2half(W[(long)k * N + n]);
}

// ONE kernel: convert obj + pred fp32 -> fp16 (vectorized x4)
__global__ void prep_a_k(const float* __restrict__ obj, const float* __restrict__ pred,
                         __half* __restrict__ objh, __half* __restrict__ predh,
                         long no4, long np4)
{
    long i = blockIdx.x * (long)blockDim.x + threadIdx.x;
    if (i >= no4 + np4) return;
    const float* src; __half* dst; long e0;
    if (i < no4) { src = obj;  dst = objh;  e0 = i * 4; }
    else         { src = pred; dst = predh; e0 = (i - no4) * 4; }
    float4 v = *reinterpret_cast<const float4*>(src + e0);
    __half2 h01 = __floats2half2_rn(v.x, v.y);
    __half2 h23 = __floats2half2_rn(v.z, v.w);
    *reinterpret_cast<uint2*>(dst + e0) =
        make_uint2(*reinterpret_cast<uint32_t*>(&h01), *reinterpret_cast<uint32_t*>(&h23));
}

// bn-apply + lrelu -> fp16
__global__ void bnhalf_k(const float* __restrict__ X,
                         const float* __restrict__ cA, const float* __restrict__ cB,
                         __half* __restrict__ h, long n4, int N)
{
    long i = blockIdx.x * (long)blockDim.x + threadIdx.x;
    if (i >= n4) return;
    long e0 = i * 4;
    int c = (int)(e0 & (N - 1));
    float4 v = *reinterpret_cast<const float4*>(X + e0);
    float4 a = *reinterpret_cast<const float4*>(cA + c);
    float4 b = *reinterpret_cast<const float4*>(cB + c);
    v.x = fmaf(v.x, a.x, b.x); v.x = v.x >= 0.f ? v.x : ALPHA * v.x;
    v.y = fmaf(v.y, a.y, b.y); v.y = v.y >= 0.f ? v.y : ALPHA * v.y;
    v.z = fmaf(v.z, a.z, b.z); v.z = v.z >= 0.f ? v.z : ALPHA * v.z;
    v.w = fmaf(v.w, a.w, b.w); v.w = v.w >= 0.f ? v.w : ALPHA * v.w;
    __half2 h01 = __floats2half2_rn(v.x, v.y);
    __half2 h23 = __floats2half2_rn(v.z, v.w);
    *reinterpret_cast<uint2*>(h + e0) =
        make_uint2(*reinterpret_cast<uint32_t*>(&h01), *reinterpret_cast<uint32_t*>(&h23));
}

// pooled / clamp(count) -> fp16
__global__ void divhalf_k(const float* __restrict__ P, const float* __restrict__ cnt,
                          __half* __restrict__ h, long n4, float ocap)
{
    long i = blockIdx.x * (long)blockDim.x + threadIdx.x;
    if (i >= n4) return;
    long e0 = i * 4;
    float c = cnt[e0 >> 9];
    c = fminf(fmaxf(c, 1.f), ocap);
    float r = 1.f / c;
    float4 v = *reinterpret_cast<const float4*>(P + e0);
    __half2 h01 = __floats2half2_rn(v.x * r, v.y * r);
    __half2 h23 = __floats2half2_rn(v.z * r, v.w * r);
    *reinterpret_cast<uint2*>(h + e0) =
        make_uint2(*reinterpret_cast<uint32_t*>(&h01), *reinterpret_cast<uint32_t*>(&h23));
}

// ======================= pipelined mma.sync GEMM ===============================
// CTA 128x128, 16 warps (4x4), warp tile 32x32, single fp16 A and B (1 MMA/tile).
// K-chunk 64, 3-stage cp.async. Fused column stats. OutT = float or __half.
#define ROWB   144
#define STAGE  (2 * 128 * ROWB)          // 36864 B: A, B
#define NSTG   3
#define GEMM_SMEM (NSTG * STAGE)         // 110592 B

template<bool GATHER, typename TOUT>
__global__ void __launch_bounds__(512, 1)
mma_gemm_k(const __half* __restrict__ Ax,
           const __half* __restrict__ objh, const __half* __restrict__ predh,
           const int* __restrict__ es, const int* __restrict__ eo,
           const __half* __restrict__ Bt,
           const float* __restrict__ bias,
           TOUT* __restrict__ C, float* __restrict__ gsum, float* __restrict__ gsq,
           int M, int N, int K)
{
    extern __shared__ __align__(16) char smem[];
    const uint32_t sbase = smem_to_u32(smem);

    const int tid  = threadIdx.x;
    const int lane = tid & 31;
    const int wid  = tid >> 5;
    const int wm   = wid >> 2;
    const int wn   = wid & 3;
    const int m0   = blockIdx.y * 128, n0 = blockIdx.x * 128;
    const int q8   = lane >> 3;
    const int r8   = lane & 7;

    float acc[2][4][4];
#pragma unroll
    for (int i = 0; i < 2; i++)
#pragma unroll
        for (int j = 0; j < 4; j++)
#pragma unroll
            for (int q = 0; q < 4; q++) acc[i][j][q] = 0.f;

    const int nk = K >> 6;

    auto load_chunk = [&](int k0, int stage) {
        const uint32_t aA = sbase + stage * STAGE;
        const uint32_t aB = aA + 128 * ROWB;
        // A: 128 rows x 8 chunks of 16B = 1024 cp16 / 512 thr = 2
#pragma unroll
        for (int i = 0; i < 2; i++) {
            int idx = tid + (i << 9);
            int r   = (idx >> 3) & 127;
            int c   = idx & 7;
            int gm  = m0 + r;
            int gmc = gm < M ? gm : M - 1;
            const __half* src;
            if (GATHER) {
                long sr; const __half* sh;
                if (k0 < 128)      { sr = (long)es[gmc]; sh = objh;  }
                else if (k0 < 256) { sr = gmc;           sh = predh; }
                else               { sr = (long)eo[gmc]; sh = objh;  }
                src = sh + sr * 128 + (k0 & 127) + c * 8;
            } else {
                src = Ax + (long)gmc * K + k0 + c * 8;
            }
            cp16(aA + r * ROWB + c * 16, src);
        }
        // B: 128 rows x 8 chunks of 16B
#pragma unroll
        for (int i = 0; i < 2; i++) {
            int idx = tid + (i << 9);
            int r   = (idx >> 3) & 127;
            int c   = idx & 7;
            const __half* src = Bt + (long)(n0 + r) * K + k0 + c * 8;
            cp16(aB + r * ROWB + c * 16, src);
        }
        CP_COMMIT();
    };

    auto compute = [&](int stage) {
        const uint32_t aA = sbase + stage * STAGE;
        const uint32_t aB = aA + 128 * ROWB;
#pragma unroll
        for (int s = 0; s < 4; s++) {
            uint32_t bh[4][2], ah[2][4];
#pragma unroll
            for (int j = 0; j < 2; j++) {
                int nrow = wn * 32 + j * 16 + (q8 >> 1) * 8 + r8;
                int kb   = s * 32 + (q8 & 1) * 16;
                uint32_t addr = (uint32_t)(nrow * ROWB + kb);
                uint32_t r[4];
                ldsm_x4(aB + addr, r);
                bh[2 * j][0] = r[0]; bh[2 * j][1] = r[1];
                bh[2 * j + 1][0] = r[2]; bh[2 * j + 1][1] = r[3];
            }
#pragma unroll
            for (int mt = 0; mt < 2; mt++) {
                int mrow = wm * 32 + mt * 16 + (q8 & 1) * 8 + r8;
                int kb   = s * 32 + (q8 >> 1) * 16;
                ldsm_x4(aA + (uint32_t)(mrow * ROWB + kb), ah[mt]);
            }
#pragma unroll
            for (int mt = 0; mt < 2; mt++)
#pragma unroll
                for (int nt = 0; nt < 4; nt++)
                    mma_f16(acc[mt][nt], ah[mt], bh[nt]);
        }
    };

    load_chunk(0, 0);
    if (nk > 1) load_chunk(64, 1);
    for (int it = 0; it < nk; it++) {
        if (it == nk - 1) { CP_WAIT(0); } else { CP_WAIT(1); }
        __syncthreads();
        compute(it % NSTG);
        if (it + 2 < nk) load_chunk((it + 2) << 6, (it + 2) % NSTG);
    }

    // ---- epilogue: +bias, store (fp32 or fp16), fused column stats ----
#pragma unroll
    for (int nt = 0; nt < 4; nt++) {
        int col = n0 + wn * 32 + nt * 8 + (lane & 3) * 2;
        float2 bv = *reinterpret_cast<const float2*>(bias + col);
        float s0 = 0.f, s1 = 0.f, q0 = 0.f, q1 = 0.f;
#pragma unroll
        for (int mt = 0; mt < 2; mt++) {
            int row0 = m0 + wm * 32 + mt * 16 + (lane >> 2);
            int row1 = row0 + 8;
            float v0 = acc[mt][nt][0] + bv.x;
            float v1 = acc[mt][nt][1] + bv.y;
            float v2 = acc[mt][nt][2] + bv.x;
            float v3 = acc[mt][nt][3] + bv.y;
            if (row0 < M) {
                store2(C, (long)row0 * N + col, v0, v1);
                s0 += v0; q0 += v0 * v0; s1 += v1; q1 += v1 * v1;
            }
            if (row1 < M) {
                store2(C, (long)row1 * N + col, v2, v3);
                s0 += v2; q0 += v2 * v2; s1 += v3; q1 += v3 * v3;
            }
        }
#pragma unroll
        for (int off = 4; off < 32; off <<= 1) {
            s0 += __shfl_down_sync(0xffffffffu, s0, off);
            s1 += __shfl_down_sync(0xffffffffu, s1, off);
            q0 += __shfl_down_sync(0xffffffffu, q0, off);
            q1 += __shfl_down_sync(0xffffffffu, q1, off);
        }
        if (lane < 4) {
            atomicAdd(&gsum[col],     s0);
            atomicAdd(&gsum[col + 1], s1);
            atomicAdd(&gsq[col],      q0);
            atomicAdd(&gsq[col + 1],  q1);
        }
    }
}

// ======================= stats finalize / BN out / scatter ====================
__global__ void finalize_k(const float* __restrict__ sum, const float* __restrict__ sq,
                           const float* __restrict__ gamma, const float* __restrict__ beta,
                           float invM, int N,
                           float* __restrict__ cA, float* __restrict__ cB)
{
    int n = blockIdx.x * blockDim.x + threadIdx.x;
    if (n >= N) return;
    float mean = sum[n] * invM;
    float var  = sq[n] * invM - mean * mean;
    float inv  = rsqrtf(var + EPS);
    float a    = inv * gamma[n];
    cA[n] = a;
    cB[n] = beta[n] - mean * a;
}

__global__ void bn_out_k(const float* __restrict__ X, const float* __restrict__ cA,
                         const float* __restrict__ cB, float* __restrict__ out,
                         long total, int N)
{
    long i = blockIdx.x * (long)blockDim.x + threadIdx.x;
    if (i >= total) return;
    int n = (int)(i % N);
    float v = X[i] * cA[n] + cB[n];
    out[i] = (v >= 0.f) ? v : ALPHA * v;
}

__device__ __forceinline__ float4 bn4(float4 v, float4 a, float4 b) {
    v.x = fmaf(v.x, a.x, b.x); v.x = v.x >= 0.f ? v.x : ALPHA * v.x;
    v.y = fmaf(v.y, a.y, b.y); v.y = v.y >= 0.f ? v.y : ALPHA * v.y;
    v.z = fmaf(v.z, a.z, b.z); v.z = v.z >= 0.f ? v.z : ALPHA * v.z;
    v.w = fmaf(v.w, a.w, b.w); v.w = v.w >= 0.f ? v.w : ALPHA * v.w;
    return v;
}

__device__ __forceinline__ float4 ld_h4(const __half* p) {
    uint2 raw = *reinterpret_cast<const uint2*>(p);
    __half2 p0 = *reinterpret_cast<__half2*>(&raw.x);
    __half2 p1 = *reinterpret_cast<__half2*>(&raw.y);
    float2 f0 = __half22float2(p0), f1 = __half22float2(p1);
    return make_float4(f0.x, f0.y, f1.x, f1.y);
}

// one block (128 thr) per triple row; A2 is fp16; v4 reductions into pooled
__global__ void scatter_k(const __half* __restrict__ A2,
                          const float* __restrict__ cA, const float* __restrict__ cB,
                          const int* __restrict__ es, const int* __restrict__ eo,
                          float* __restrict__ pooled, float* __restrict__ out_p, int T)
{
    int t = blockIdx.x;
    if (t >= T) return;
    int s = es[t];
    int o = eo[t];
    int tid = threadIdx.x;
    const __half* row = A2 + (long)t * 1152;
    const float4* a4  = reinterpret_cast<const float4*>(cA);
    const float4* b4  = reinterpret_cast<const float4*>(cB);

    {
        float4 v = bn4(ld_h4(row + 4 * tid), a4[tid], b4[tid]);
        red4(&pooled[(long)s * 512 + tid * 4], v);
    }
    if (tid < 32) {
        int g = 128 + tid;
        float4 v = bn4(ld_h4(row + 4 * g), a4[g], b4[g]);
        *reinterpret_cast<float4*>(out_p + (long)t * 128 + tid * 4) = v;
    }
    {
        int g = 160 + tid;
        float4 v = bn4(ld_h4(row + 4 * g), a4[g], b4[g]);
        red4(&pooled[(long)o * 512 + tid * 4], v);
    }
}

// ======================= launch ================================================
extern "C" void kernel_launch(void* const* d_in, const int* in_sizes, int n_in,
                              void* d_out, int out_size)
{
    const float* obj   = (const float*)d_in[0];
    const float* pred  = (const float*)d_in[1];
    const int*   e32   = (const int*)d_in[2];
    const float* W1a = (const float*)d_in[3];
    const float* b1a = (const float*)d_in[4];
    const float* g1a = (const float*)d_in[5];
    const float* be1a= (const float*)d_in[6];
    const float* W1b = (const float*)d_in[7];
    const float* b1b = (const float*)d_in[8];
    const float* g1b = (const float*)d_in[9];
    const float* be1b= (const float*)d_in[10];
    const float* W2a = (const float*)d_in[11];
    const float* b2a = (const float*)d_in[12];
    const float* g2a = (const float*)d_in[13];
    const float* be2a= (const float*)d_in[14];
    const float* W2b = (const float*)d_in[15];
    const float* b2b = (const float*)d_in[16];
    const float* g2b = (const float*)d_in[17];
    const float* be2b= (const float*)d_in[18];

    const int O = in_sizes[0] / 128;
    const int T = in_sizes[1] / 128;

    float* out     = (float*)d_out;
    float* out_obj = out;
    float* out_p   = out + (size_t)O * 128;

    float *A1, *POOL, *A4, *CNT, *SUM, *SQ, *CA, *CB;
    __half *A2;
    int *ES, *EO, *FLAG;
    __half *WT, *OBJH, *PRH, *XH;
    cudaGetSymbolAddress((void**)&A1,   g_A1);
    cudaGetSymbolAddress((void**)&A2,   g_A2);
    cudaGetSymbolAddress((void**)&POOL, g_pooled);
    cudaGetSymbolAddress((void**)&A4,   g_A4);
    cudaGetSymbolAddress((void**)&CNT,  g_counts);
    cudaGetSymbolAddress((void**)&SUM,  g_sum);
    cudaGetSymbolAddress((void**)&SQ,   g_sq);
    cudaGetSymbolAddress((void**)&CA,   g_cA);
    cudaGetSymbolAddress((void**)&CB,   g_cB);
    cudaGetSymbolAddress((void**)&ES,   g_es);
    cudaGetSymbolAddress((void**)&EO,   g_eo);
    cudaGetSymbolAddress((void**)&FLAG, g_flag32);
    cudaGetSymbolAddress((void**)&WT,   g_wt);
    cudaGetSymbolAddress((void**)&OBJH, g_objh);
    cudaGetSymbolAddress((void**)&PRH,  g_predh);
    cudaGetSymbolAddress((void**)&XH,   g_xh);

    cudaFuncSetAttribute(mma_gemm_k<true,  float>,
                         cudaFuncAttributeMaxDynamicSharedMemorySize, GEMM_SMEM);
    cudaFuncSetAttribute(mma_gemm_k<false, __half>,
                         cudaFuncAttributeMaxDynamicSharedMemorySize, GEMM_SMEM);
    cudaFuncSetAttribute(mma_gemm_k<false, float>,
                         cudaFuncAttributeMaxDynamicSharedMemorySize, GEMM_SMEM);

    const int OFF1 = 0, OFF2 = 512, OFF3 = 1664, OFF4 = 2176;
    const int W1A_OFF = 0, W1B_OFF = 196608, W2A_OFF = 786432, W2B_OFF = 1048576;

    // launches 0-4 (GEMM1 lands at profile slot -s 5)
    zero_k<<<2048, 256>>>(POOL, CNT, SUM, SQ, FLAG, (long)O * 512, O);
    probe_k<<<(T + 255) / 256, 256>>>(e32, FLAG, T);
    convert_k<<<(T + 255) / 256, 256>>>(e32, FLAG, ES, EO, CNT, T);
    prep_w_k<<<(WT_TOTAL + 255) / 256, 256>>>(W1a, W1b, W2a, W2b, WT);
    prep_a_k<<<(unsigned)(((long)(O + T) * 32 + 255) / 256), 256>>>(
        obj, pred, OBJH, PRH, (long)O * 32, (long)T * 32);

    // 1) GEMM1 (gathered): A1 = cur_t @ W1a + b1a  [T,512] fp32  + L1 stats
    mma_gemm_k<true, float><<<dim3(4, (T + 127) / 128), 512, GEMM_SMEM>>>(
        nullptr, OBJH, PRH, ES, EO, WT + W1A_OFF, b1a,
        A1, SUM + OFF1, SQ + OFF1, T, 512, 384);
    finalize_k<<<2, 256>>>(SUM + OFF1, SQ + OFF1, g1a, be1a, 1.f / T, 512, CA + OFF1, CB + OFF1);

    // 2) BN1-apply + lrelu -> XH (fp16)
    bnhalf_k<<<(unsigned)(((long)T * 128 + 255) / 256), 256>>>(
        A1, CA + OFF1, CB + OFF1, XH, (long)T * 128, 512);

    // 3) GEMM2: A2 = X @ W1b + b1b  [T,1152] fp16  + L2 stats
    mma_gemm_k<false, __half><<<dim3(9, (T + 127) / 128), 512, GEMM_SMEM>>>(
        XH, nullptr, nullptr, nullptr, nullptr, WT + W1B_OFF, b1b,
        A2, SUM + OFF2, SQ + OFF2, T, 1152, 512);
    finalize_k<<<5, 256>>>(SUM + OFF2, SQ + OFF2, g1b, be1b, 1.f / T, 1152, CA + OFF2, CB + OFF2);

    // 4) scatter (BN2+lrelu fused, fp16 A2, v4 reductions) -> POOL, out_p
    scatter_k<<<T, 128>>>(A2, CA + OFF2, CB + OFF2, ES, EO, POOL, out_p, T);

    // 5) divide + fp16 -> XH
    divhalf_k<<<(unsigned)(((long)O * 128 + 255) / 256), 256>>>(
        POOL, CNT, XH, (long)O * 128, (float)O);

    // 6) GEMM3: A3(=A1) = X @ W2a + b2a  [O,512] fp32  + L3 stats
    mma_gemm_k<false, float><<<dim3(4, (O + 127) / 128), 512, GEMM_SMEM>>>(
        XH, nullptr, nullptr, nullptr, nullptr, WT + W2A_OFF, b2a,
        A1, SUM + OFF3, SQ + OFF3, O, 512, 512);
    finalize_k<<<2, 256>>>(SUM + OFF3, SQ + OFF3, g2a, be2a, 1.f / O, 512, CA + OFF3, CB + OFF3);

    // 7) BN3-apply + lrelu -> XH
    bnhalf_k<<<(unsigned)(((long)O * 128 + 255) / 256), 256>>>(
        A1, CA + OFF3, CB + OFF3, XH, (long)O * 128, 512);

    // 8) GEMM4: A4 = X @ W2b + b2b  [O,128] fp32  + L4 stats
    mma_gemm_k<false, float><<<dim3(1, (O + 127) / 128), 512, GEMM_SMEM>>>(
        XH, nullptr, nullptr, nullptr, nullptr, WT + W2B_OFF, b2b,
        A4, SUM + OFF4, SQ + OFF4, O, 128, 512);
    finalize_k<<<1, 256>>>(SUM + OFF4, SQ + OFF4, g2b, be2b, 1.f / O, 128, CA + OFF4, CB + OFF4);

    // 9) BN4 apply -> out_obj
    bn_out_k<<<(unsigned)(((long)O * 128 + 255) / 256), 256>>>(
        A4, CA + OFF4, CB + OFF4, out_obj, (long)O * 128, 128);
}

// round 12
// speedup vs baseline: 4.8822x; 1.0319x over previous
#include <cuda_runtime.h>
#include <cuda_fp16.h>
#include <cstdint>

#define EPS    1e-5f
#define ALPHA  0.2f
#define MAX_O  50000
#define MAX_T  200000

// ---------------- scratch (static device globals; no allocation) -------------
__device__ float  g_A1[(size_t)MAX_T * 512];          // pre-BN fp32 (reused for A3)
__device__ __half g_A2[(size_t)MAX_T * 1152];         // pre-BN fp16
__device__ float  g_A4[(size_t)MAX_O * 128];
__device__ int    g_deg[MAX_O];
__device__ int    g_off[MAX_O + 1];
__device__ int    g_cur[MAX_O];
__device__ int    g_elist[2 * MAX_T];
__device__ int    g_es[MAX_T];
__device__ int    g_eo[MAX_T];
__device__ int    g_flag32;
__device__ __half g_objh[(size_t)MAX_O * 128];
__device__ __half g_predh[(size_t)MAX_T * 128];
__device__ __half g_xh[(size_t)MAX_T * 512];
#define WT_TOTAL 1114112
__device__ __half g_wt[WT_TOTAL];
__device__ float g_sum[2304];
__device__ float g_sq[2304];
__device__ float g_cA[2304];
__device__ float g_cB[2304];

// ======================= PTX wrappers =========================================
__device__ __forceinline__ uint32_t smem_to_u32(const void* p) {
    uint32_t a;
    asm("{ .reg .u64 t; cvta.to.shared.u64 t, %1; cvt.u32.u64 %0, t; }" : "=r"(a) : "l"(p));
    return a;
}
__device__ __forceinline__ void ldsm_x4(uint32_t addr, uint32_t* r) {
    asm volatile("ldmatrix.sync.aligned.m8n8.x4.shared.b16 {%0,%1,%2,%3}, [%4];"
        : "=r"(r[0]), "=r"(r[1]), "=r"(r[2]), "=r"(r[3]) : "r"(addr));
}
__device__ __forceinline__ void mma_f16(float* c, const uint32_t* a, const uint32_t* b) {
    asm volatile("mma.sync.aligned.m16n8k16.row.col.f32.f16.f16.f32 "
        "{%0,%1,%2,%3},{%4,%5,%6,%7},{%8,%9},{%0,%1,%2,%3};"
        : "+f"(c[0]), "+f"(c[1]), "+f"(c[2]), "+f"(c[3])
        : "r"(a[0]), "r"(a[1]), "r"(a[2]), "r"(a[3]), "r"(b[0]), "r"(b[1]));
}
__device__ __forceinline__ void cp16(uint32_t dst, const void* src) {
    asm volatile("cp.async.cg.shared.global [%0], [%1], 16;" :: "r"(dst), "l"(src));
}
#define CP_COMMIT() asm volatile("cp.async.commit_group;" ::: "memory")
#define CP_WAIT(n)  asm volatile("cp.async.wait_group %0;" :: "n"(n) : "memory")

__device__ __forceinline__ void store2(float* C, long off, float v0, float v1) {
    *reinterpret_cast<float2*>(C + off) = make_float2(v0, v1);
}
__device__ __forceinline__ void store2(__half* C, long off, float v0, float v1) {
    *reinterpret_cast<__half2*>(C + off) = __floats2half2_rn(v0, v1);
}

__device__ __forceinline__ float4 bn4(float4 v, float4 a, float4 b) {
    v.x = fmaf(v.x, a.x, b.x); v.x = v.x >= 0.f ? v.x : ALPHA * v.x;
    v.y = fmaf(v.y, a.y, b.y); v.y = v.y >= 0.f ? v.y : ALPHA * v.y;
    v.z = fmaf(v.z, a.z, b.z); v.z = v.z >= 0.f ? v.z : ALPHA * v.z;
    v.w = fmaf(v.w, a.w, b.w); v.w = v.w >= 0.f ? v.w : ALPHA * v.w;
    return v;
}
__device__ __forceinline__ float4 ld_h4(const __half* p) {
    uint2 raw = *reinterpret_cast<const uint2*>(p);
    __half2 p0 = *reinterpret_cast<__half2*>(&raw.x);
    __half2 p1 = *reinterpret_cast<__half2*>(&raw.y);
    float2 f0 = __half22float2(p0), f1 = __half22float2(p1);
    return make_float4(f0.x, f0.y, f1.x, f1.y);
}

// ======================= setup kernels =========================================
__global__ void zero_k(int* deg, float* sum, float* sq, int* flag32, int O)
{
    if (blockIdx.x == 0 && threadIdx.x == 0) *flag32 = 0;
    int total = O + 2 * 2304;
    for (int i = blockIdx.x * blockDim.x + threadIdx.x; i < total;
         i += gridDim.x * blockDim.x) {
        if (i < O) deg[i] = 0;
        else {
            int j = i - O;
            if (j < 2304) sum[j] = 0.f; else sq[j - 2304] = 0.f;
        }
    }
}

__global__ void probe_k(const int* __restrict__ e32, int* flag32, int T)
{
    int t = blockIdx.x * blockDim.x + threadIdx.x;
    if (t >= T) return;
    if (e32[2 * t + 1] != 0) atomicOr(flag32, 1);
}

__global__ void convert_k(const int* __restrict__ e32, const int* __restrict__ flag32,
                          int* __restrict__ es, int* __restrict__ eo,
                          int* __restrict__ deg, int T)
{
    int t = blockIdx.x * blockDim.x + threadIdx.x;
    if (t >= T) return;
    int s, o;
    if (*flag32) { s = e32[2 * t]; o = e32[2 * t + 1]; }
    else         { s = e32[4 * t]; o = e32[4 * t + 2]; }
    es[t] = s;
    eo[t] = o;
    atomicAdd(&deg[s], 1);
    atomicAdd(&deg[o], 1);
}

// transpose all 4 weights fp32[K,N] -> fp16[N,K] into packed g_wt
__global__ void prep_w_k(const float* __restrict__ W1a, const float* __restrict__ W1b,
                         const float* __restrict__ W2a, const float* __restrict__ W2b,
                         __half* __restrict__ wt)
{
    int i = blockIdx.x * blockDim.x + threadIdx.x;
    if (i >= WT_TOTAL) return;
    const float* W; int K, N, base;
    if (i < 196608)       { W = W1a; K = 384; N = 512;  base = 0;       }
    else if (i < 786432)  { W = W1b; K = 512; N = 1152; base = 196608;  }
    else if (i < 1048576) { W = W2a; K = 512; N = 512;  base = 786432;  }
    else                  { W = W2b; K = 512; N = 128;  base = 1048576; }
    int j = i - base;
    int k = j / N, n = j % N;
    wt[(long)base + (long)n * K + k] = __float2half(W[(long)k * N + n]);
}

__global__ void prep_a_k(const float* __restrict__ obj, const float* __restrict__ pred,
                         __half* __restrict__ objh, __half* __restrict__ predh,
                         long no4, long np4)
{
    long i = blockIdx.x * (long)blockDim.x + threadIdx.x;
    if (i >= no4 + np4) return;
    const float* src; __half* dst; long e0;
    if (i < no4) { src = obj;  dst = objh;  e0 = i * 4; }
    else         { src = pred; dst = predh; e0 = (i - no4) * 4; }
    float4 v = *reinterpret_cast<const float4*>(src + e0);
    __half2 h01 = __floats2half2_rn(v.x, v.y);
    __half2 h23 = __floats2half2_rn(v.z, v.w);
    *reinterpret_cast<uint2*>(dst + e0) =
        make_uint2(*reinterpret_cast<uint32_t*>(&h01), *reinterpret_cast<uint32_t*>(&h23));
}

// single-block prefix scan of degrees -> offsets + cursors
__global__ void scan_k(const int* __restrict__ deg, int* __restrict__ offs,
                       int* __restrict__ cur, int O)
{
    __shared__ int part[1024];
    int tid = threadIdx.x;
    int chunk = (O + 1023) / 1024;
    int b = tid * chunk, e = b + chunk; if (e > O) e = O; if (b > O) b = O;
    int s = 0;
    for (int i = b; i < e; i++) s += deg[i];
    part[tid] = s;
    __syncthreads();
    for (int off = 1; off < 1024; off <<= 1) {
        int v = (tid >= off) ? part[tid - off] : 0;
        __syncthreads();
        part[tid] += v;
        __syncthreads();
    }
    int base = (tid == 0) ? 0 : part[tid - 1];
    for (int i = b; i < e; i++) {
        offs[i] = base;
        cur[i]  = base;
        base += deg[i];
    }
    if (tid == 0) offs[O] = part[1023];
}

// scatter edge-side codes into CSR list
__global__ void fill_k(const int* __restrict__ es, const int* __restrict__ eo,
                       int* __restrict__ cur, int* __restrict__ elist, int T)
{
    int t = blockIdx.x * blockDim.x + threadIdx.x;
    if (t >= T) return;
    int p = atomicAdd(&cur[es[t]], 1);
    elist[p] = t * 2;
    int q = atomicAdd(&cur[eo[t]], 1);
    elist[q] = t * 2 + 1;
}

// bn-apply + lrelu fp32 -> fp16
__global__ void bnhalf_k(const float* __restrict__ X,
                         const float* __restrict__ cA, const float* __restrict__ cB,
                         __half* __restrict__ h, long n4, int N)
{
    long i = blockIdx.x * (long)blockDim.x + threadIdx.x;
    if (i >= n4) return;
    long e0 = i * 4;
    int c = (int)(e0 & (N - 1));
    float4 v = *reinterpret_cast<const float4*>(X + e0);
    float4 a = *reinterpret_cast<const float4*>(cA + c);
    float4 b = *reinterpret_cast<const float4*>(cB + c);
    v = bn4(v, a, b);
    __half2 h01 = __floats2half2_rn(v.x, v.y);
    __half2 h23 = __floats2half2_rn(v.z, v.w);
    *reinterpret_cast<uint2*>(h + e0) =
        make_uint2(*reinterpret_cast<uint32_t*>(&h01), *reinterpret_cast<uint32_t*>(&h23));
}

// ======================= pipelined mma.sync GEMM ===============================
#define ROWB   144
#define STAGE  (2 * 128 * ROWB)          // 36864 B: A, B
#define NSTG   3
#define GEMM_SMEM (NSTG * STAGE)         // 110592 B

template<bool GATHER, typename TOUT>
__global__ void __launch_bounds__(512, 1)
mma_gemm_k(const __half* __restrict__ Ax,
           const __half* __restrict__ objh, const __half* __restrict__ predh,
           const int* __restrict__ es, const int* __restrict__ eo,
           const __half* __restrict__ Bt,
           const float* __restrict__ bias,
           TOUT* __restrict__ C, float* __restrict__ gsum, float* __restrict__ gsq,
           int M, int N, int K)
{
    extern __shared__ __align__(16) char smem[];
    const uint32_t sbase = smem_to_u32(smem);

    const int tid  = threadIdx.x;
    const int lane = tid & 31;
    const int wid  = tid >> 5;
    const int wm   = wid >> 2;
    const int wn   = wid & 3;
    const int m0   = blockIdx.y * 128, n0 = blockIdx.x * 128;
    const int q8   = lane >> 3;
    const int r8   = lane & 7;

    float acc[2][4][4];
#pragma unroll
    for (int i = 0; i < 2; i++)
#pragma unroll
        for (int j = 0; j < 4; j++)
#pragma unroll
            for (int q = 0; q < 4; q++) acc[i][j][q] = 0.f;

    const int nk = K >> 6;

    auto load_chunk = [&](int k0, int stage) {
        const uint32_t aA = sbase + stage * STAGE;
        const uint32_t aB = aA + 128 * ROWB;
#pragma unroll
        for (int i = 0; i < 2; i++) {
            int idx = tid + (i << 9);
            int r   = (idx >> 3) & 127;
            int c   = idx & 7;
            int gm  = m0 + r;
            int gmc = gm < M ? gm : M - 1;
            const __half* src;
            if (GATHER) {
                long sr; const __half* sh;
                if (k0 < 128)      { sr = (long)es[gmc]; sh = objh;  }
                else if (k0 < 256) { sr = gmc;           sh = predh; }
                else               { sr = (long)eo[gmc]; sh = objh;  }
                src = sh + sr * 128 + (k0 & 127) + c * 8;
            } else {
                src = Ax + (long)gmc * K + k0 + c * 8;
            }
            cp16(aA + r * ROWB + c * 16, src);
        }
#pragma unroll
        for (int i = 0; i < 2; i++) {
            int idx = tid + (i << 9);
            int r   = (idx >> 3) & 127;
            int c   = idx & 7;
            const __half* src = Bt + (long)(n0 + r) * K + k0 + c * 8;
            cp16(aB + r * ROWB + c * 16, src);
        }
        CP_COMMIT();
    };

    auto compute = [&](int stage) {
        const uint32_t aA = sbase + stage * STAGE;
        const uint32_t aB = aA + 128 * ROWB;
#pragma unroll
        for (int s = 0; s < 4; s++) {
            uint32_t bh[4][2], ah[2][4];
#pragma unroll
            for (int j = 0; j < 2; j++) {
                int nrow = wn * 32 + j * 16 + (q8 >> 1) * 8 + r8;
                int kb   = s * 32 + (q8 & 1) * 16;
                uint32_t addr = (uint32_t)(nrow * ROWB + kb);
                uint32_t r[4];
                ldsm_x4(aB + addr, r);
                bh[2 * j][0] = r[0]; bh[2 * j][1] = r[1];
                bh[2 * j + 1][0] = r[2]; bh[2 * j + 1][1] = r[3];
            }
#pragma unroll
            for (int mt = 0; mt < 2; mt++) {
                int mrow = wm * 32 + mt * 16 + (q8 & 1) * 8 + r8;
                int kb   = s * 32 + (q8 >> 1) * 16;
                ldsm_x4(aA + (uint32_t)(mrow * ROWB + kb), ah[mt]);
            }
#pragma unroll
            for (int mt = 0; mt < 2; mt++)
#pragma unroll
                for (int nt = 0; nt < 4; nt++)
                    mma_f16(acc[mt][nt], ah[mt], bh[nt]);
        }
    };

    load_chunk(0, 0);
    if (nk > 1) load_chunk(64, 1);
    for (int it = 0; it < nk; it++) {
        if (it == nk - 1) { CP_WAIT(0); } else { CP_WAIT(1); }
        __syncthreads();
        compute(it % NSTG);
        if (it + 2 < nk) load_chunk((it + 2) << 6, (it + 2) % NSTG);
    }

#pragma unroll
    for (int nt = 0; nt < 4; nt++) {
        int col = n0 + wn * 32 + nt * 8 + (lane & 3) * 2;
        float2 bv = *reinterpret_cast<const float2*>(bias + col);
        float s0 = 0.f, s1 = 0.f, q0 = 0.f, q1 = 0.f;
#pragma unroll
        for (int mt = 0; mt < 2; mt++) {
            int row0 = m0 + wm * 32 + mt * 16 + (lane >> 2);
            int row1 = row0 + 8;
            float v0 = acc[mt][nt][0] + bv.x;
            float v1 = acc[mt][nt][1] + bv.y;
            float v2 = acc[mt][nt][2] + bv.x;
            float v3 = acc[mt][nt][3] + bv.y;
            if (row0 < M) {
                store2(C, (long)row0 * N + col, v0, v1);
                s0 += v0; q0 += v0 * v0; s1 += v1; q1 += v1 * v1;
            }
            if (row1 < M) {
                store2(C, (long)row1 * N + col, v2, v3);
                s0 += v2; q0 += v2 * v2; s1 += v3; q1 += v3 * v3;
            }
        }
#pragma unroll
        for (int off = 4; off < 32; off <<= 1) {
            s0 += __shfl_down_sync(0xffffffffu, s0, off);
            s1 += __shfl_down_sync(0xffffffffu, s1, off);
            q0 += __shfl_down_sync(0xffffffffu, q0, off);
            q1 += __shfl_down_sync(0xffffffffu, q1, off);
        }
        if (lane < 4) {
            atomicAdd(&gsum[col],     s0);
            atomicAdd(&gsum[col + 1], s1);
            atomicAdd(&gsq[col],      q0);
            atomicAdd(&gsq[col + 1],  q1);
        }
    }
}

// ======================= stats finalize / BN out ==============================
__global__ void finalize_k(const float* __restrict__ sum, const float* __restrict__ sq,
                           const float* __restrict__ gamma, const float* __restrict__ beta,
                           float invM, int N,
                           float* __restrict__ cA, float* __restrict__ cB)
{
    int n = blockIdx.x * blockDim.x + threadIdx.x;
    if (n >= N) return;
    float mean = sum[n] * invM;
    float var  = sq[n] * invM - mean * mean;
    float inv  = rsqrtf(var + EPS);
    float a    = inv * gamma[n];
    cA[n] = a;
    cB[n] = beta[n] - mean * a;
}

__global__ void bn_out_k(const float* __restrict__ X, const float* __restrict__ cA,
                         const float* __restrict__ cB, float* __restrict__ out,
                         long total, int N)
{
    long i = blockIdx.x * (long)blockDim.x + threadIdx.x;
    if (i >= total) return;
    int n = (int)(i % N);
    float v = X[i] * cA[n] + cB[n];
    out[i] = (v >= 0.f) ? v : ALPHA * v;
}

// ======================= CSR pooling (no float atomics) =======================
// one block (128 thr) per object: accumulate BN2+lrelu rows of incident edges,
// divide by clamped degree, write XH fp16 directly.
__global__ void pool_k(const __half* __restrict__ A2,
                       const float* __restrict__ cA, const float* __restrict__ cB,
                       const int* __restrict__ offs, const int* __restrict__ elist,
                       __half* __restrict__ xh, int O, float ocap)
{
    int b = blockIdx.x;
    if (b >= O) return;
    int tid = threadIdx.x;                       // 0..127
    int d0 = offs[b], d1 = offs[b + 1];
    float4 acc = make_float4(0.f, 0.f, 0.f, 0.f);
    for (int e = d0; e < d1; e++) {
        int code = elist[e];
        int t = code >> 1;
        int cb = (code & 1) ? 640 : 0;
        int c  = cb + tid * 4;
        float4 a = *reinterpret_cast<const float4*>(cA + c);
        float4 bb = *reinterpret_cast<const float4*>(cB + c);
        float4 v = bn4(ld_h4(A2 + (long)t * 1152 + c), a, bb);
        acc.x += v.x; acc.y += v.y; acc.z += v.z; acc.w += v.w;
    }
    float c = fminf(fmaxf((float)(d1 - d0), 1.f), ocap);
    float r = 1.f / c;
    __half2 h01 = __floats2half2_rn(acc.x * r, acc.y * r);
    __half2 h23 = __floats2half2_rn(acc.z * r, acc.w * r);
    *reinterpret_cast<uint2*>(xh + (long)b * 512 + tid * 4) =
        make_uint2(*reinterpret_cast<uint32_t*>(&h01), *reinterpret_cast<uint32_t*>(&h23));
}

// middle 128 cols of A2 (BN2+lrelu) -> out_p; 32 threads per edge
__global__ void outp_k(const __half* __restrict__ A2,
                       const float* __restrict__ cA, const float* __restrict__ cB,
                       float* __restrict__ out_p, int T)
{
    int idx = blockIdx.x * blockDim.x + threadIdx.x;
    int t = idx >> 5, lane = idx & 31;
    if (t >= T) return;
    int c = 512 + lane * 4;
    float4 a = *reinterpret_cast<const float4*>(cA + c);
    float4 bb = *reinterpret_cast<const float4*>(cB + c);
    float4 v = bn4(ld_h4(A2 + (long)t * 1152 + c), a, bb);
    *reinterpret_cast<float4*>(out_p + (long)t * 128 + lane * 4) = v;
}

// ======================= launch ================================================
extern "C" void kernel_launch(void* const* d_in, const int* in_sizes, int n_in,
                              void* d_out, int out_size)
{
    const float* obj   = (const float*)d_in[0];
    const float* pred  = (const float*)d_in[1];
    const int*   e32   = (const int*)d_in[2];
    const float* W1a = (const float*)d_in[3];
    const float* b1a = (const float*)d_in[4];
    const float* g1a = (const float*)d_in[5];
    const float* be1a= (const float*)d_in[6];
    const float* W1b = (const float*)d_in[7];
    const float* b1b = (const float*)d_in[8];
    const float* g1b = (const float*)d_in[9];
    const float* be1b= (const float*)d_in[10];
    const float* W2a = (const float*)d_in[11];
    const float* b2a = (const float*)d_in[12];
    const float* g2a = (const float*)d_in[13];
    const float* be2a= (const float*)d_in[14];
    const float* W2b = (const float*)d_in[15];
    const float* b2b = (const float*)d_in[16];
    const float* g2b = (const float*)d_in[17];
    const float* be2b= (const float*)d_in[18];

    const int O = in_sizes[0] / 128;
    const int T = in_sizes[1] / 128;

    float* out     = (float*)d_out;
    float* out_obj = out;
    float* out_p   = out + (size_t)O * 128;

    float *A1, *A4, *SUM, *SQ, *CA, *CB;
    __half *A2;
    int *ES, *EO, *FLAG, *DEG, *OFFS, *CUR, *ELIST;
    __half *WT, *OBJH, *PRH, *XH;
    cudaGetSymbolAddress((void**)&A1,    g_A1);
    cudaGetSymbolAddress((void**)&A2,    g_A2);
    cudaGetSymbolAddress((void**)&A4,    g_A4);
    cudaGetSymbolAddress((void**)&SUM,   g_sum);
    cudaGetSymbolAddress((void**)&SQ,    g_sq);
    cudaGetSymbolAddress((void**)&CA,    g_cA);
    cudaGetSymbolAddress((void**)&CB,    g_cB);
    cudaGetSymbolAddress((void**)&ES,    g_es);
    cudaGetSymbolAddress((void**)&EO,    g_eo);
    cudaGetSymbolAddress((void**)&FLAG,  g_flag32);
    cudaGetSymbolAddress((void**)&DEG,   g_deg);
    cudaGetSymbolAddress((void**)&OFFS,  g_off);
    cudaGetSymbolAddress((void**)&CUR,   g_cur);
    cudaGetSymbolAddress((void**)&ELIST, g_elist);
    cudaGetSymbolAddress((void**)&WT,    g_wt);
    cudaGetSymbolAddress((void**)&OBJH,  g_objh);
    cudaGetSymbolAddress((void**)&PRH,   g_predh);
    cudaGetSymbolAddress((void**)&XH,    g_xh);

    cudaFuncSetAttribute(mma_gemm_k<true,  float>,
                         cudaFuncAttributeMaxDynamicSharedMemorySize, GEMM_SMEM);
    cudaFuncSetAttribute(mma_gemm_k<false, __half>,
                         cudaFuncAttributeMaxDynamicSharedMemorySize, GEMM_SMEM);
    cudaFuncSetAttribute(mma_gemm_k<false, float>,
                         cudaFuncAttributeMaxDynamicSharedMemorySize, GEMM_SMEM);

    const int OFF1 = 0, OFF2 = 512, OFF3 = 1664, OFF4 = 2176;
    const int W1A_OFF = 0, W1B_OFF = 196608, W2A_OFF = 786432, W2B_OFF = 1048576;

    // launches 0-4 (GEMM1 profiled at -s 5)
    zero_k<<<128, 256>>>(DEG, SUM, SQ, FLAG, O);
    probe_k<<<(T + 255) / 256, 256>>>(e32, FLAG, T);
    convert_k<<<(T + 255) / 256, 256>>>(e32, FLAG, ES, EO, DEG, T);
    prep_w_k<<<(WT_TOTAL + 255) / 256, 256>>>(W1a, W1b, W2a, W2b, WT);
    prep_a_k<<<(unsigned)(((long)(O + T) * 32 + 255) / 256), 256>>>(
        obj, pred, OBJH, PRH, (long)O * 32, (long)T * 32);

    // 1) GEMM1 (gathered): A1 = cur_t @ W1a + b1a  [T,512] fp32 + L1 stats
    mma_gemm_k<true, float><<<dim3(4, (T + 127) / 128), 512, GEMM_SMEM>>>(
        nullptr, OBJH, PRH, ES, EO, WT + W1A_OFF, b1a,
        A1, SUM + OFF1, SQ + OFF1, T, 512, 384);
    finalize_k<<<2, 256>>>(SUM + OFF1, SQ + OFF1, g1a, be1a, 1.f / T, 512, CA + OFF1, CB + OFF1);

    // 2) BN1-apply + lrelu -> XH; build CSR in parallel slots
    bnhalf_k<<<(unsigned)(((long)T * 128 + 255) / 256), 256>>>(
        A1, CA + OFF1, CB + OFF1, XH, (long)T * 128, 512);
    scan_k<<<1, 1024>>>(DEG, OFFS, CUR, O);
    fill_k<<<(T + 255) / 256, 256>>>(ES, EO, CUR, ELIST, T);

    // 3) GEMM2: A2 = X @ W1b + b1b  [T,1152] fp16 + L2 stats
    mma_gemm_k<false, __half><<<dim3(9, (T + 127) / 128), 512, GEMM_SMEM>>>(
        XH, nullptr, nullptr, nullptr, nullptr, WT + W1B_OFF, b1b,
        A2, SUM + OFF2, SQ + OFF2, T, 1152, 512);
    finalize_k<<<5, 256>>>(SUM + OFF2, SQ + OFF2, g1b, be1b, 1.f / T, 1152, CA + OFF2, CB + OFF2);

    // 4) CSR pooling (BN2+lrelu+mean fused) -> XH ; out_p slice
    pool_k<<<O, 128>>>(A2, CA + OFF2, CB + OFF2, OFFS, ELIST, XH, O, (float)O);
    outp_k<<<(T * 32 + 255) / 256, 256>>>(A2, CA + OFF2, CB + OFF2, out_p, T);

    // 5) GEMM3: A3(=A1) = X @ W2a + b2a  [O,512] fp32 + L3 stats
    mma_gemm_k<false, float><<<dim3(4, (O + 127) / 128), 512, GEMM_SMEM>>>(
        XH, nullptr, nullptr, nullptr, nullptr, WT + W2A_OFF, b2a,
        A1, SUM + OFF3, SQ + OFF3, O, 512, 512);
    finalize_k<<<2, 256>>>(SUM + OFF3, SQ + OFF3, g2a, be2a, 1.f / O, 512, CA + OFF3, CB + OFF3);

    // 6) BN3-apply + lrelu -> XH
    bnhalf_k<<<(unsigned)(((long)O * 128 + 255) / 256), 256>>>(
        A1, CA + OFF3, CB + OFF3, XH, (long)O * 128, 512);

    // 7) GEMM4: A4 = X @ W2b + b2b  [O,128] fp32 + L4 stats
    mma_gemm_k<false, float><<<dim3(1, (O + 127) / 128), 512, GEMM_SMEM>>>(
        XH, nullptr, nullptr, nullptr, nullptr, WT + W2B_OFF, b2b,
        A4, SUM + OFF4, SQ + OFF4, O, 128, 512);
    finalize_k<<<1, 256>>>(SUM + OFF4, SQ + OFF4, g2b, be2b, 1.f / O, 128, CA + OFF4, CB + OFF4);

    // 8) BN4 apply -> out_obj
    bn_out_k<<<(unsigned)(((long)O * 128 + 255) / 256), 256>>>(
        A4, CA + OFF4, CB + OFF4, out_obj, (long)O * 128, 128);
}

// round 15
// speedup vs baseline: 4.8925x; 1.0021x over previous
#include <cuda_runtime.h>
#include <cuda_fp16.h>
#include <cstdint>

#define EPS    1e-5f
#define ALPHA  0.2f
#define MAX_O  50000
#define MAX_T  200000

// ---------------- scratch (static device globals; no allocation) -------------
__device__ float  g_A1[(size_t)MAX_T * 512];          // pre-BN fp32 (reused for A3)
__device__ __half g_A2[(size_t)MAX_T * 1152];         // pre-BN fp16
__device__ float  g_A4[(size_t)MAX_O * 128];
__device__ int    g_deg[MAX_O];
__device__ int    g_off[MAX_O + 1];
__device__ int    g_cur[MAX_O];
__device__ int    g_elist[2 * MAX_T];
__device__ int    g_es[MAX_T];
__device__ int    g_eo[MAX_T];
__device__ int    g_flag32;
__device__ __half g_objh[(size_t)MAX_O * 128];
__device__ __half g_predh[(size_t)MAX_T * 128];
__device__ __half g_xh[(size_t)MAX_T * 512];
#define WT_TOTAL 1114112
__device__ __half g_wt[WT_TOTAL];
__device__ float g_sum[2304];
__device__ float g_sq[2304];
__device__ float g_cA[2304];
__device__ float g_cB[2304];

// ======================= PTX wrappers =========================================
__device__ __forceinline__ uint32_t smem_to_u32(const void* p) {
    uint32_t a;
    asm("{ .reg .u64 t; cvta.to.shared.u64 t, %1; cvt.u32.u64 %0, t; }" : "=r"(a) : "l"(p));
    return a;
}
__device__ __forceinline__ void ldsm_x4(uint32_t addr, uint32_t* r) {
    asm volatile("ldmatrix.sync.aligned.m8n8.x4.shared.b16 {%0,%1,%2,%3}, [%4];"
        : "=r"(r[0]), "=r"(r[1]), "=r"(r[2]), "=r"(r[3]) : "r"(addr));
}
__device__ __forceinline__ void mma_f16(float* c, const uint32_t* a, const uint32_t* b) {
    asm volatile("mma.sync.aligned.m16n8k16.row.col.f32.f16.f16.f32 "
        "{%0,%1,%2,%3},{%4,%5,%6,%7},{%8,%9},{%0,%1,%2,%3};"
        : "+f"(c[0]), "+f"(c[1]), "+f"(c[2]), "+f"(c[3])
        : "r"(a[0]), "r"(a[1]), "r"(a[2]), "r"(a[3]), "r"(b[0]), "r"(b[1]));
}
__device__ __forceinline__ void cp16(uint32_t dst, const void* src) {
    asm volatile("cp.async.cg.shared.global [%0], [%1], 16;" :: "r"(dst), "l"(src));
}
#define CP_COMMIT() asm volatile("cp.async.commit_group;" ::: "memory")
#define CP_WAIT(n)  asm volatile("cp.async.wait_group %0;" :: "n"(n) : "memory")

__device__ __forceinline__ void store2(float* C, long off, float v0, float v1) {
    *reinterpret_cast<float2*>(C + off) = make_float2(v0, v1);
}
__device__ __forceinline__ void store2(__half* C, long off, float v0, float v1) {
    *reinterpret_cast<__half2*>(C + off) = __floats2half2_rn(v0, v1);
}

__device__ __forceinline__ float4 bn4(float4 v, float4 a, float4 b) {
    v.x = fmaf(v.x, a.x, b.x); v.x = v.x >= 0.f ? v.x : ALPHA * v.x;
    v.y = fmaf(v.y, a.y, b.y); v.y = v.y >= 0.f ? v.y : ALPHA * v.y;
    v.z = fmaf(v.z, a.z, b.z); v.z = v.z >= 0.f ? v.z : ALPHA * v.z;
    v.w = fmaf(v.w, a.w, b.w); v.w = v.w >= 0.f ? v.w : ALPHA * v.w;
    return v;
}
__device__ __forceinline__ float4 ld_h4(const __half* p) {
    uint2 raw = *reinterpret_cast<const uint2*>(p);
    __half2 p0 = *reinterpret_cast<__half2*>(&raw.x);
    __half2 p1 = *reinterpret_cast<__half2*>(&raw.y);
    float2 f0 = __half22float2(p0), f1 = __half22float2(p1);
    return make_float4(f0.x, f0.y, f1.x, f1.y);
}

// ======================= setup kernels =========================================
// launch 0: zero deg/stats/flag + weight transpose->fp16 + obj/pred->fp16.
// All writes, all disjoint buffers, flag read by NO thread here -> race-free.
__global__ void zero_prep_k(int* deg, float* sum, float* sq, int* flag32,
                            const float* __restrict__ W1a, const float* __restrict__ W1b,
                            const float* __restrict__ W2a, const float* __restrict__ W2b,
                            __half* __restrict__ wt,
                            const float* __restrict__ obj, const float* __restrict__ pred,
                            __half* __restrict__ objh, __half* __restrict__ predh,
                            int O, long no4, long np4)
{
    long i = blockIdx.x * (long)blockDim.x + threadIdx.x;
    if (i == 0) *flag32 = 0;
    if (i < O) { deg[i] = 0; return; }
    i -= O;
    if (i < 4608) {
        if (i < 2304) sum[i] = 0.f; else sq[i - 2304] = 0.f;
        return;
    }
    i -= 4608;
    if (i < WT_TOTAL) {
        const float* W; int K, N; long base;
        if (i < 196608)       { W = W1a; K = 384; N = 512;  base = 0;       }
        else if (i < 786432)  { W = W1b; K = 512; N = 1152; base = 196608;  }
        else if (i < 1048576) { W = W2a; K = 512; N = 512;  base = 786432;  }
        else                  { W = W2b; K = 512; N = 128;  base = 1048576; }
        int j = (int)(i - base);
        int k = j / N, n = j % N;
        wt[base + (long)n * K + k] = __float2half(W[(long)k * N + n]);
        return;
    }
    i -= WT_TOTAL;
    if (i >= no4 + np4) return;
    const float* src; __half* dst; long e0;
    if (i < no4) { src = obj;  dst = objh;  e0 = i * 4; }
    else         { src = pred; dst = predh; e0 = (i - no4) * 4; }
    float4 v = *reinterpret_cast<const float4*>(src + e0);
    __half2 h01 = __floats2half2_rn(v.x, v.y);
    __half2 h23 = __floats2half2_rn(v.z, v.w);
    *reinterpret_cast<uint2*>(dst + e0) =
        make_uint2(*reinterpret_cast<uint32_t*>(&h01), *reinterpret_cast<uint32_t*>(&h23));
}

// launch 1
__global__ void probe_k(const int* __restrict__ e32, int* flag32, int T)
{
    int t = blockIdx.x * blockDim.x + threadIdx.x;
    if (t >= T) return;
    if (e32[2 * t + 1] != 0) atomicOr(flag32, 1);
}

// launch 2
__global__ void convert_k(const int* __restrict__ e32, const int* __restrict__ flag32,
                          int* __restrict__ es, int* __restrict__ eo,
                          int* __restrict__ deg, int T)
{
    int t = blockIdx.x * blockDim.x + threadIdx.x;
    if (t >= T) return;
    int s, o;
    if (*flag32) { s = e32[2 * t]; o = e32[2 * t + 1]; }
    else         { s = e32[4 * t]; o = e32[4 * t + 2]; }
    es[t] = s;
    eo[t] = o;
    atomicAdd(&deg[s], 1);
    atomicAdd(&deg[o], 1);
}

// single-block prefix scan of degrees -> offsets + cursors
__global__ void scan_k(const int* __restrict__ deg, int* __restrict__ offs,
                       int* __restrict__ cur, int O)
{
    __shared__ int part[1024];
    int tid = threadIdx.x;
    int chunk = (O + 1023) / 1024;
    int b = tid * chunk, e = b + chunk; if (e > O) e = O; if (b > O) b = O;
    int s = 0;
    for (int i = b; i < e; i++) s += deg[i];
    part[tid] = s;
    __syncthreads();
    for (int off = 1; off < 1024; off <<= 1) {
        int v = (tid >= off) ? part[tid - off] : 0;
        __syncthreads();
        part[tid] += v;
        __syncthreads();
    }
    int base = (tid == 0) ? 0 : part[tid - 1];
    for (int i = b; i < e; i++) {
        offs[i] = base;
        cur[i]  = base;
        base += deg[i];
    }
    if (tid == 0) offs[O] = part[1023];
}

__global__ void fill_k(const int* __restrict__ es, const int* __restrict__ eo,
                       int* __restrict__ cur, int* __restrict__ elist, int T)
{
    int t = blockIdx.x * blockDim.x + threadIdx.x;
    if (t >= T) return;
    int p = atomicAdd(&cur[es[t]], 1);
    elist[p] = t * 2;
    int q = atomicAdd(&cur[eo[t]], 1);
    elist[q] = t * 2 + 1;
}

__global__ void bnhalf_k(const float* __restrict__ X,
                         const float* __restrict__ cA, const float* __restrict__ cB,
                         __half* __restrict__ h, long n4, int N)
{
    long i = blockIdx.x * (long)blockDim.x + threadIdx.x;
    if (i >= n4) return;
    long e0 = i * 4;
    int c = (int)(e0 & (N - 1));
    float4 v = *reinterpret_cast<const float4*>(X + e0);
    float4 a = *reinterpret_cast<const float4*>(cA + c);
    float4 b = *reinterpret_cast<const float4*>(cB + c);
    v = bn4(v, a, b);
    __half2 h01 = __floats2half2_rn(v.x, v.y);
    __half2 h23 = __floats2half2_rn(v.z, v.w);
    *reinterpret_cast<uint2*>(h + e0) =
        make_uint2(*reinterpret_cast<uint32_t*>(&h01), *reinterpret_cast<uint32_t*>(&h23));
}

// ======================= pipelined mma.sync GEMM (R12 verbatim) ================
#define ROWB   144
#define STAGE  (2 * 128 * ROWB)          // 36864 B: A, B
#define NSTG   3
#define GEMM_SMEM (NSTG * STAGE)         // 110592 B

template<bool GATHER, typename TOUT>
__global__ void __launch_bounds__(512, 1)
mma_gemm_k(const __half* __restrict__ Ax,
           const __half* __restrict__ objh, const __half* __restrict__ predh,
           const int* __restrict__ es, const int* __restrict__ eo,
           const __half* __restrict__ Bt,
           const float* __restrict__ bias,
           TOUT* __restrict__ C, float* __restrict__ gsum, float* __restrict__ gsq,
           int M, int N, int K)
{
    extern __shared__ __align__(16) char smem[];
    const uint32_t sbase = smem_to_u32(smem);

    const int tid  = threadIdx.x;
    const int lane = tid & 31;
    const int wid  = tid >> 5;
    const int wm   = wid >> 2;
    const int wn   = wid & 3;
    const int m0   = blockIdx.y * 128, n0 = blockIdx.x * 128;
    const int q8   = lane >> 3;
    const int r8   = lane & 7;

    float acc[2][4][4];
#pragma unroll
    for (int i = 0; i < 2; i++)
#pragma unroll
        for (int j = 0; j < 4; j++)
#pragma unroll
            for (int q = 0; q < 4; q++) acc[i][j][q] = 0.f;

    const int nk = K >> 6;

    auto load_chunk = [&](int k0, int stage) {
        const uint32_t aA = sbase + stage * STAGE;
        const uint32_t aB = aA + 128 * ROWB;
#pragma unroll
        for (int i = 0; i < 2; i++) {
            int idx = tid + (i << 9);
            int r   = (idx >> 3) & 127;
            int c   = idx & 7;
            int gm  = m0 + r;
            int gmc = gm < M ? gm : M - 1;
            const __half* src;
            if (GATHER) {
                long sr; const __half* sh;
                if (k0 < 128)      { sr = (long)es[gmc]; sh = objh;  }
                else if (k0 < 256) { sr = gmc;           sh = predh; }
                else               { sr = (long)eo[gmc]; sh = objh;  }
                src = sh + sr * 128 + (k0 & 127) + c * 8;
            } else {
                src = Ax + (long)gmc * K + k0 + c * 8;
            }
            cp16(aA + r * ROWB + c * 16, src);
        }
#pragma unroll
        for (int i = 0; i < 2; i++) {
            int idx = tid + (i << 9);
            int r   = (idx >> 3) & 127;
            int c   = idx & 7;
            const __half* src = Bt + (long)(n0 + r) * K + k0 + c * 8;
            cp16(aB + r * ROWB + c * 16, src);
        }
        CP_COMMIT();
    };

    auto compute = [&](int stage) {
        const uint32_t aA = sbase + stage * STAGE;
        const uint32_t aB = aA + 128 * ROWB;
#pragma unroll
        for (int s = 0; s < 4; s++) {
            uint32_t bh[4][2], ah[2][4];
#pragma unroll
            for (int j = 0; j < 2; j++) {
                int nrow = wn * 32 + j * 16 + (q8 >> 1) * 8 + r8;
                int kb   = s * 32 + (q8 & 1) * 16;
                uint32_t addr = (uint32_t)(nrow * ROWB + kb);
                uint32_t r[4];
                ldsm_x4(aB + addr, r);
                bh[2 * j][0] = r[0]; bh[2 * j][1] = r[1];
                bh[2 * j + 1][0] = r[2]; bh[2 * j + 1][1] = r[3];
            }
#pragma unroll
            for (int mt = 0; mt < 2; mt++) {
                int mrow = wm * 32 + mt * 16 + (q8 & 1) * 8 + r8;
                int kb   = s * 32 + (q8 >> 1) * 16;
                ldsm_x4(aA + (uint32_t)(mrow * ROWB + kb), ah[mt]);
            }
#pragma unroll
            for (int mt = 0; mt < 2; mt++)
#pragma unroll
                for (int nt = 0; nt < 4; nt++)
                    mma_f16(acc[mt][nt], ah[mt], bh[nt]);
        }
    };

    load_chunk(0, 0);
    if (nk > 1) load_chunk(64, 1);
    for (int it = 0; it < nk; it++) {
        if (it == nk - 1) { CP_WAIT(0); } else { CP_WAIT(1); }
        __syncthreads();
        compute(it % NSTG);
        if (it + 2 < nk) load_chunk((it + 2) << 6, (it + 2) % NSTG);
    }

    // ---- epilogue: +bias, store, fused column stats (R12 verbatim) ----
#pragma unroll
    for (int nt = 0; nt < 4; nt++) {
        int col = n0 + wn * 32 + nt * 8 + (lane & 3) * 2;
        float2 bv = *reinterpret_cast<const float2*>(bias + col);
        float s0 = 0.f, s1 = 0.f, q0 = 0.f, q1 = 0.f;
#pragma unroll
        for (int mt = 0; mt < 2; mt++) {
            int row0 = m0 + wm * 32 + mt * 16 + (lane >> 2);
            int row1 = row0 + 8;
            float v0 = acc[mt][nt][0] + bv.x;
            float v1 = acc[mt][nt][1] + bv.y;
            float v2 = acc[mt][nt][2] + bv.x;
            float v3 = acc[mt][nt][3] + bv.y;
            if (row0 < M) {
                store2(C, (long)row0 * N + col, v0, v1);
                s0 += v0; q0 += v0 * v0; s1 += v1; q1 += v1 * v1;
            }
            if (row1 < M) {
                store2(C, (long)row1 * N + col, v2, v3);
                s0 += v2; q0 += v2 * v2; s1 += v3; q1 += v3 * v3;
            }
        }
#pragma unroll
        for (int off = 4; off < 32; off <<= 1) {
            s0 += __shfl_down_sync(0xffffffffu, s0, off);
            s1 += __shfl_down_sync(0xffffffffu, s1, off);
            q0 += __shfl_down_sync(0xffffffffu, q0, off);
            q1 += __shfl_down_sync(0xffffffffu, q1, off);
        }
        if (lane < 4) {
            atomicAdd(&gsum[col],     s0);
            atomicAdd(&gsum[col + 1], s1);
            atomicAdd(&gsq[col],      q0);
            atomicAdd(&gsq[col + 1],  q1);
        }
    }
}

// ======================= stats finalize / BN out ==============================
__global__ void finalize_k(const float* __restrict__ sum, const float* __restrict__ sq,
                           const float* __restrict__ gamma, const float* __restrict__ beta,
                           float invM, int N,
                           float* __restrict__ cA, float* __restrict__ cB)
{
    int n = blockIdx.x * blockDim.x + threadIdx.x;
    if (n >= N) return;
    float mean = sum[n] * invM;
    float var  = sq[n] * invM - mean * mean;
    float inv  = rsqrtf(var + EPS);
    float a    = inv * gamma[n];
    cA[n] = a;
    cB[n] = beta[n] - mean * a;
}

__global__ void bn_out_k(const float* __restrict__ X, const float* __restrict__ cA,
                         const float* __restrict__ cB, float* __restrict__ out,
                         long total, int N)
{
    long i = blockIdx.x * (long)blockDim.x + threadIdx.x;
    if (i >= total) return;
    int n = (int)(i % N);
    float v = X[i] * cA[n] + cB[n];
    out[i] = (v >= 0.f) ? v : ALPHA * v;
}

// ======================= CSR pooling ==========================================
__global__ void pool_k(const __half* __restrict__ A2,
                       const float* __restrict__ cA, const float* __restrict__ cB,
                       const int* __restrict__ offs, const int* __restrict__ elist,
                       __half* __restrict__ xh, int O, float ocap)
{
    int b = blockIdx.x;
    if (b >= O) return;
    int tid = threadIdx.x;
    int d0 = offs[b], d1 = offs[b + 1];
    float4 acc = make_float4(0.f, 0.f, 0.f, 0.f);
    for (int e = d0; e < d1; e++) {
        int code = elist[e];
        int t = code >> 1;
        int cb = (code & 1) ? 640 : 0;
        int c  = cb + tid * 4;
        float4 a = *reinterpret_cast<const float4*>(cA + c);
        float4 bb = *reinterpret_cast<const float4*>(cB + c);
        float4 v = bn4(ld_h4(A2 + (long)t * 1152 + c), a, bb);
        acc.x += v.x; acc.y += v.y; acc.z += v.z; acc.w += v.w;
    }
    float c = fminf(fmaxf((float)(d1 - d0), 1.f), ocap);
    float r = 1.f / c;
    __half2 h01 = __floats2half2_rn(acc.x * r, acc.y * r);
    __half2 h23 = __floats2half2_rn(acc.z * r, acc.w * r);
    *reinterpret_cast<uint2*>(xh + (long)b * 512 + tid * 4) =
        make_uint2(*reinterpret_cast<uint32_t*>(&h01), *reinterpret_cast<uint32_t*>(&h23));
}

__global__ void outp_k(const __half* __restrict__ A2,
                       const float* __restrict__ cA, const float* __restrict__ cB,
                       float* __restrict__ out_p, int T)
{
    int idx = blockIdx.x * blockDim.x + threadIdx.x;
    int t = idx >> 5, lane = idx & 31;
    if (t >= T) return;
    int c = 512 + lane * 4;
    float4 a = *reinterpret_cast<const float4*>(cA + c);
    float4 bb = *reinterpret_cast<const float4*>(cB + c);
    float4 v = bn4(ld_h4(A2 + (long)t * 1152 + c), a, bb);
    *reinterpret_cast<float4*>(out_p + (long)t * 128 + lane * 4) = v;
}

// ======================= launch ================================================
extern "C" void kernel_launch(void* const* d_in, const int* in_sizes, int n_in,
                              void* d_out, int out_size)
{
    const float* obj   = (const float*)d_in[0];
    const float* pred  = (const float*)d_in[1];
    const int*   e32   = (const int*)d_in[2];
    const float* W1a = (const float*)d_in[3];
    const float* b1a = (const float*)d_in[4];
    const float* g1a = (const float*)d_in[5];
    const float* be1a= (const float*)d_in[6];
    const float* W1b = (const float*)d_in[7];
    const float* b1b = (const float*)d_in[8];
    const float* g1b = (const float*)d_in[9];
    const float* be1b= (const float*)d_in[10];
    const float* W2a = (const float*)d_in[11];
    const float* b2a = (const float*)d_in[12];
    const float* g2a = (const float*)d_in[13];
    const float* be2a= (const float*)d_in[14];
    const float* W2b = (const float*)d_in[15];
    const float* b2b = (const float*)d_in[16];
    const float* g2b = (const float*)d_in[17];
    const float* be2b= (const float*)d_in[18];

    const int O = in_sizes[0] / 128;
    const int T = in_sizes[1] / 128;

    float* out     = (float*)d_out;
    float* out_obj = out;
    float* out_p   = out + (size_t)O * 128;

    float *A1, *A4, *SUM, *SQ, *CA, *CB;
    __half *A2;
    int *ES, *EO, *FLAG, *DEG, *OFFS, *CUR, *ELIST;
    __half *WT, *OBJH, *PRH, *XH;
    cudaGetSymbolAddress((void**)&A1,    g_A1);
    cudaGetSymbolAddress((void**)&A2,    g_A2);
    cudaGetSymbolAddress((void**)&A4,    g_A4);
    cudaGetSymbolAddress((void**)&SUM,   g_sum);
    cudaGetSymbolAddress((void**)&SQ,    g_sq);
    cudaGetSymbolAddress((void**)&CA,    g_cA);
    cudaGetSymbolAddress((void**)&CB,    g_cB);
    cudaGetSymbolAddress((void**)&ES,    g_es);
    cudaGetSymbolAddress((void**)&EO,    g_eo);
    cudaGetSymbolAddress((void**)&FLAG,  g_flag32);
    cudaGetSymbolAddress((void**)&DEG,   g_deg);
    cudaGetSymbolAddress((void**)&OFFS,  g_off);
    cudaGetSymbolAddress((void**)&CUR,   g_cur);
    cudaGetSymbolAddress((void**)&ELIST, g_elist);
    cudaGetSymbolAddress((void**)&WT,    g_wt);
    cudaGetSymbolAddress((void**)&OBJH,  g_objh);
    cudaGetSymbolAddress((void**)&PRH,   g_predh);
    cudaGetSymbolAddress((void**)&XH,    g_xh);

    cudaFuncSetAttribute(mma_gemm_k<true,  float>,
                         cudaFuncAttributeMaxDynamicSharedMemorySize, GEMM_SMEM);
    cudaFuncSetAttribute(mma_gemm_k<false, __half>,
                         cudaFuncAttributeMaxDynamicSharedMemorySize, GEMM_SMEM);
    cudaFuncSetAttribute(mma_gemm_k<false, float>,
                         cudaFuncAttributeMaxDynamicSharedMemorySize, GEMM_SMEM);

    const int OFF1 = 0, OFF2 = 512, OFF3 = 1664, OFF4 = 2176;
    const int W1A_OFF = 0, W1B_OFF = 196608, W2A_OFF = 786432, W2B_OFF = 1048576;

    const long no4 = (long)O * 32, np4 = (long)T * 32;
    const long prep_total = (long)O + 4608 + WT_TOTAL + no4 + np4;

    // launch 0: zero + weight/input prep (pure writes; flag zeroed here,
    //           read only by LATER kernels)
    zero_prep_k<<<(unsigned)((prep_total + 255) / 256), 256>>>(
        DEG, SUM, SQ, FLAG, W1a, W1b, W2a, W2b, WT,
        obj, pred, OBJH, PRH, O, no4, np4);
    // launch 1: probe edge dtype
    probe_k<<<(T + 255) / 256, 256>>>(e32, FLAG, T);
    // launch 2: decode edges + degrees
    convert_k<<<(T + 255) / 256, 256>>>(e32, FLAG, ES, EO, DEG, T);

    // launch 3: GEMM1 (gathered)  <-- ncu capture slot
    mma_gemm_k<true, float><<<dim3(4, (T + 127) / 128), 512, GEMM_SMEM>>>(
        nullptr, OBJH, PRH, ES, EO, WT + W1A_OFF, b1a,
        A1, SUM + OFF1, SQ + OFF1, T, 512, 384);
    finalize_k<<<2, 256>>>(SUM + OFF1, SQ + OFF1, g1a, be1a, 1.f / T, 512, CA + OFF1, CB + OFF1);

    bnhalf_k<<<(unsigned)(((long)T * 128 + 255) / 256), 256>>>(
        A1, CA + OFF1, CB + OFF1, XH, (long)T * 128, 512);
    scan_k<<<1, 1024>>>(DEG, OFFS, CUR, O);
    fill_k<<<(T + 255) / 256, 256>>>(ES, EO, CUR, ELIST, T);

    mma_gemm_k<false, __half><<<dim3(9, (T + 127) / 128), 512, GEMM_SMEM>>>(
        XH, nullptr, nullptr, nullptr, nullptr, WT + W1B_OFF, b1b,
        A2, SUM + OFF2, SQ + OFF2, T, 1152, 512);
    finalize_k<<<5, 256>>>(SUM + OFF2, SQ + OFF2, g1b, be1b, 1.f / T, 1152, CA + OFF2, CB + OFF2);

    pool_k<<<O, 128>>>(A2, CA + OFF2, CB + OFF2, OFFS, ELIST, XH, O, (float)O);
    outp_k<<<(T * 32 + 255) / 256, 256>>>(A2, CA + OFF2, CB + OFF2, out_p, T);

    mma_gemm_k<false, float><<<dim3(4, (O + 127) / 128), 512, GEMM_SMEM>>>(
        XH, nullptr, nullptr, nullptr, nullptr, WT + W2A_OFF, b2a,
        A1, SUM + OFF3, SQ + OFF3, O, 512, 512);
    finalize_k<<<2, 256>>>(SUM + OFF3, SQ + OFF3, g2a, be2a, 1.f / O, 512, CA + OFF3, CB + OFF3);

    bnhalf_k<<<(unsigned)(((long)O * 128 + 255) / 256), 256>>>(
        A1, CA + OFF3, CB + OFF3, XH, (long)O * 128, 512);

    mma_gemm_k<false, float><<<dim3(1, (O + 127) / 128), 512, GEMM_SMEM>>>(
        XH, nullptr, nullptr, nullptr, nullptr, WT + W2B_OFF, b2b,
        A4, SUM + OFF4, SQ + OFF4, O, 128, 512);
    finalize_k<<<1, 256>>>(SUM + OFF4, SQ + OFF4, g2b, be2b, 1.f / O, 128, CA + OFF4, CB + OFF4);

    bn_out_k<<<(unsigned)(((long)O * 128 + 255) / 256), 256>>>(
        A4, CA + OFF4, CB + OFF4, out_obj, (long)O * 128, 128);
}